// round 8
// baseline (speedup 1.0000x reference)
#include <cuda_runtime.h>
#include <cuda_bf16.h>
#include <math.h>
#include <stdint.h>

// ---------------- problem constants ----------------
#define B_      8192
#define N_      49
#define DIM_    128
#define NH_     4
#define HD_     32
#define NW_     64
#define QKV_N   384
#define M_TOTAL (B_ * N_)          // 401408
#define SCALE_  0.17677669529663687f  // 32^-0.5

// ---------------- scratch (device globals; allocation-free) ----------------
__device__ __nv_bfloat16 g_xh[(size_t)M_TOTAL * DIM_];
__device__ __nv_bfloat16 g_xl[(size_t)M_TOTAL * DIM_];
__device__ __nv_bfloat16 g_qkvh[(size_t)M_TOTAL * QKV_N];
__device__ __nv_bfloat16 g_qkvl[(size_t)M_TOTAL * QKV_N];
__device__ __nv_bfloat16 g_oh[(size_t)M_TOTAL * DIM_];
__device__ __nv_bfloat16 g_ol[(size_t)M_TOTAL * DIM_];
__device__ __nv_bfloat16 g_wqh[QKV_N * DIM_], g_wql[QKV_N * DIM_];
__device__ __nv_bfloat16 g_wph[DIM_ * DIM_], g_wpl[DIM_ * DIM_];
__device__ float g_rmb[NW_ * NH_ * N_ * N_];

// ---------------- helpers ----------------
#define MMA16816(d, a, b)                                                     \
  asm volatile(                                                               \
      "mma.sync.aligned.m16n8k16.row.col.f32.bf16.bf16.f32 "                  \
      "{%0,%1,%2,%3}, {%4,%5,%6,%7}, {%8,%9}, {%0,%1,%2,%3};"                 \
      : "+f"(d[0]), "+f"(d[1]), "+f"(d[2]), "+f"(d[3])                        \
      : "r"(a[0]), "r"(a[1]), "r"(a[2]), "r"(a[3]), "r"(b[0]), "r"(b[1]))

#define LDSM_X4(R0, R1, R2, R3, ADDR)                                         \
  asm volatile("ldmatrix.sync.aligned.m8n8.x4.shared.b16 {%0,%1,%2,%3}, [%4];"\
      : "=r"(R0), "=r"(R1), "=r"(R2), "=r"(R3) : "r"(ADDR))

#define CP_ASYNC_COMMIT asm volatile("cp.async.commit_group;" ::: "memory")
#define CP_ASYNC_WAIT_1 asm volatile("cp.async.wait_group 1;" ::: "memory")
#define CP_ASYNC_WAIT_0 asm volatile("cp.async.wait_group 0;" ::: "memory")

__device__ __forceinline__ void cp16(void* smem, const void* gmem)
{
    uint32_t s = (uint32_t)__cvta_generic_to_shared(smem);
    asm volatile("cp.async.cg.shared.global [%0], [%1], 16;" :: "r"(s), "l"(gmem));
}

__device__ __forceinline__ uint32_t smem_u32(const void* p) {
    uint32_t a;
    asm("{ .reg .u64 t; cvta.to.shared.u64 t, %1; cvt.u32.u64 %0, t; }" : "=r"(a) : "l"(p));
    return a;
}

__device__ __forceinline__ void pack_hl(float a, float b, uint32_t& hp, uint32_t& lp)
{
    __nv_bfloat16 ah = __float2bfloat16(a), bh = __float2bfloat16(b);
    __nv_bfloat16 al = __float2bfloat16(a - __bfloat162float(ah));
    __nv_bfloat16 bl = __float2bfloat16(b - __bfloat162float(bh));
    __nv_bfloat162 hv = __halves2bfloat162(ah, bh);
    __nv_bfloat162 lv = __halves2bfloat162(al, bl);
    hp = *(uint32_t*)&hv;
    lp = *(uint32_t*)&lv;
}

// ============================================================================
// setup kernels
// ============================================================================
__global__ void convert_x(const float* __restrict__ x)
{
    size_t i = (size_t)blockIdx.x * 256 + threadIdx.x;
    float4 v = ((const float4*)x)[i];
    uint32_t h0, l0, h1, l1;
    pack_hl(v.x, v.y, h0, l0);
    pack_hl(v.z, v.w, h1, l1);
    ((uint2*)g_xh)[i] = make_uint2(h0, h1);
    ((uint2*)g_xl)[i] = make_uint2(l0, l1);
}

__global__ void convert_w(const float* __restrict__ qkv_w, const float* __restrict__ proj_w)
{
    int i = blockIdx.x * 256 + threadIdx.x;
    float4 v;
    if (i < 12288) v = ((const float4*)qkv_w)[i];
    else           v = ((const float4*)proj_w)[i - 12288];
    uint32_t h0, l0, h1, l1;
    pack_hl(v.x, v.y, h0, l0);
    pack_hl(v.z, v.w, h1, l1);
    if (i < 12288) {
        ((uint2*)g_wqh)[i] = make_uint2(h0, h1);
        ((uint2*)g_wql)[i] = make_uint2(l0, l1);
    } else {
        ((uint2*)g_wph)[i - 12288] = make_uint2(h0, h1);
        ((uint2*)g_wpl)[i - 12288] = make_uint2(l0, l1);
    }
}

__global__ void build_rmb(const float* __restrict__ mask, const float* __restrict__ rpb,
                          const int* __restrict__ rel)
{
    int t = blockIdx.x * 256 + threadIdx.x;
    int ij = t % (N_ * N_);
    int wh = t / (N_ * N_);
    int h = wh & 3, w = wh >> 2;
    g_rmb[t] = mask[w * N_ * N_ + ij] + rpb[rel[ij] * NH_ + h];
}

// ============================================================================
// Full-K split-bf16 HMMA GEMM: out[128 x NB*128] = A @ B^T + bias.
// A (hi/lo, full K=128) resident in smem; B n-blocks double-buffered.
// Grid over M only. 8 warps (4m x 2n). Pass-major MMA for 16-deep ILP.
// ============================================================================
#define GROW 136                       // smem row stride (bf16), conflict-free LDSM
#define SLAB (128 * GROW)              // one array (elems)
#define SLAB_B (SLAB * 2)              // bytes

template<int NB, bool OUT_BF16>
__global__ void __launch_bounds__(256, 1) gemm_fullk(
    const __nv_bfloat16* __restrict__ Ahg, const __nv_bfloat16* __restrict__ Alg,
    const __nv_bfloat16* __restrict__ Bhg, const __nv_bfloat16* __restrict__ Blg,
    const float* __restrict__ bias,
    float* __restrict__ outf, __nv_bfloat16* __restrict__ outh,
    __nv_bfloat16* __restrict__ outl, int Nstride)
{
    extern __shared__ __align__(16) __nv_bfloat16 sm[];
    __nv_bfloat16* sAh = sm;                      // [128][GROW]
    __nv_bfloat16* sAl = sm + SLAB;
    __nv_bfloat16* sB  = sm + 2 * SLAB;           // buf0: hi, lo ; buf1: hi, lo

    const int tid  = threadIdx.x;
    const int lane = tid & 31;
    const int warp = tid >> 5;
    const int wm   = warp & 3;
    const int wn   = warp >> 2;
    const int g    = lane >> 2;
    const int t    = lane & 3;
    const int m0   = blockIdx.x * 128;

    auto ld_arr = [&](__nv_bfloat16* dst, const __nv_bfloat16* src, int grow0) {
        #pragma unroll
        for (int it = 0; it < 8; ++it) {
            int idx = tid + it * 256;          // 0..2047
            int row = idx >> 4;                // 0..127
            int ch  = idx & 15;                // 16B chunk
            cp16(dst + row * GROW + ch * 8,
                 src + (size_t)(grow0 + row) * DIM_ + ch * 8);
        }
    };

    // ---- prologue loads ----
    ld_arr(sAh, Ahg, m0);
    ld_arr(sAl, Alg, m0);
    ld_arr(sB,        Bhg, 0);
    ld_arr(sB + SLAB, Blg, 0);
    CP_ASYNC_COMMIT;
    if (NB > 1) {
        ld_arr(sB + 2 * SLAB, Bhg, 128);
        ld_arr(sB + 3 * SLAB, Blg, 128);
        CP_ASYNC_COMMIT;
    }

    const uint32_t uA = smem_u32(sAh);
    const uint32_t uB = smem_u32(sB);
    const uint32_t aOff = ((wm * 32 + (lane & 7) + ((lane >> 3) & 1) * 8) * GROW
                           + ((lane >> 4) & 1) * 8) * 2;
    const uint32_t bOff = ((wn * 64 + (lane & 7) + ((lane >> 4) & 1) * 8) * GROW
                           + ((lane >> 3) & 1) * 8) * 2;

    float acc[2][8][4];

    auto compute = [&](uint32_t bufB) {
        #pragma unroll
        for (int mt = 0; mt < 2; ++mt)
            #pragma unroll
            for (int nt = 0; nt < 8; ++nt)
                #pragma unroll
                for (int r = 0; r < 4; ++r) acc[mt][nt][r] = 0.f;

        #pragma unroll
        for (int ks = 0; ks < 8; ++ks) {
            const uint32_t kB = ks * 32;
            uint32_t ah[2][4], al[2][4], bh[8][2], bl[8][2];
            LDSM_X4(ah[0][0], ah[0][1], ah[0][2], ah[0][3], uA + aOff + kB);
            LDSM_X4(ah[1][0], ah[1][1], ah[1][2], ah[1][3], uA + aOff + kB + 4352);
            LDSM_X4(al[0][0], al[0][1], al[0][2], al[0][3], uA + SLAB_B + aOff + kB);
            LDSM_X4(al[1][0], al[1][1], al[1][2], al[1][3], uA + SLAB_B + aOff + kB + 4352);
            #pragma unroll
            for (int p = 0; p < 4; ++p) {
                uint32_t ba = bufB + bOff + kB + (uint32_t)(p * 4352);
                LDSM_X4(bh[2*p][0], bh[2*p][1], bh[2*p+1][0], bh[2*p+1][1], ba);
                LDSM_X4(bl[2*p][0], bl[2*p][1], bl[2*p+1][0], bl[2*p+1][1], ba + SLAB_B);
            }
            // pass-major: 16 independent MMAs per pass
            #pragma unroll
            for (int nt = 0; nt < 8; ++nt)
                #pragma unroll
                for (int mt = 0; mt < 2; ++mt)
                    MMA16816(acc[mt][nt], ah[mt], bh[nt]);
            #pragma unroll
            for (int nt = 0; nt < 8; ++nt)
                #pragma unroll
                for (int mt = 0; mt < 2; ++mt)
                    MMA16816(acc[mt][nt], ah[mt], bl[nt]);
            #pragma unroll
            for (int nt = 0; nt < 8; ++nt)
                #pragma unroll
                for (int mt = 0; mt < 2; ++mt)
                    MMA16816(acc[mt][nt], al[mt], bh[nt]);
        }
    };

    auto epilogue = [&](int nb) {
        #pragma unroll
        for (int mt = 0; mt < 2; ++mt) {
            int r0 = m0 + wm * 32 + mt * 16 + g;
            #pragma unroll
            for (int nt = 0; nt < 8; ++nt) {
                int cc = nb * 128 + wn * 64 + nt * 8 + 2 * t;
                float b0 = __ldg(&bias[cc]);
                float b1 = __ldg(&bias[cc + 1]);
                float v00 = acc[mt][nt][0] + b0, v01 = acc[mt][nt][1] + b1;
                float v10 = acc[mt][nt][2] + b0, v11 = acc[mt][nt][3] + b1;
                if (OUT_BF16) {
                    uint32_t hp, lp;
                    pack_hl(v00, v01, hp, lp);
                    *(uint32_t*)&outh[(size_t)r0 * Nstride + cc] = hp;
                    *(uint32_t*)&outl[(size_t)r0 * Nstride + cc] = lp;
                    pack_hl(v10, v11, hp, lp);
                    *(uint32_t*)&outh[(size_t)(r0 + 8) * Nstride + cc] = hp;
                    *(uint32_t*)&outl[(size_t)(r0 + 8) * Nstride + cc] = lp;
                } else {
                    *(float2*)&outf[(size_t)r0 * Nstride + cc] = make_float2(v00, v01);
                    *(float2*)&outf[(size_t)(r0 + 8) * Nstride + cc] = make_float2(v10, v11);
                }
            }
        }
    };

    if (NB == 3) {
        CP_ASYNC_WAIT_1;                  // A + B0 ready
        __syncthreads();
        compute(uB);                      // nb0 uses buf0
        __syncthreads();                  // everyone done reading buf0
        ld_arr(sB,        Bhg, 256);      // B2 -> buf0
        ld_arr(sB + SLAB, Blg, 256);
        CP_ASYNC_COMMIT;
        epilogue(0);                      // overlaps B2 load

        CP_ASYNC_WAIT_1;                  // B1 ready
        __syncthreads();
        compute(uB + 2 * SLAB_B);         // nb1 uses buf1
        epilogue(1);

        CP_ASYNC_WAIT_0;                  // B2 ready
        __syncthreads();
        compute(uB);                      // nb2 uses buf0
        epilogue(2);
    } else {
        CP_ASYNC_WAIT_0;
        __syncthreads();
        compute(uB);
        epilogue(0);
    }
}

// ============================================================================
// Register-resident MMA window attention (unchanged from round 7; passing).
// ============================================================================
#define QROW 136
#define VROW 72
#define ASM_Q (64 * QROW)
#define ASM_V (128 * VROW)
#define ATTN_SM_ELEMS (4 * ASM_Q + 2 * ASM_V)

__global__ void __launch_bounds__(512) attn_mma(
    const __nv_bfloat16* __restrict__ qkvh, const __nv_bfloat16* __restrict__ qkvl,
    const float* __restrict__ rmb,
    __nv_bfloat16* __restrict__ oh, __nv_bfloat16* __restrict__ ol)
{
    extern __shared__ __align__(16) __nv_bfloat16 sm[];
    __nv_bfloat16* sqh = sm;
    __nv_bfloat16* sql = sm + ASM_Q;
    __nv_bfloat16* skh = sm + 2 * ASM_Q;
    __nv_bfloat16* skl = sm + 3 * ASM_Q;
    __nv_bfloat16* svh = sm + 4 * ASM_Q;
    __nv_bfloat16* svl = sm + 4 * ASM_Q + ASM_V;

    const int b    = blockIdx.x;
    const int tid  = threadIdx.x;
    const int lane = tid & 31;
    const int warp = tid >> 5;
    const int g    = lane >> 2;
    const int t    = lane & 3;
    const int h    = warp >> 2;
    const int wm   = warp & 3;

    {
        uint4 zz = make_uint4(0, 0, 0, 0);
        uint4* zp = (uint4*)sm;
        #pragma unroll 4
        for (int i = tid; i < ATTN_SM_ELEMS / 8; i += 512) zp[i] = zz;
    }
    __syncthreads();

    for (int idx = tid; idx < 49 * 16; idx += 512) {
        int i = idx >> 4, seg = (idx & 15) * 8;
        size_t gb = (size_t)(b * N_ + i) * QKV_N + seg;
        cp16(sqh + i * QROW + seg, qkvh + gb);
        cp16(sql + i * QROW + seg, qkvl + gb);
        cp16(skh + i * QROW + seg, qkvh + gb + 128);
        cp16(skl + i * QROW + seg, qkvl + gb + 128);
    }
    for (int idx = tid; idx < 49 * 64; idx += 512) {
        int dp = idx & 63, i = idx >> 6;
        size_t gb = (size_t)(b * N_ + i) * QKV_N + 256 + 2 * dp;
        uint32_t vh = *(const uint32_t*)(qkvh + gb);
        uint32_t vl = *(const uint32_t*)(qkvl + gb);
        int d0 = 2 * dp;
        ((uint16_t*)svh)[d0 * VROW + i]       = (uint16_t)(vh & 0xffff);
        ((uint16_t*)svh)[(d0 + 1) * VROW + i] = (uint16_t)(vh >> 16);
        ((uint16_t*)svl)[d0 * VROW + i]       = (uint16_t)(vl & 0xffff);
        ((uint16_t*)svl)[(d0 + 1) * VROW + i] = (uint16_t)(vl >> 16);
    }
    CP_ASYNC_COMMIT; CP_ASYNC_WAIT_0;
    __syncthreads();

    const int hoff = h * HD_;
    const int r0 = 16 * wm + g;
    const int r1 = r0 + 8;

    const uint32_t uqh = smem_u32(sqh), uql = smem_u32(sql);
    const uint32_t ukh = smem_u32(skh), ukl = smem_u32(skl);
    const uint32_t uvh = smem_u32(svh), uvl = smem_u32(svl);
    const uint32_t qaOff = ((16 * wm + (lane & 7) + ((lane >> 3) & 1) * 8) * QROW
                            + hoff + ((lane >> 4) & 1) * 8) * 2;
    const uint32_t kbOff = (((lane & 7) + ((lane >> 4) & 1) * 8) * QROW
                            + hoff + ((lane >> 3) & 1) * 8) * 2;
    const uint32_t vbOff = ((hoff + (lane & 7) + ((lane >> 4) & 1) * 8) * VROW
                            + ((lane >> 3) & 1) * 8) * 2;

    float sacc[8][4];
    #pragma unroll
    for (int nt = 0; nt < 8; ++nt)
        #pragma unroll
        for (int r = 0; r < 4; ++r) sacc[nt][r] = 0.f;

    #pragma unroll
    for (int ks = 0; ks < 2; ++ks) {
        const uint32_t kB = ks * 32;
        uint32_t ah[4], al[4];
        LDSM_X4(ah[0], ah[1], ah[2], ah[3], uqh + qaOff + kB);
        LDSM_X4(al[0], al[1], al[2], al[3], uql + qaOff + kB);
        #pragma unroll
        for (int p = 0; p < 4; ++p) {
            uint32_t bh[2][2], bl[2][2];
            uint32_t ba = kbOff + kB + (uint32_t)(p * 16 * QROW * 2);
            LDSM_X4(bh[0][0], bh[0][1], bh[1][0], bh[1][1], ukh + ba);
            LDSM_X4(bl[0][0], bl[0][1], bl[1][0], bl[1][1], ukl + ba);
            MMA16816(sacc[2*p],     ah, bh[0]);
            MMA16816(sacc[2*p],     ah, bl[0]);
            MMA16816(sacc[2*p],     al, bh[0]);
            MMA16816(sacc[2*p + 1], ah, bh[1]);
            MMA16816(sacc[2*p + 1], ah, bl[1]);
            MMA16816(sacc[2*p + 1], al, bh[1]);
        }
    }

    const float* rmbw = rmb + (((b & (NW_ - 1)) * NH_ + h) * N_ * N_);
    float p0[16], p1[16];
    #pragma unroll
    for (int nt = 0; nt < 8; ++nt) {
        int c0 = 8 * nt + 2 * t;
        int c1 = c0 + 1;
        p0[2 * nt]     = (r0 < N_ && c0 < N_) ? fmaf(sacc[nt][0], SCALE_, __ldg(rmbw + r0 * N_ + c0)) : -1e30f;
        p0[2 * nt + 1] = (r0 < N_ && c1 < N_) ? fmaf(sacc[nt][1], SCALE_, __ldg(rmbw + r0 * N_ + c1)) : -1e30f;
        p1[2 * nt]     = (r1 < N_ && c0 < N_) ? fmaf(sacc[nt][2], SCALE_, __ldg(rmbw + r1 * N_ + c0)) : -1e30f;
        p1[2 * nt + 1] = (r1 < N_ && c1 < N_) ? fmaf(sacc[nt][3], SCALE_, __ldg(rmbw + r1 * N_ + c1)) : -1e30f;
    }
    float m0 = -1e30f, m1 = -1e30f;
    #pragma unroll
    for (int i = 0; i < 16; ++i) { m0 = fmaxf(m0, p0[i]); m1 = fmaxf(m1, p1[i]); }
    m0 = fmaxf(m0, __shfl_xor_sync(0xffffffffu, m0, 1));
    m0 = fmaxf(m0, __shfl_xor_sync(0xffffffffu, m0, 2));
    m1 = fmaxf(m1, __shfl_xor_sync(0xffffffffu, m1, 1));
    m1 = fmaxf(m1, __shfl_xor_sync(0xffffffffu, m1, 2));
    float s0 = 0.f, s1 = 0.f;
    #pragma unroll
    for (int i = 0; i < 16; ++i) {
        p0[i] = __expf(p0[i] - m0); s0 += p0[i];
        p1[i] = __expf(p1[i] - m1); s1 += p1[i];
    }
    s0 += __shfl_xor_sync(0xffffffffu, s0, 1);
    s0 += __shfl_xor_sync(0xffffffffu, s0, 2);
    s1 += __shfl_xor_sync(0xffffffffu, s1, 1);
    s1 += __shfl_xor_sync(0xffffffffu, s1, 2);
    float i0 = __frcp_rn(s0), i1 = __frcp_rn(s1);
    #pragma unroll
    for (int i = 0; i < 16; ++i) { p0[i] *= i0; p1[i] *= i1; }

    uint32_t pah[4][4], pal[4][4];
    #pragma unroll
    for (int ks = 0; ks < 4; ++ks) {
        pack_hl(p0[4 * ks],     p0[4 * ks + 1], pah[ks][0], pal[ks][0]);
        pack_hl(p1[4 * ks],     p1[4 * ks + 1], pah[ks][1], pal[ks][1]);
        pack_hl(p0[4 * ks + 2], p0[4 * ks + 3], pah[ks][2], pal[ks][2]);
        pack_hl(p1[4 * ks + 2], p1[4 * ks + 3], pah[ks][3], pal[ks][3]);
    }

    float oacc[4][4];
    #pragma unroll
    for (int nt = 0; nt < 4; ++nt)
        #pragma unroll
        for (int r = 0; r < 4; ++r) oacc[nt][r] = 0.f;

    #pragma unroll
    for (int ks = 0; ks < 4; ++ks) {
        const uint32_t kB = ks * 32;
        #pragma unroll
        for (int p = 0; p < 2; ++p) {
            uint32_t bh[2][2], bl[2][2];
            uint32_t ba = vbOff + kB + (uint32_t)(p * 16 * VROW * 2);
            LDSM_X4(bh[0][0], bh[0][1], bh[1][0], bh[1][1], uvh + ba);
            LDSM_X4(bl[0][0], bl[0][1], bl[1][0], bl[1][1], uvl + ba);
            MMA16816(oacc[2*p],     pah[ks], bh[0]);
            MMA16816(oacc[2*p],     pah[ks], bl[0]);
            MMA16816(oacc[2*p],     pal[ks], bh[0]);
            MMA16816(oacc[2*p + 1], pah[ks], bh[1]);
            MMA16816(oacc[2*p + 1], pah[ks], bl[1]);
            MMA16816(oacc[2*p + 1], pal[ks], bh[1]);
        }
    }

    #pragma unroll
    for (int nt = 0; nt < 4; ++nt) {
        int c = hoff + 8 * nt + 2 * t;
        uint32_t hp, lp;
        if (r0 < N_) {
            size_t o = (size_t)(b * N_ + r0) * DIM_ + c;
            pack_hl(oacc[nt][0], oacc[nt][1], hp, lp);
            *(uint32_t*)&oh[o] = hp;
            *(uint32_t*)&ol[o] = lp;
        }
        if (r1 < N_) {
            size_t o = (size_t)(b * N_ + r1) * DIM_ + c;
            pack_hl(oacc[nt][2], oacc[nt][3], hp, lp);
            *(uint32_t*)&oh[o] = hp;
            *(uint32_t*)&ol[o] = lp;
        }
    }
}

// ============================================================================
// launch
// ============================================================================
#define GEMM_SM3 (6 * SLAB * (int)sizeof(__nv_bfloat16))   // 208896
#define GEMM_SM1 (4 * SLAB * (int)sizeof(__nv_bfloat16))   // 139264
#define ATTN_SM_BYTES (ATTN_SM_ELEMS * (int)sizeof(__nv_bfloat16))

extern "C" void kernel_launch(void* const* d_in, const int* in_sizes, int n_in,
                              void* d_out, int out_size)
{
    const float* x      = (const float*)d_in[0];
    const float* mask   = (const float*)d_in[1];
    const float* qkv_w  = (const float*)d_in[2];
    const float* qkv_b  = (const float*)d_in[3];
    const float* proj_w = (const float*)d_in[4];
    const float* proj_b = (const float*)d_in[5];
    const float* rpb    = (const float*)d_in[6];
    const int*   rel    = (const int*)d_in[7];
    float* out = (float*)d_out;

    __nv_bfloat16 *xh, *xl, *qh, *ql, *ohp, *olp, *wqh, *wql, *wph, *wpl;
    float* rmbp;
    cudaGetSymbolAddress((void**)&xh,  g_xh);
    cudaGetSymbolAddress((void**)&xl,  g_xl);
    cudaGetSymbolAddress((void**)&qh,  g_qkvh);
    cudaGetSymbolAddress((void**)&ql,  g_qkvl);
    cudaGetSymbolAddress((void**)&ohp, g_oh);
    cudaGetSymbolAddress((void**)&olp, g_ol);
    cudaGetSymbolAddress((void**)&wqh, g_wqh);
    cudaGetSymbolAddress((void**)&wql, g_wql);
    cudaGetSymbolAddress((void**)&wph, g_wph);
    cudaGetSymbolAddress((void**)&wpl, g_wpl);
    cudaGetSymbolAddress((void**)&rmbp, g_rmb);

    static bool attr_set = false;
    if (!attr_set) {
        cudaFuncSetAttribute(gemm_fullk<3, true>,  cudaFuncAttributeMaxDynamicSharedMemorySize, GEMM_SM3);
        cudaFuncSetAttribute(gemm_fullk<1, false>, cudaFuncAttributeMaxDynamicSharedMemorySize, GEMM_SM1);
        cudaFuncSetAttribute(attn_mma, cudaFuncAttributeMaxDynamicSharedMemorySize, ATTN_SM_BYTES);
        attr_set = true;
    }

    convert_x<<<(M_TOTAL * DIM_ / 4) / 256, 256>>>(x);
    convert_w<<<64, 256>>>(qkv_w, proj_w);
    build_rmb<<<N_ * N_, 256>>>(mask, rpb, rel);

    // QKV projection -> bf16 hi/lo
    gemm_fullk<3, true><<<M_TOTAL / 128, 256, GEMM_SM3>>>(
        xh, xl, wqh, wql, qkv_b, nullptr, qh, ql, QKV_N);

    // window attention -> bf16 hi/lo
    attn_mma<<<B_, 512, ATTN_SM_BYTES>>>(qh, ql, rmbp, ohp, olp);

    // output projection -> fp32
    gemm_fullk<1, false><<<M_TOTAL / 128, 256, GEMM_SM1>>>(
        ohp, olp, wph, wpl, proj_b, out, nullptr, nullptr, DIM_);
}

// round 9
// speedup vs baseline: 1.0476x; 1.0476x over previous
#include <cuda_runtime.h>
#include <cuda_bf16.h>
#include <math.h>
#include <stdint.h>

// ---------------- problem constants ----------------
#define B_      8192
#define N_      49
#define DIM_    128
#define NH_     4
#define HD_     32
#define NW_     64
#define QKV_N   384
#define M_TOTAL (B_ * N_)          // 401408
#define SCALE_  0.17677669529663687f  // 32^-0.5

// ---------------- scratch (device globals; allocation-free) ----------------
__device__ __nv_bfloat16 g_xh[(size_t)M_TOTAL * DIM_];
__device__ __nv_bfloat16 g_xl[(size_t)M_TOTAL * DIM_];
__device__ __nv_bfloat16 g_qkvh[(size_t)M_TOTAL * QKV_N];
__device__ __nv_bfloat16 g_qkvl[(size_t)M_TOTAL * QKV_N];
__device__ __nv_bfloat16 g_wqh[QKV_N * DIM_], g_wql[QKV_N * DIM_];
__device__ __nv_bfloat16 g_wph[DIM_ * DIM_], g_wpl[DIM_ * DIM_];
__device__ float g_rmb[NW_ * NH_ * N_ * N_];

// ---------------- helpers ----------------
#define MMA16816(d, a, b)                                                     \
  asm volatile(                                                               \
      "mma.sync.aligned.m16n8k16.row.col.f32.bf16.bf16.f32 "                  \
      "{%0,%1,%2,%3}, {%4,%5,%6,%7}, {%8,%9}, {%0,%1,%2,%3};"                 \
      : "+f"(d[0]), "+f"(d[1]), "+f"(d[2]), "+f"(d[3])                        \
      : "r"(a[0]), "r"(a[1]), "r"(a[2]), "r"(a[3]), "r"(b[0]), "r"(b[1]))

#define LDSM_X4(R0, R1, R2, R3, ADDR)                                         \
  asm volatile("ldmatrix.sync.aligned.m8n8.x4.shared.b16 {%0,%1,%2,%3}, [%4];"\
      : "=r"(R0), "=r"(R1), "=r"(R2), "=r"(R3) : "r"(ADDR))

#define LDSM_X4T(R0, R1, R2, R3, ADDR)                                        \
  asm volatile("ldmatrix.sync.aligned.m8n8.x4.trans.shared.b16 {%0,%1,%2,%3}, [%4];"\
      : "=r"(R0), "=r"(R1), "=r"(R2), "=r"(R3) : "r"(ADDR))

#define CP_ASYNC_COMMIT asm volatile("cp.async.commit_group;" ::: "memory")
#define CP_ASYNC_WAIT_1 asm volatile("cp.async.wait_group 1;" ::: "memory")
#define CP_ASYNC_WAIT_0 asm volatile("cp.async.wait_group 0;" ::: "memory")

__device__ __forceinline__ void cp16(void* smem, const void* gmem)
{
    uint32_t s = (uint32_t)__cvta_generic_to_shared(smem);
    asm volatile("cp.async.cg.shared.global [%0], [%1], 16;" :: "r"(s), "l"(gmem));
}

__device__ __forceinline__ uint32_t smem_u32(const void* p) {
    uint32_t a;
    asm("{ .reg .u64 t; cvta.to.shared.u64 t, %1; cvt.u32.u64 %0, t; }" : "=r"(a) : "l"(p));
    return a;
}

__device__ __forceinline__ void pack_hl(float a, float b, uint32_t& hp, uint32_t& lp)
{
    __nv_bfloat16 ah = __float2bfloat16(a), bh = __float2bfloat16(b);
    __nv_bfloat16 al = __float2bfloat16(a - __bfloat162float(ah));
    __nv_bfloat16 bl = __float2bfloat16(b - __bfloat162float(bh));
    __nv_bfloat162 hv = __halves2bfloat162(ah, bh);
    __nv_bfloat162 lv = __halves2bfloat162(al, bl);
    hp = *(uint32_t*)&hv;
    lp = *(uint32_t*)&lv;
}

// ============================================================================
// setup kernels
// ============================================================================
__global__ void convert_x(const float* __restrict__ x)
{
    size_t i = (size_t)blockIdx.x * 256 + threadIdx.x;
    float4 v = ((const float4*)x)[i];
    uint32_t h0, l0, h1, l1;
    pack_hl(v.x, v.y, h0, l0);
    pack_hl(v.z, v.w, h1, l1);
    ((uint2*)g_xh)[i] = make_uint2(h0, h1);
    ((uint2*)g_xl)[i] = make_uint2(l0, l1);
}

__global__ void convert_w(const float* __restrict__ qkv_w, const float* __restrict__ proj_w)
{
    int i = blockIdx.x * 256 + threadIdx.x;
    float4 v;
    if (i < 12288) v = ((const float4*)qkv_w)[i];
    else           v = ((const float4*)proj_w)[i - 12288];
    uint32_t h0, l0, h1, l1;
    pack_hl(v.x, v.y, h0, l0);
    pack_hl(v.z, v.w, h1, l1);
    if (i < 12288) {
        ((uint2*)g_wqh)[i] = make_uint2(h0, h1);
        ((uint2*)g_wql)[i] = make_uint2(l0, l1);
    } else {
        ((uint2*)g_wph)[i - 12288] = make_uint2(h0, h1);
        ((uint2*)g_wpl)[i - 12288] = make_uint2(l0, l1);
    }
}

__global__ void build_rmb(const float* __restrict__ mask, const float* __restrict__ rpb,
                          const int* __restrict__ rel)
{
    int t = blockIdx.x * 256 + threadIdx.x;
    int ij = t % (N_ * N_);
    int wh = t / (N_ * N_);
    int h = wh & 3, w = wh >> 2;
    g_rmb[t] = mask[w * N_ * N_ + ij] + rpb[rel[ij] * NH_ + h];
}

// ============================================================================
// Split-bf16 HMMA GEMM (round-7 known-good: 2-stage cp.async, LDSM frags).
// Used for QKV only; emits bf16 hi/lo.
// ============================================================================
__global__ void __launch_bounds__(256, 2) gemm_qkv(
    const __nv_bfloat16* __restrict__ Ahg, const __nv_bfloat16* __restrict__ Alg,
    const __nv_bfloat16* __restrict__ Bhg, const __nv_bfloat16* __restrict__ Blg,
    const float* __restrict__ bias,
    __nv_bfloat16* __restrict__ outh, __nv_bfloat16* __restrict__ outl)
{
    extern __shared__ __align__(16) __nv_bfloat16 sm[];
    const int STG = 128 * 40;
    __nv_bfloat16* sAh = sm;
    __nv_bfloat16* sAl = sm + 2 * STG;
    __nv_bfloat16* sBh = sm + 4 * STG;
    __nv_bfloat16* sBl = sm + 6 * STG;

    const int tid  = threadIdx.x;
    const int lane = tid & 31;
    const int warp = tid >> 5;
    const int wm   = warp & 3;
    const int wn   = warp >> 2;
    const int g    = lane >> 2;
    const int t    = lane & 3;

    const int m0 = blockIdx.y * 128;
    const int n0 = blockIdx.x * 128;

    const uint32_t uAh = smem_u32(sAh), uAl = smem_u32(sAl);
    const uint32_t uBh = smem_u32(sBh), uBl = smem_u32(sBl);
    const uint32_t aOff = ((wm * 32 + (lane & 7) + ((lane >> 3) & 1) * 8) * 40
                           + ((lane >> 4) & 1) * 8) * 2;
    const uint32_t bOff = ((wn * 64 + (lane & 7) + ((lane >> 4) & 1) * 8) * 40
                           + ((lane >> 3) & 1) * 8) * 2;

    float acc[2][8][4];
    #pragma unroll
    for (int mt = 0; mt < 2; ++mt)
        #pragma unroll
        for (int nt = 0; nt < 8; ++nt)
            #pragma unroll
            for (int r = 0; r < 4; ++r) acc[mt][nt][r] = 0.f;

    auto load_stage = [&](int st, int kc) {
        #pragma unroll
        for (int it = 0; it < 2; ++it) {
            int idx = tid + it * 256;
            int row = idx >> 2;
            int c8  = (idx & 3) * 8;
            size_t gA = (size_t)(m0 + row) * DIM_ + kc + c8;
            size_t gB = (size_t)(n0 + row) * DIM_ + kc + c8;
            int so = st * STG + row * 40 + c8;
            cp16(sAh + so, Ahg + gA);
            cp16(sAl + so, Alg + gA);
            cp16(sBh + so, Bhg + gB);
            cp16(sBl + so, Blg + gB);
        }
    };

    load_stage(0, 0);  CP_ASYNC_COMMIT;
    load_stage(1, 32); CP_ASYNC_COMMIT;

    for (int c = 0; c < 4; ++c) {
        if (c < 3) { CP_ASYNC_WAIT_1; } else { CP_ASYNC_WAIT_0; }
        __syncthreads();

        const uint32_t stB = (uint32_t)((c & 1) * (STG * 2));
        #pragma unroll
        for (int ks = 0; ks < 2; ++ks) {
            const uint32_t kB = stB + ks * 32;
            uint32_t afh[2][4], afl[2][4];
            LDSM_X4(afh[0][0], afh[0][1], afh[0][2], afh[0][3], uAh + kB + aOff);
            LDSM_X4(afh[1][0], afh[1][1], afh[1][2], afh[1][3], uAh + kB + aOff + 1280);
            LDSM_X4(afl[0][0], afl[0][1], afl[0][2], afl[0][3], uAl + kB + aOff);
            LDSM_X4(afl[1][0], afl[1][1], afl[1][2], afl[1][3], uAl + kB + aOff + 1280);

            #pragma unroll
            for (int half = 0; half < 2; ++half) {
                uint32_t bh[4][2], bl[4][2];
                #pragma unroll
                for (int p = 0; p < 2; ++p) {
                    uint32_t ba = kB + bOff + (uint32_t)((half * 2 + p) * 1280);
                    LDSM_X4(bh[2*p][0], bh[2*p][1], bh[2*p+1][0], bh[2*p+1][1], uBh + ba);
                    LDSM_X4(bl[2*p][0], bl[2*p][1], bl[2*p+1][0], bl[2*p+1][1], uBl + ba);
                }
                #pragma unroll
                for (int q = 0; q < 4; ++q) {
                    int nt = half * 4 + q;
                    #pragma unroll
                    for (int mt = 0; mt < 2; ++mt) {
                        MMA16816(acc[mt][nt], afh[mt], bh[q]);
                        MMA16816(acc[mt][nt], afh[mt], bl[q]);
                        MMA16816(acc[mt][nt], afl[mt], bh[q]);
                    }
                }
            }
        }
        __syncthreads();
        if (c < 2) { load_stage(c & 1, (c + 2) * 32); CP_ASYNC_COMMIT; }
    }

    #pragma unroll
    for (int mt = 0; mt < 2; ++mt) {
        int r0 = m0 + wm * 32 + mt * 16 + g;
        #pragma unroll
        for (int nt = 0; nt < 8; ++nt) {
            int cc = n0 + wn * 64 + nt * 8 + 2 * t;
            float b0 = __ldg(&bias[cc]);
            float b1 = __ldg(&bias[cc + 1]);
            uint32_t hp, lp;
            pack_hl(acc[mt][nt][0] + b0, acc[mt][nt][1] + b1, hp, lp);
            *(uint32_t*)&outh[(size_t)r0 * QKV_N + cc] = hp;
            *(uint32_t*)&outl[(size_t)r0 * QKV_N + cc] = lp;
            pack_hl(acc[mt][nt][2] + b0, acc[mt][nt][3] + b1, hp, lp);
            *(uint32_t*)&outh[(size_t)(r0 + 8) * QKV_N + cc] = hp;
            *(uint32_t*)&outl[(size_t)(r0 + 8) * QKV_N + cc] = lp;
        }
    }
}

// ============================================================================
// Fused attention + output projection. One CTA/window, 512 threads.
// Phases: load qkv rows -> S=QK^T -> (issue Wp loads) -> softmax -> PV (trans
// ldmatrix on V rows) -> O to smem (reusing V space) -> proj vs Wp (reusing
// Q/K space) -> fp32 out.
// ============================================================================
#define QR 136
#define SLB (64 * QR)                 // 8704 elems per 64-row slab
#define ATTN_ELEMS (6 * SLB)          // 52224
#define ATTN_SM_BYTES (ATTN_ELEMS * 2)

__global__ void __launch_bounds__(512) attn_fused(
    const __nv_bfloat16* __restrict__ qkvh, const __nv_bfloat16* __restrict__ qkvl,
    const float* __restrict__ rmb,
    const __nv_bfloat16* __restrict__ wph, const __nv_bfloat16* __restrict__ wpl,
    const float* __restrict__ pbias,
    float* __restrict__ out)
{
    extern __shared__ __align__(16) __nv_bfloat16 sm[];
    __nv_bfloat16* sqh = sm;            // Q-hi; later Wp-hi rows 0-63
    __nv_bfloat16* sql = sm + SLB;      //        later Wp-hi rows 64-127
    __nv_bfloat16* skh = sm + 2 * SLB;  // K-hi; later Wp-lo rows 0-63
    __nv_bfloat16* skl = sm + 3 * SLB;  //        later Wp-lo rows 64-127
    __nv_bfloat16* svh = sm + 4 * SLB;  // V-hi; later O-hi
    __nv_bfloat16* svl = sm + 5 * SLB;  // V-lo; later O-lo

    const int b    = blockIdx.x;
    const int tid  = threadIdx.x;
    const int lane = tid & 31;
    const int warp = tid >> 5;
    const int g    = lane >> 2;
    const int t    = lane & 3;
    const int h    = warp >> 2;
    const int wm   = warp & 3;

    // zero pads (rows 49..63 must be finite/zero)
    {
        uint4 zz = make_uint4(0, 0, 0, 0);
        uint4* zp = (uint4*)sm;
        #pragma unroll 4
        for (int i = tid; i < ATTN_ELEMS / 8; i += 512) zp[i] = zz;
    }
    __syncthreads();

    // ---- load q,k,v rows (hi/lo) via cp.async ----
    for (int idx = tid; idx < 49 * 16; idx += 512) {
        int i = idx >> 4, seg = (idx & 15) * 8;
        size_t gb = (size_t)(b * N_ + i) * QKV_N + seg;
        cp16(sqh + i * QR + seg, qkvh + gb);
        cp16(sql + i * QR + seg, qkvl + gb);
        cp16(skh + i * QR + seg, qkvh + gb + 128);
        cp16(skl + i * QR + seg, qkvl + gb + 128);
        cp16(svh + i * QR + seg, qkvh + gb + 256);
        cp16(svl + i * QR + seg, qkvl + gb + 256);
    }
    CP_ASYNC_COMMIT; CP_ASYNC_WAIT_0;
    __syncthreads();

    const int hoff = h * HD_;
    const int r0 = 16 * wm + g;
    const int r1 = r0 + 8;

    const uint32_t uqh = smem_u32(sqh), uql = smem_u32(sql);
    const uint32_t ukh = smem_u32(skh), ukl = smem_u32(skl);
    const uint32_t uvh = smem_u32(svh), uvl = smem_u32(svl);

    const uint32_t qaOff = ((16 * wm + (lane & 7) + ((lane >> 3) & 1) * 8) * QR
                            + hoff + ((lane >> 4) & 1) * 8) * 2;
    const uint32_t kbOff = (((lane & 7) + ((lane >> 4) & 1) * 8) * QR
                            + hoff + ((lane >> 3) & 1) * 8) * 2;
    const uint32_t vtOff = (((lane & 7) + ((lane >> 3) & 1) * 8) * QR
                            + ((lane >> 4) & 1) * 8) * 2;

    // ---- S = Q K^T ----
    float sacc[8][4];
    #pragma unroll
    for (int nt = 0; nt < 8; ++nt)
        #pragma unroll
        for (int r = 0; r < 4; ++r) sacc[nt][r] = 0.f;

    #pragma unroll
    for (int ks = 0; ks < 2; ++ks) {
        const uint32_t kB = ks * 32;
        uint32_t ah[4], al[4];
        LDSM_X4(ah[0], ah[1], ah[2], ah[3], uqh + qaOff + kB);
        LDSM_X4(al[0], al[1], al[2], al[3], uql + qaOff + kB);
        #pragma unroll
        for (int p = 0; p < 4; ++p) {
            uint32_t bh[2][2], bl[2][2];
            uint32_t ba = kbOff + kB + (uint32_t)(p * 16 * QR * 2);
            LDSM_X4(bh[0][0], bh[0][1], bh[1][0], bh[1][1], ukh + ba);
            LDSM_X4(bl[0][0], bl[0][1], bl[1][0], bl[1][1], ukl + ba);
            MMA16816(sacc[2*p],     ah, bh[0]);
            MMA16816(sacc[2*p],     ah, bl[0]);
            MMA16816(sacc[2*p],     al, bh[0]);
            MMA16816(sacc[2*p + 1], ah, bh[1]);
            MMA16816(sacc[2*p + 1], ah, bl[1]);
            MMA16816(sacc[2*p + 1], al, bh[1]);
        }
    }

    __syncthreads();   // all warps finished reading Q/K smem

    // ---- overlap: load Wp hi/lo into (dead) Q/K smem space ----
    for (int idx = tid; idx < 128 * 16; idx += 512) {
        int r = idx >> 4, ch = (idx & 15) * 8;
        cp16(sqh + r * QR + ch, wph + r * 128 + ch);   // spans sqh..sql
        cp16(skh + r * QR + ch, wpl + r * 128 + ch);   // spans skh..skl
    }
    CP_ASYNC_COMMIT;

    // ---- bias + mask, register softmax (quad shuffles) ----
    const float* rmbw = rmb + (((b & (NW_ - 1)) * NH_ + h) * N_ * N_);
    float p0[16], p1[16];
    #pragma unroll
    for (int nt = 0; nt < 8; ++nt) {
        int c0 = 8 * nt + 2 * t;
        int c1 = c0 + 1;
        p0[2 * nt]     = (r0 < N_ && c0 < N_) ? fmaf(sacc[nt][0], SCALE_, __ldg(rmbw + r0 * N_ + c0)) : -1e30f;
        p0[2 * nt + 1] = (r0 < N_ && c1 < N_) ? fmaf(sacc[nt][1], SCALE_, __ldg(rmbw + r0 * N_ + c1)) : -1e30f;
        p1[2 * nt]     = (r1 < N_ && c0 < N_) ? fmaf(sacc[nt][2], SCALE_, __ldg(rmbw + r1 * N_ + c0)) : -1e30f;
        p1[2 * nt + 1] = (r1 < N_ && c1 < N_) ? fmaf(sacc[nt][3], SCALE_, __ldg(rmbw + r1 * N_ + c1)) : -1e30f;
    }
    float m0 = -1e30f, m1 = -1e30f;
    #pragma unroll
    for (int i = 0; i < 16; ++i) { m0 = fmaxf(m0, p0[i]); m1 = fmaxf(m1, p1[i]); }
    m0 = fmaxf(m0, __shfl_xor_sync(0xffffffffu, m0, 1));
    m0 = fmaxf(m0, __shfl_xor_sync(0xffffffffu, m0, 2));
    m1 = fmaxf(m1, __shfl_xor_sync(0xffffffffu, m1, 1));
    m1 = fmaxf(m1, __shfl_xor_sync(0xffffffffu, m1, 2));
    float s0 = 0.f, s1 = 0.f;
    #pragma unroll
    for (int i = 0; i < 16; ++i) {
        p0[i] = __expf(p0[i] - m0); s0 += p0[i];
        p1[i] = __expf(p1[i] - m1); s1 += p1[i];
    }
    s0 += __shfl_xor_sync(0xffffffffu, s0, 1);
    s0 += __shfl_xor_sync(0xffffffffu, s0, 2);
    s1 += __shfl_xor_sync(0xffffffffu, s1, 1);
    s1 += __shfl_xor_sync(0xffffffffu, s1, 2);
    float i0 = __frcp_rn(s0), i1 = __frcp_rn(s1);
    #pragma unroll
    for (int i = 0; i < 16; ++i) { p0[i] *= i0; p1[i] *= i1; }

    // ---- P -> PV A-fragments ----
    uint32_t pah[4][4], pal[4][4];
    #pragma unroll
    for (int ks = 0; ks < 4; ++ks) {
        pack_hl(p0[4 * ks],     p0[4 * ks + 1], pah[ks][0], pal[ks][0]);
        pack_hl(p1[4 * ks],     p1[4 * ks + 1], pah[ks][1], pal[ks][1]);
        pack_hl(p0[4 * ks + 2], p0[4 * ks + 3], pah[ks][2], pal[ks][2]);
        pack_hl(p1[4 * ks + 2], p1[4 * ks + 3], pah[ks][3], pal[ks][3]);
    }

    // ---- O = P V (trans ldmatrix on V rows) ----
    float oacc[4][4];
    #pragma unroll
    for (int nt = 0; nt < 4; ++nt)
        #pragma unroll
        for (int r = 0; r < 4; ++r) oacc[nt][r] = 0.f;

    #pragma unroll
    for (int ks = 0; ks < 4; ++ks) {
        #pragma unroll
        for (int p = 0; p < 2; ++p) {
            uint32_t bh[2][2], bl[2][2];
            uint32_t ba = vtOff + (uint32_t)(ks * 16 * QR * 2) + (hoff + p * 16) * 2;
            LDSM_X4T(bh[0][0], bh[0][1], bh[1][0], bh[1][1], uvh + ba);
            LDSM_X4T(bl[0][0], bl[0][1], bl[1][0], bl[1][1], uvl + ba);
            MMA16816(oacc[2*p],     pah[ks], bh[0]);
            MMA16816(oacc[2*p],     pah[ks], bl[0]);
            MMA16816(oacc[2*p],     pal[ks], bh[0]);
            MMA16816(oacc[2*p + 1], pah[ks], bh[1]);
            MMA16816(oacc[2*p + 1], pah[ks], bl[1]);
            MMA16816(oacc[2*p + 1], pal[ks], bh[1]);
        }
    }

    __syncthreads();   // all warps finished reading V smem

    // ---- store O (hi/lo) into V smem space ----
    #pragma unroll
    for (int nt = 0; nt < 4; ++nt) {
        int col = hoff + 8 * nt + 2 * t;
        uint32_t hp, lp;
        pack_hl(oacc[nt][0], oacc[nt][1], hp, lp);
        *(uint32_t*)&svh[r0 * QR + col] = hp;
        *(uint32_t*)&svl[r0 * QR + col] = lp;
        pack_hl(oacc[nt][2], oacc[nt][3], hp, lp);
        *(uint32_t*)&svh[r1 * QR + col] = hp;
        *(uint32_t*)&svl[r1 * QR + col] = lp;
    }

    CP_ASYNC_WAIT_0;   // Wp resident
    __syncthreads();   // O stores visible to all warps

    // ---- proj: out = O @ Wp^T + pbias ----
    const uint32_t oaOff = ((16 * wm + (lane & 7) + ((lane >> 3) & 1) * 8) * QR
                            + ((lane >> 4) & 1) * 8) * 2;
    const uint32_t wbOff = ((32 * h + (lane & 7) + ((lane >> 4) & 1) * 8) * QR
                            + ((lane >> 3) & 1) * 8) * 2;

    float pacc[4][4];
    #pragma unroll
    for (int nt = 0; nt < 4; ++nt)
        #pragma unroll
        for (int r = 0; r < 4; ++r) pacc[nt][r] = 0.f;

    #pragma unroll
    for (int ks = 0; ks < 8; ++ks) {
        const uint32_t kB = ks * 32;
        uint32_t ah[4], al[4];
        LDSM_X4(ah[0], ah[1], ah[2], ah[3], uvh + oaOff + kB);
        LDSM_X4(al[0], al[1], al[2], al[3], uvl + oaOff + kB);
        #pragma unroll
        for (int p = 0; p < 2; ++p) {
            uint32_t bh[2][2], bl[2][2];
            uint32_t ba = wbOff + kB + (uint32_t)(p * 16 * QR * 2);
            LDSM_X4(bh[0][0], bh[0][1], bh[1][0], bh[1][1], uqh + ba);
            LDSM_X4(bl[0][0], bl[0][1], bl[1][0], bl[1][1], ukh + ba);
            MMA16816(pacc[2*p],     ah, bh[0]);
            MMA16816(pacc[2*p],     ah, bl[0]);
            MMA16816(pacc[2*p],     al, bh[0]);
            MMA16816(pacc[2*p + 1], ah, bh[1]);
            MMA16816(pacc[2*p + 1], ah, bl[1]);
            MMA16816(pacc[2*p + 1], al, bh[1]);
        }
    }

    // ---- epilogue: fp32 out ----
    #pragma unroll
    for (int nt = 0; nt < 4; ++nt) {
        int c = 32 * h + 8 * nt + 2 * t;
        float b0 = __ldg(&pbias[c]);
        float b1 = __ldg(&pbias[c + 1]);
        if (r0 < N_)
            *(float2*)&out[((size_t)b * N_ + r0) * DIM_ + c] =
                make_float2(pacc[nt][0] + b0, pacc[nt][1] + b1);
        if (r1 < N_)
            *(float2*)&out[((size_t)b * N_ + r1) * DIM_ + c] =
                make_float2(pacc[nt][2] + b0, pacc[nt][3] + b1);
    }
}

// ============================================================================
// launch
// ============================================================================
#define GEMM_SM_BYTES (8 * 128 * 40 * (int)sizeof(__nv_bfloat16))   // 81920

extern "C" void kernel_launch(void* const* d_in, const int* in_sizes, int n_in,
                              void* d_out, int out_size)
{
    const float* x      = (const float*)d_in[0];
    const float* mask   = (const float*)d_in[1];
    const float* qkv_w  = (const float*)d_in[2];
    const float* qkv_b  = (const float*)d_in[3];
    const float* proj_w = (const float*)d_in[4];
    const float* proj_b = (const float*)d_in[5];
    const float* rpb    = (const float*)d_in[6];
    const int*   rel    = (const int*)d_in[7];
    float* out = (float*)d_out;

    __nv_bfloat16 *xh, *xl, *qh, *ql, *wqh, *wql, *wph, *wpl;
    float* rmbp;
    cudaGetSymbolAddress((void**)&xh,  g_xh);
    cudaGetSymbolAddress((void**)&xl,  g_xl);
    cudaGetSymbolAddress((void**)&qh,  g_qkvh);
    cudaGetSymbolAddress((void**)&ql,  g_qkvl);
    cudaGetSymbolAddress((void**)&wqh, g_wqh);
    cudaGetSymbolAddress((void**)&wql, g_wql);
    cudaGetSymbolAddress((void**)&wph, g_wph);
    cudaGetSymbolAddress((void**)&wpl, g_wpl);
    cudaGetSymbolAddress((void**)&rmbp, g_rmb);

    static bool attr_set = false;
    if (!attr_set) {
        cudaFuncSetAttribute(gemm_qkv, cudaFuncAttributeMaxDynamicSharedMemorySize, GEMM_SM_BYTES);
        cudaFuncSetAttribute(attn_fused, cudaFuncAttributeMaxDynamicSharedMemorySize, ATTN_SM_BYTES);
        attr_set = true;
    }

    convert_x<<<(M_TOTAL * DIM_ / 4) / 256, 256>>>(x);
    convert_w<<<64, 256>>>(qkv_w, proj_w);
    build_rmb<<<N_ * N_, 256>>>(mask, rpb, rel);

    // QKV projection -> bf16 hi/lo
    gemm_qkv<<<dim3(QKV_N / 128, M_TOTAL / 128), 256, GEMM_SM_BYTES>>>(
        xh, xl, wqh, wql, qkv_b, qh, ql);

    // fused window attention + output projection -> fp32 out
    attn_fused<<<B_, 512, ATTN_SM_BYTES>>>(qh, ql, rmbp, wph, wpl, proj_b, out);
}

// round 10
// speedup vs baseline: 1.2241x; 1.1685x over previous
#include <cuda_runtime.h>
#include <math.h>
#include <stdint.h>

// ---------------- problem constants ----------------
#define B_      8192
#define N_      49
#define DIM_    128
#define NH_     4
#define HD_     32
#define NW_     64
#define QKV_N   384
#define M_TOTAL (B_ * N_)          // 401408
#define SCALE_  0.17677669529663687f  // 32^-0.5

// ---------------- scratch (device globals; allocation-free) ----------------
__device__ float g_qkv[(size_t)M_TOTAL * QKV_N];   // fp32, tf32-rounded
__device__ float g_wq[QKV_N * DIM_];               // tf32-rounded weights
__device__ float g_wp[DIM_ * DIM_];
__device__ float g_rmb[NW_ * NH_ * N_ * N_];       // mask + rpb fused

// ---------------- tf32 mma helpers ----------------
#define MMAT32(d, a, b)                                                       \
  asm volatile(                                                               \
      "mma.sync.aligned.m16n8k8.row.col.f32.tf32.tf32.f32 "                   \
      "{%0,%1,%2,%3}, {%4,%5,%6,%7}, {%8,%9}, {%0,%1,%2,%3};"                 \
      : "+f"(d[0]), "+f"(d[1]), "+f"(d[2]), "+f"(d[3])                        \
      : "r"(a[0]), "r"(a[1]), "r"(a[2]), "r"(a[3]), "r"(b[0]), "r"(b[1]))

__device__ __forceinline__ uint32_t f2tf(float f)
{
    uint32_t r;
    asm("cvt.rna.tf32.f32 %0, %1;" : "=r"(r) : "f"(f));
    return r;
}
__device__ __forceinline__ float f2tff(float f) { return __uint_as_float(f2tf(f)); }

#define CP_ASYNC_COMMIT asm volatile("cp.async.commit_group;" ::: "memory")
#define CP_ASYNC_WAIT_1 asm volatile("cp.async.wait_group 1;" ::: "memory")
#define CP_ASYNC_WAIT_0 asm volatile("cp.async.wait_group 0;" ::: "memory")

__device__ __forceinline__ void cp16(void* smem, const void* gmem)
{
    uint32_t s = (uint32_t)__cvta_generic_to_shared(smem);
    asm volatile("cp.async.cg.shared.global [%0], [%1], 16;" :: "r"(s), "l"(gmem));
}

// ============================================================================
// setup kernels
// ============================================================================
__global__ void round_w(const float* __restrict__ qkv_w, const float* __restrict__ proj_w)
{
    int i = blockIdx.x * 256 + threadIdx.x;   // float4 index, 0..16383
    float4 v = (i < 12288) ? ((const float4*)qkv_w)[i]
                           : ((const float4*)proj_w)[i - 12288];
    v.x = f2tff(v.x); v.y = f2tff(v.y); v.z = f2tff(v.z); v.w = f2tff(v.w);
    if (i < 12288) ((float4*)g_wq)[i] = v;
    else           ((float4*)g_wp)[i - 12288] = v;
}

__global__ void build_rmb(const float* __restrict__ mask, const float* __restrict__ rpb,
                          const int* __restrict__ rel)
{
    int t = blockIdx.x * 256 + threadIdx.x;
    int ij = t % (N_ * N_);
    int wh = t / (N_ * N_);
    int h = wh & 3, w = wh >> 2;
    g_rmb[t] = mask[w * N_ * N_ + ij] + rpb[rel[ij] * NH_ + h];
}

// ============================================================================
// TF32 single-pass GEMM: qkv = x @ Wq^T + bias (output tf32-rounded fp32).
// CTA 128x128, k-chunk 32, 2-stage cp.async, 256 thr, 2 CTA/SM.
// A (x) rounded in-register; B (weights) pre-rounded.
// ============================================================================
#define GA 36                      // smem row stride (floats); 36 % 32 = 4 -> conflict-free
#define GSTG (128 * GA)            // one stage of one array

__global__ void __launch_bounds__(256, 2) gemm_qkv(
    const float* __restrict__ X, const float* __restrict__ W,
    const float* __restrict__ bias, float* __restrict__ out)
{
    extern __shared__ __align__(16) float sm[];
    float* sA = sm;                 // [2][128][GA]
    float* sB = sm + 2 * GSTG;

    const int tid  = threadIdx.x;
    const int lane = tid & 31;
    const int warp = tid >> 5;
    const int wm   = warp & 3;
    const int wn   = warp >> 2;
    const int g    = lane >> 2;
    const int t    = lane & 3;
    const int m0   = blockIdx.y * 128;
    const int n0   = blockIdx.x * 128;

    auto load_stage = [&](int st, int kc) {
        #pragma unroll
        for (int it = 0; it < 4; ++it) {
            int idx = tid + it * 256;          // 0..1023
            int row = idx >> 3;
            int ch  = (idx & 7) * 4;           // float offset
            cp16(sA + (st * 128 + row) * GA + ch, X + (size_t)(m0 + row) * DIM_ + kc + ch);
            cp16(sB + (st * 128 + row) * GA + ch, W + (size_t)(n0 + row) * DIM_ + kc + ch);
        }
    };

    float acc[2][8][4];
    #pragma unroll
    for (int mt = 0; mt < 2; ++mt)
        #pragma unroll
        for (int nt = 0; nt < 8; ++nt)
            #pragma unroll
            for (int r = 0; r < 4; ++r) acc[mt][nt][r] = 0.f;

    load_stage(0, 0);  CP_ASYNC_COMMIT;
    load_stage(1, 32); CP_ASYNC_COMMIT;

    for (int c = 0; c < 4; ++c) {
        if (c < 3) { CP_ASYNC_WAIT_1; } else { CP_ASYNC_WAIT_0; }
        __syncthreads();

        const float* pA = sA + (c & 1) * GSTG;
        const float* pB = sB + (c & 1) * GSTG;
        #pragma unroll
        for (int ks = 0; ks < 4; ++ks) {
            const int col = ks * 8 + t;
            uint32_t af[2][4];
            #pragma unroll
            for (int mt = 0; mt < 2; ++mt) {
                const float* ar = pA + (wm * 32 + mt * 16 + g) * GA + col;
                af[mt][0] = f2tf(ar[0]);
                af[mt][1] = f2tf(ar[8 * GA]);
                af[mt][2] = f2tf(ar[4]);
                af[mt][3] = f2tf(ar[8 * GA + 4]);
            }
            uint32_t bf[8][2];
            #pragma unroll
            for (int nt = 0; nt < 8; ++nt) {
                const float* br = pB + (wn * 64 + nt * 8 + g) * GA + col;
                bf[nt][0] = __float_as_uint(br[0]);
                bf[nt][1] = __float_as_uint(br[4]);
            }
            #pragma unroll
            for (int nt = 0; nt < 8; ++nt)
                #pragma unroll
                for (int mt = 0; mt < 2; ++mt)
                    MMAT32(acc[mt][nt], af[mt], bf[nt]);
        }
        __syncthreads();
        if (c < 2) { load_stage(c & 1, (c + 2) * 32); CP_ASYNC_COMMIT; }
    }

    // epilogue: add bias, round to tf32 (downstream mma operands), store fp32
    #pragma unroll
    for (int mt = 0; mt < 2; ++mt) {
        int r0 = m0 + wm * 32 + mt * 16 + g;
        #pragma unroll
        for (int nt = 0; nt < 8; ++nt) {
            int cc = n0 + wn * 64 + nt * 8 + 2 * t;
            float b0 = __ldg(&bias[cc]);
            float b1 = __ldg(&bias[cc + 1]);
            *(float2*)&out[(size_t)r0 * QKV_N + cc] =
                make_float2(f2tff(acc[mt][nt][0] + b0), f2tff(acc[mt][nt][1] + b1));
            *(float2*)&out[(size_t)(r0 + 8) * QKV_N + cc] =
                make_float2(f2tff(acc[mt][nt][2] + b0), f2tff(acc[mt][nt][3] + b1));
        }
    }
}

// ============================================================================
// Fused TF32 attention + output projection. One CTA/window, 512 threads.
// warp = (head h = w>>2, m-tile wm = w&3). All operands fp32 (tf32-rounded),
// scalar conflict-free LDS (no ldmatrix, no transposes, no splits).
// ============================================================================
#define AR 132                              // q/k/v/o/wp row stride (floats)
#define PR 68                               // P row stride
#define SQF (64 * AR)                       // 8448 floats per slab
#define ATTN_FLOATS (3 * SQF + 4 * 64 * PR) // 25344 + 17408 = 42752
#define ATTN_SM_BYTES (ATTN_FLOATS * 4)     // 171008

__global__ void __launch_bounds__(512) attn_fused(
    const float* __restrict__ qkv, const float* __restrict__ rmb,
    const float* __restrict__ wp,  const float* __restrict__ pbias,
    float* __restrict__ out)
{
    extern __shared__ __align__(16) float sm[];
    float* sq = sm;                // later Wp rows 0-63
    float* sk = sm + SQF;          // later Wp rows 64-127 (contiguous with sq)
    float* sv = sm + 2 * SQF;      // later O
    float* sp = sm + 3 * SQF;      // P: [4 heads][64][PR]

    const int b    = blockIdx.x;
    const int tid  = threadIdx.x;
    const int lane = tid & 31;
    const int warp = tid >> 5;
    const int g    = lane >> 2;
    const int t    = lane & 3;
    const int h    = warp >> 2;
    const int wm   = warp & 3;

    // zero all smem (pad rows must be 0)
    {
        float4 zz = make_float4(0.f, 0.f, 0.f, 0.f);
        float4* zp = (float4*)sm;
        #pragma unroll 4
        for (int i = tid; i < ATTN_FLOATS / 4; i += 512) zp[i] = zz;
    }
    __syncthreads();

    // load q, k, v rows (fp32, already tf32-rounded by gemm epilogue)
    for (int idx = tid; idx < 49 * 32; idx += 512) {
        int i = idx >> 5, seg = (idx & 31) * 4;
        size_t gb = (size_t)(b * N_ + i) * QKV_N + seg;
        cp16(sq + i * AR + seg, qkv + gb);
        cp16(sk + i * AR + seg, qkv + gb + 128);
        cp16(sv + i * AR + seg, qkv + gb + 256);
    }
    CP_ASYNC_COMMIT; CP_ASYNC_WAIT_0;
    __syncthreads();

    const int hoff = h * HD_;
    const int r0 = 16 * wm + g;
    const int r1 = r0 + 8;

    // ---- S = Q K^T ----
    float sacc[8][4];
    #pragma unroll
    for (int nt = 0; nt < 8; ++nt)
        #pragma unroll
        for (int r = 0; r < 4; ++r) sacc[nt][r] = 0.f;

    #pragma unroll
    for (int ks = 0; ks < 4; ++ks) {
        const float* ar = sq + r0 * AR + hoff + ks * 8 + t;
        uint32_t a[4] = { __float_as_uint(ar[0]),
                          __float_as_uint(ar[8 * AR]),
                          __float_as_uint(ar[4]),
                          __float_as_uint(ar[8 * AR + 4]) };
        #pragma unroll
        for (int nt = 0; nt < 8; ++nt) {
            const float* br = sk + (8 * nt + g) * AR + hoff + ks * 8 + t;
            uint32_t bfr[2] = { __float_as_uint(br[0]), __float_as_uint(br[4]) };
            MMAT32(sacc[nt], a, bfr);
        }
    }
    __syncthreads();   // q,k smem dead

    // overlap: load Wp into sq/sk space (contiguous 128 rows)
    for (int idx = tid; idx < 128 * 32; idx += 512) {
        int r = idx >> 5, ch = (idx & 31) * 4;
        cp16(sq + r * AR + ch, wp + r * 128 + ch);
    }
    CP_ASYNC_COMMIT;

    // ---- bias + mask, register softmax ----
    const float* rmbw = rmb + (((b & (NW_ - 1)) * NH_ + h) * N_ * N_);
    float p0[16], p1[16];
    #pragma unroll
    for (int nt = 0; nt < 8; ++nt) {
        int c0 = 8 * nt + 2 * t;
        int c1 = c0 + 1;
        p0[2 * nt]     = (r0 < N_ && c0 < N_) ? fmaf(sacc[nt][0], SCALE_, __ldg(rmbw + r0 * N_ + c0)) : -1e30f;
        p0[2 * nt + 1] = (r0 < N_ && c1 < N_) ? fmaf(sacc[nt][1], SCALE_, __ldg(rmbw + r0 * N_ + c1)) : -1e30f;
        p1[2 * nt]     = (r1 < N_ && c0 < N_) ? fmaf(sacc[nt][2], SCALE_, __ldg(rmbw + r1 * N_ + c0)) : -1e30f;
        p1[2 * nt + 1] = (r1 < N_ && c1 < N_) ? fmaf(sacc[nt][3], SCALE_, __ldg(rmbw + r1 * N_ + c1)) : -1e30f;
    }
    float m0 = -1e30f, m1 = -1e30f;
    #pragma unroll
    for (int i = 0; i < 16; ++i) { m0 = fmaxf(m0, p0[i]); m1 = fmaxf(m1, p1[i]); }
    m0 = fmaxf(m0, __shfl_xor_sync(0xffffffffu, m0, 1));
    m0 = fmaxf(m0, __shfl_xor_sync(0xffffffffu, m0, 2));
    m1 = fmaxf(m1, __shfl_xor_sync(0xffffffffu, m1, 1));
    m1 = fmaxf(m1, __shfl_xor_sync(0xffffffffu, m1, 2));
    float s0 = 0.f, s1 = 0.f;
    #pragma unroll
    for (int i = 0; i < 16; ++i) {
        p0[i] = __expf(p0[i] - m0); s0 += p0[i];
        p1[i] = __expf(p1[i] - m1); s1 += p1[i];
    }
    s0 += __shfl_xor_sync(0xffffffffu, s0, 1);
    s0 += __shfl_xor_sync(0xffffffffu, s0, 2);
    s1 += __shfl_xor_sync(0xffffffffu, s1, 1);
    s1 += __shfl_xor_sync(0xffffffffu, s1, 2);
    float i0 = __frcp_rn(s0), i1 = __frcp_rn(s1);

    // ---- store P (tf32-rounded) to per-head smem; rows 16wm..+15 owned by this warp ----
    float* ph = sp + h * 64 * PR;
    #pragma unroll
    for (int nt = 0; nt < 8; ++nt) {
        int c = 8 * nt + 2 * t;
        *(float2*)&ph[r0 * PR + c] =
            make_float2(f2tff(p0[2 * nt] * i0), f2tff(p0[2 * nt + 1] * i0));
        *(float2*)&ph[r1 * PR + c] =
            make_float2(f2tff(p1[2 * nt] * i1), f2tff(p1[2 * nt + 1] * i1));
    }
    __syncwarp();

    // ---- O = P V ----
    float oacc[4][4];
    #pragma unroll
    for (int nt = 0; nt < 4; ++nt)
        #pragma unroll
        for (int r = 0; r < 4; ++r) oacc[nt][r] = 0.f;

    #pragma unroll
    for (int ks = 0; ks < 8; ++ks) {
        const float* ar = ph + r0 * PR + ks * 8 + t;
        uint32_t a[4] = { __float_as_uint(ar[0]),
                          __float_as_uint(ar[8 * PR]),
                          __float_as_uint(ar[4]),
                          __float_as_uint(ar[8 * PR + 4]) };
        #pragma unroll
        for (int nt = 0; nt < 4; ++nt) {
            const float* br = sv + (ks * 8 + t) * AR + hoff + 8 * nt + g;
            uint32_t bfr[2] = { __float_as_uint(br[0]), __float_as_uint(br[4 * AR]) };
            MMAT32(oacc[nt], a, bfr);
        }
    }
    __syncthreads();   // all PV reads of sv done

    // ---- store O (tf32-rounded) into sv ----
    #pragma unroll
    for (int nt = 0; nt < 4; ++nt) {
        int c = hoff + 8 * nt + 2 * t;
        *(float2*)&sv[r0 * AR + c] = make_float2(f2tff(oacc[nt][0]), f2tff(oacc[nt][1]));
        *(float2*)&sv[r1 * AR + c] = make_float2(f2tff(oacc[nt][2]), f2tff(oacc[nt][3]));
    }
    CP_ASYNC_WAIT_0;   // Wp resident
    __syncthreads();   // O visible

    // ---- proj: out = O @ Wp^T + pbias ----
    float pacc[4][4];
    #pragma unroll
    for (int nt = 0; nt < 4; ++nt)
        #pragma unroll
        for (int r = 0; r < 4; ++r) pacc[nt][r] = 0.f;

    #pragma unroll
    for (int ks = 0; ks < 16; ++ks) {
        const float* ar = sv + r0 * AR + ks * 8 + t;
        uint32_t a[4] = { __float_as_uint(ar[0]),
                          __float_as_uint(ar[8 * AR]),
                          __float_as_uint(ar[4]),
                          __float_as_uint(ar[8 * AR + 4]) };
        #pragma unroll
        for (int nt = 0; nt < 4; ++nt) {
            const float* br = sq + (32 * h + 8 * nt + g) * AR + ks * 8 + t;
            uint32_t bfr[2] = { __float_as_uint(br[0]), __float_as_uint(br[4]) };
            MMAT32(pacc[nt], a, bfr);
        }
    }

    // ---- epilogue: fp32 out ----
    #pragma unroll
    for (int nt = 0; nt < 4; ++nt) {
        int c = 32 * h + 8 * nt + 2 * t;
        float b0 = __ldg(&pbias[c]);
        float b1 = __ldg(&pbias[c + 1]);
        if (r0 < N_)
            *(float2*)&out[((size_t)b * N_ + r0) * DIM_ + c] =
                make_float2(pacc[nt][0] + b0, pacc[nt][1] + b1);
        if (r1 < N_)
            *(float2*)&out[((size_t)b * N_ + r1) * DIM_ + c] =
                make_float2(pacc[nt][2] + b0, pacc[nt][3] + b1);
    }
}

// ============================================================================
// launch
// ============================================================================
#define GEMM_SM_BYTES (4 * GSTG * (int)sizeof(float))   // 73728

extern "C" void kernel_launch(void* const* d_in, const int* in_sizes, int n_in,
                              void* d_out, int out_size)
{
    const float* x      = (const float*)d_in[0];
    const float* mask   = (const float*)d_in[1];
    const float* qkv_w  = (const float*)d_in[2];
    const float* qkv_b  = (const float*)d_in[3];
    const float* proj_w = (const float*)d_in[4];
    const float* proj_b = (const float*)d_in[5];
    const float* rpb    = (const float*)d_in[6];
    const int*   rel    = (const int*)d_in[7];
    float* out = (float*)d_out;

    float *qkvp, *wqp, *wpp, *rmbp;
    cudaGetSymbolAddress((void**)&qkvp, g_qkv);
    cudaGetSymbolAddress((void**)&wqp,  g_wq);
    cudaGetSymbolAddress((void**)&wpp,  g_wp);
    cudaGetSymbolAddress((void**)&rmbp, g_rmb);

    static bool attr_set = false;
    if (!attr_set) {
        cudaFuncSetAttribute(gemm_qkv,  cudaFuncAttributeMaxDynamicSharedMemorySize, GEMM_SM_BYTES);
        cudaFuncSetAttribute(attn_fused, cudaFuncAttributeMaxDynamicSharedMemorySize, ATTN_SM_BYTES);
        attr_set = true;
    }

    build_rmb<<<N_ * N_, 256>>>(mask, rpb, rel);
    round_w<<<64, 256>>>(qkv_w, proj_w);

    // QKV projection (tf32 single-pass) -> tf32-rounded fp32
    gemm_qkv<<<dim3(QKV_N / 128, M_TOTAL / 128), 256, GEMM_SM_BYTES>>>(
        x, wqp, qkv_b, qkvp);

    // fused window attention + output projection -> fp32 out
    attn_fused<<<B_, 512, ATTN_SM_BYTES>>>(qkvp, rmbp, wpp, proj_b, out);
}

// round 11
// speedup vs baseline: 2.1333x; 1.7426x over previous
#include <cuda_runtime.h>
#include <cuda_fp16.h>
#include <math.h>
#include <stdint.h>

// ---------------- problem constants ----------------
#define B_      8192
#define N_      49
#define DIM_    128
#define NH_     4
#define HD_     32
#define NW_     64
#define QKV_N   384
#define M_TOTAL (B_ * N_)          // 401408
#define SCALE_  0.17677669529663687f  // 32^-0.5

// ---------------- scratch (device globals; allocation-free) ----------------
__device__ __half g_x[(size_t)M_TOTAL * DIM_];      // x fp16
__device__ __half g_qkv[(size_t)M_TOTAL * QKV_N];   // qkv fp16
__device__ __half g_wq[QKV_N * DIM_];               // fp16 weights
__device__ __half g_wp[DIM_ * DIM_];
__device__ float g_rmb[NW_ * NH_ * N_ * N_];        // mask + rpb fused

// ---------------- helpers ----------------
#define MMAF16(d, a, b)                                                       \
  asm volatile(                                                               \
      "mma.sync.aligned.m16n8k16.row.col.f32.f16.f16.f32 "                    \
      "{%0,%1,%2,%3}, {%4,%5,%6,%7}, {%8,%9}, {%0,%1,%2,%3};"                 \
      : "+f"(d[0]), "+f"(d[1]), "+f"(d[2]), "+f"(d[3])                        \
      : "r"(a[0]), "r"(a[1]), "r"(a[2]), "r"(a[3]), "r"(b[0]), "r"(b[1]))

#define LDSM_X4(R0, R1, R2, R3, ADDR)                                         \
  asm volatile("ldmatrix.sync.aligned.m8n8.x4.shared.b16 {%0,%1,%2,%3}, [%4];"\
      : "=r"(R0), "=r"(R1), "=r"(R2), "=r"(R3) : "r"(ADDR))

#define LDSM_X4T(R0, R1, R2, R3, ADDR)                                        \
  asm volatile("ldmatrix.sync.aligned.m8n8.x4.trans.shared.b16 {%0,%1,%2,%3}, [%4];"\
      : "=r"(R0), "=r"(R1), "=r"(R2), "=r"(R3) : "r"(ADDR))

#define CP_ASYNC_COMMIT asm volatile("cp.async.commit_group;" ::: "memory")
#define CP_ASYNC_WAIT_1 asm volatile("cp.async.wait_group 1;" ::: "memory")
#define CP_ASYNC_WAIT_0 asm volatile("cp.async.wait_group 0;" ::: "memory")

__device__ __forceinline__ void cp16(void* smem, const void* gmem)
{
    uint32_t s = (uint32_t)__cvta_generic_to_shared(smem);
    asm volatile("cp.async.cg.shared.global [%0], [%1], 16;" :: "r"(s), "l"(gmem));
}

__device__ __forceinline__ uint32_t smem_u32(const void* p) {
    uint32_t a;
    asm("{ .reg .u64 t; cvta.to.shared.u64 t, %1; cvt.u32.u64 %0, t; }" : "=r"(a) : "l"(p));
    return a;
}

__device__ __forceinline__ uint32_t pack2h(float a, float b)
{
    __half2 h = __floats2half2_rn(a, b);
    return *(uint32_t*)&h;
}

// ============================================================================
// setup kernels
// ============================================================================
__global__ void convert_x(const float* __restrict__ x)
{
    size_t i = (size_t)blockIdx.x * 256 + threadIdx.x;   // float4 index
    float4 v = ((const float4*)x)[i];
    ((uint2*)g_x)[i] = make_uint2(pack2h(v.x, v.y), pack2h(v.z, v.w));
}

__global__ void convert_w(const float* __restrict__ qkv_w, const float* __restrict__ proj_w)
{
    int i = blockIdx.x * 256 + threadIdx.x;   // float4 index, 0..16383
    float4 v = (i < 12288) ? ((const float4*)qkv_w)[i]
                           : ((const float4*)proj_w)[i - 12288];
    uint2 p = make_uint2(pack2h(v.x, v.y), pack2h(v.z, v.w));
    if (i < 12288) ((uint2*)g_wq)[i] = p;
    else           ((uint2*)g_wp)[i - 12288] = p;
}

__global__ void build_rmb(const float* __restrict__ mask, const float* __restrict__ rpb,
                          const int* __restrict__ rel)
{
    int t = blockIdx.x * 256 + threadIdx.x;
    int ij = t % (N_ * N_);
    int wh = t / (N_ * N_);
    int h = wh & 3, w = wh >> 2;
    g_rmb[t] = mask[w * N_ * N_ + ij] + rpb[rel[ij] * NH_ + h];
}

// ============================================================================
// Single-pass fp16 HMMA GEMM: qkv = x @ Wq^T + bias (fp16 out).
// CTA 128x128, k-chunk 32, 2-stage cp.async, 256 thr, 2 CTA/SM. LDSM frags.
// ============================================================================
#define GSTG (128 * 40)            // one stage of one array (halfs)

__global__ void __launch_bounds__(256, 2) gemm_qkv(
    const __half* __restrict__ X, const __half* __restrict__ W,
    const float* __restrict__ bias, __half* __restrict__ out)
{
    extern __shared__ __align__(16) __half sm[];
    __half* sA = sm;                // [2][128][40]
    __half* sB = sm + 2 * GSTG;

    const int tid  = threadIdx.x;
    const int lane = tid & 31;
    const int warp = tid >> 5;
    const int wm   = warp & 3;
    const int wn   = warp >> 2;
    const int g    = lane >> 2;
    const int t    = lane & 3;
    const int m0   = blockIdx.y * 128;
    const int n0   = blockIdx.x * 128;

    const uint32_t uA = smem_u32(sA);
    const uint32_t uB = smem_u32(sB);
    const uint32_t aOff = ((wm * 32 + (lane & 7) + ((lane >> 3) & 1) * 8) * 40
                           + ((lane >> 4) & 1) * 8) * 2;
    const uint32_t bOff = ((wn * 64 + (lane & 7) + ((lane >> 4) & 1) * 8) * 40
                           + ((lane >> 3) & 1) * 8) * 2;

    auto load_stage = [&](int st, int kc) {
        #pragma unroll
        for (int it = 0; it < 2; ++it) {
            int idx = tid + it * 256;            // 0..511
            int row = idx >> 2;                  // 0..127
            int c8  = (idx & 3) * 8;             // 16B chunk (8 halfs)
            int so  = st * GSTG + row * 40 + c8;
            cp16(sA + so, X + (size_t)(m0 + row) * DIM_ + kc + c8);
            cp16(sB + so, W + (size_t)(n0 + row) * DIM_ + kc + c8);
        }
    };

    float acc[2][8][4];
    #pragma unroll
    for (int mt = 0; mt < 2; ++mt)
        #pragma unroll
        for (int nt = 0; nt < 8; ++nt)
            #pragma unroll
            for (int r = 0; r < 4; ++r) acc[mt][nt][r] = 0.f;

    load_stage(0, 0);  CP_ASYNC_COMMIT;
    load_stage(1, 32); CP_ASYNC_COMMIT;

    for (int c = 0; c < 4; ++c) {
        if (c < 3) { CP_ASYNC_WAIT_1; } else { CP_ASYNC_WAIT_0; }
        __syncthreads();

        const uint32_t stB = (uint32_t)((c & 1) * (GSTG * 2));
        #pragma unroll
        for (int ks = 0; ks < 2; ++ks) {
            const uint32_t kB = stB + ks * 32;   // 16 halfs = 32B
            uint32_t af[2][4], bf[8][2];
            LDSM_X4(af[0][0], af[0][1], af[0][2], af[0][3], uA + kB + aOff);
            LDSM_X4(af[1][0], af[1][1], af[1][2], af[1][3], uA + kB + aOff + 1280);
            #pragma unroll
            for (int q = 0; q < 4; ++q) {
                uint32_t ba = uB + kB + bOff + (uint32_t)(q * 1280);
                LDSM_X4(bf[2*q][0], bf[2*q][1], bf[2*q+1][0], bf[2*q+1][1], ba);
            }
            #pragma unroll
            for (int nt = 0; nt < 8; ++nt)
                #pragma unroll
                for (int mt = 0; mt < 2; ++mt)
                    MMAF16(acc[mt][nt], af[mt], bf[nt]);
        }
        __syncthreads();
        if (c < 2) { load_stage(c & 1, (c + 2) * 32); CP_ASYNC_COMMIT; }
    }

    // epilogue: add bias, store fp16
    #pragma unroll
    for (int mt = 0; mt < 2; ++mt) {
        int r0 = m0 + wm * 32 + mt * 16 + g;
        #pragma unroll
        for (int nt = 0; nt < 8; ++nt) {
            int cc = n0 + wn * 64 + nt * 8 + 2 * t;
            float b0 = __ldg(&bias[cc]);
            float b1 = __ldg(&bias[cc + 1]);
            *(uint32_t*)&out[(size_t)r0 * QKV_N + cc] =
                pack2h(acc[mt][nt][0] + b0, acc[mt][nt][1] + b1);
            *(uint32_t*)&out[(size_t)(r0 + 8) * QKV_N + cc] =
                pack2h(acc[mt][nt][2] + b0, acc[mt][nt][3] + b1);
        }
    }
}

// ============================================================================
// Fused fp16 attention + output projection. One CTA/window, 512 threads.
// warp = (head h = w>>2, m-tile wm = w&3). P stays in registers (C->A frag).
// V consumed via ldmatrix.trans. Wp reuses Q/K smem; O reuses V smem.
// ============================================================================
#define QR 136                      // row stride (halfs)
#define SLB (64 * QR)               // one 64-row slab
#define ATTN_ELEMS (3 * SLB)        // q, k, v
#define ATTN_SM_BYTES (ATTN_ELEMS * 2)   // 52224

__global__ void __launch_bounds__(512, 2) attn_fused(
    const __half* __restrict__ qkv, const float* __restrict__ rmb,
    const __half* __restrict__ wp,  const float* __restrict__ pbias,
    float* __restrict__ out)
{
    extern __shared__ __align__(16) __half sm[];
    __half* sq = sm;                // later Wp rows 0-63
    __half* sk = sm + SLB;          // later Wp rows 64-127 (contiguous)
    __half* sv = sm + 2 * SLB;      // later O

    const int b    = blockIdx.x;
    const int tid  = threadIdx.x;
    const int lane = tid & 31;
    const int warp = tid >> 5;
    const int g    = lane >> 2;
    const int t    = lane & 3;
    const int h    = warp >> 2;
    const int wm   = warp & 3;

    // zero all operand smem (pad rows must be finite/zero)
    {
        uint4 zz = make_uint4(0, 0, 0, 0);
        uint4* zp = (uint4*)sm;
        #pragma unroll 4
        for (int i = tid; i < ATTN_ELEMS / 8; i += 512) zp[i] = zz;
    }
    __syncthreads();

    // load q, k, v rows (fp16)
    for (int idx = tid; idx < 49 * 16; idx += 512) {
        int i = idx >> 4, seg = (idx & 15) * 8;
        size_t gb = (size_t)(b * N_ + i) * QKV_N + seg;
        cp16(sq + i * QR + seg, qkv + gb);
        cp16(sk + i * QR + seg, qkv + gb + 128);
        cp16(sv + i * QR + seg, qkv + gb + 256);
    }
    CP_ASYNC_COMMIT; CP_ASYNC_WAIT_0;
    __syncthreads();

    const int hoff = h * HD_;
    const int r0 = 16 * wm + g;
    const int r1 = r0 + 8;

    const uint32_t usq = smem_u32(sq);
    const uint32_t usv = smem_u32(sv);
    const uint32_t qaOff = ((16 * wm + (lane & 7) + ((lane >> 3) & 1) * 8) * QR
                            + hoff + ((lane >> 4) & 1) * 8) * 2;
    const uint32_t kbOff = (((lane & 7) + ((lane >> 4) & 1) * 8) * QR
                            + hoff + ((lane >> 3) & 1) * 8) * 2;
    const uint32_t vtOff = (((lane & 7) + ((lane >> 3) & 1) * 8) * QR
                            + ((lane >> 4) & 1) * 8) * 2;

    // ---- S = Q K^T ----
    float sacc[8][4];
    #pragma unroll
    for (int nt = 0; nt < 8; ++nt)
        #pragma unroll
        for (int r = 0; r < 4; ++r) sacc[nt][r] = 0.f;

    #pragma unroll
    for (int ks = 0; ks < 2; ++ks) {
        const uint32_t kB = ks * 32;
        uint32_t ah[4];
        LDSM_X4(ah[0], ah[1], ah[2], ah[3], usq + qaOff + kB);
        #pragma unroll
        for (int p = 0; p < 4; ++p) {
            uint32_t bh[2][2];
            uint32_t ba = usq + (uint32_t)(SLB * 2) + kbOff + kB
                        + (uint32_t)(p * 16 * QR * 2);
            LDSM_X4(bh[0][0], bh[0][1], bh[1][0], bh[1][1], ba);
            MMAF16(sacc[2*p],     ah, bh[0]);
            MMAF16(sacc[2*p + 1], ah, bh[1]);
        }
    }
    __syncthreads();   // q,k smem dead

    // overlap: load Wp into q/k smem space (128 contiguous rows)
    for (int idx = tid; idx < 128 * 16; idx += 512) {
        int r = idx >> 4, ch = (idx & 15) * 8;
        cp16(sq + r * QR + ch, wp + r * 128 + ch);
    }
    CP_ASYNC_COMMIT;

    // ---- bias + mask, register softmax (quad shuffles) ----
    const float* rmbw = rmb + (((b & (NW_ - 1)) * NH_ + h) * N_ * N_);
    float p0[16], p1[16];
    #pragma unroll
    for (int nt = 0; nt < 8; ++nt) {
        int c0 = 8 * nt + 2 * t;
        int c1 = c0 + 1;
        p0[2 * nt]     = (r0 < N_ && c0 < N_) ? fmaf(sacc[nt][0], SCALE_, __ldg(rmbw + r0 * N_ + c0)) : -1e30f;
        p0[2 * nt + 1] = (r0 < N_ && c1 < N_) ? fmaf(sacc[nt][1], SCALE_, __ldg(rmbw + r0 * N_ + c1)) : -1e30f;
        p1[2 * nt]     = (r1 < N_ && c0 < N_) ? fmaf(sacc[nt][2], SCALE_, __ldg(rmbw + r1 * N_ + c0)) : -1e30f;
        p1[2 * nt + 1] = (r1 < N_ && c1 < N_) ? fmaf(sacc[nt][3], SCALE_, __ldg(rmbw + r1 * N_ + c1)) : -1e30f;
    }
    float m0 = -1e30f, m1 = -1e30f;
    #pragma unroll
    for (int i = 0; i < 16; ++i) { m0 = fmaxf(m0, p0[i]); m1 = fmaxf(m1, p1[i]); }
    m0 = fmaxf(m0, __shfl_xor_sync(0xffffffffu, m0, 1));
    m0 = fmaxf(m0, __shfl_xor_sync(0xffffffffu, m0, 2));
    m1 = fmaxf(m1, __shfl_xor_sync(0xffffffffu, m1, 1));
    m1 = fmaxf(m1, __shfl_xor_sync(0xffffffffu, m1, 2));
    float s0 = 0.f, s1 = 0.f;
    #pragma unroll
    for (int i = 0; i < 16; ++i) {
        p0[i] = __expf(p0[i] - m0); s0 += p0[i];
        p1[i] = __expf(p1[i] - m1); s1 += p1[i];
    }
    s0 += __shfl_xor_sync(0xffffffffu, s0, 1);
    s0 += __shfl_xor_sync(0xffffffffu, s0, 2);
    s1 += __shfl_xor_sync(0xffffffffu, s1, 1);
    s1 += __shfl_xor_sync(0xffffffffu, s1, 2);
    float i0 = __frcp_rn(s0), i1 = __frcp_rn(s1);
    #pragma unroll
    for (int i = 0; i < 16; ++i) { p0[i] *= i0; p1[i] *= i1; }

    // ---- P -> PV A-fragments in registers (C-frag -> A-frag) ----
    uint32_t pa[4][4];
    #pragma unroll
    for (int ks = 0; ks < 4; ++ks) {
        pa[ks][0] = pack2h(p0[4 * ks],     p0[4 * ks + 1]);
        pa[ks][1] = pack2h(p1[4 * ks],     p1[4 * ks + 1]);
        pa[ks][2] = pack2h(p0[4 * ks + 2], p0[4 * ks + 3]);
        pa[ks][3] = pack2h(p1[4 * ks + 2], p1[4 * ks + 3]);
    }

    // ---- O = P V (trans ldmatrix on V rows) ----
    float oacc[4][4];
    #pragma unroll
    for (int nt = 0; nt < 4; ++nt)
        #pragma unroll
        for (int r = 0; r < 4; ++r) oacc[nt][r] = 0.f;

    #pragma unroll
    for (int ks = 0; ks < 4; ++ks) {
        #pragma unroll
        for (int p = 0; p < 2; ++p) {
            uint32_t bh[2][2];
            uint32_t ba = usv + vtOff + (uint32_t)(ks * 16 * QR * 2)
                        + (hoff + p * 16) * 2;
            LDSM_X4T(bh[0][0], bh[0][1], bh[1][0], bh[1][1], ba);
            MMAF16(oacc[2*p],     pa[ks], bh[0]);
            MMAF16(oacc[2*p + 1], pa[ks], bh[1]);
        }
    }
    __syncthreads();   // all PV reads of sv done

    // ---- store O (fp16) into V smem space ----
    #pragma unroll
    for (int nt = 0; nt < 4; ++nt) {
        int c = hoff + 8 * nt + 2 * t;
        *(uint32_t*)&sv[r0 * QR + c] = pack2h(oacc[nt][0], oacc[nt][1]);
        *(uint32_t*)&sv[r1 * QR + c] = pack2h(oacc[nt][2], oacc[nt][3]);
    }
    CP_ASYNC_WAIT_0;   // Wp resident
    __syncthreads();   // O visible

    // ---- proj: out = O @ Wp^T + pbias ----
    const uint32_t oaOff = ((16 * wm + (lane & 7) + ((lane >> 3) & 1) * 8) * QR
                            + ((lane >> 4) & 1) * 8) * 2;
    const uint32_t wbOff = ((32 * h + (lane & 7) + ((lane >> 4) & 1) * 8) * QR
                            + ((lane >> 3) & 1) * 8) * 2;

    float pacc[4][4];
    #pragma unroll
    for (int nt = 0; nt < 4; ++nt)
        #pragma unroll
        for (int r = 0; r < 4; ++r) pacc[nt][r] = 0.f;

    #pragma unroll
    for (int ks = 0; ks < 8; ++ks) {
        const uint32_t kB = ks * 32;
        uint32_t ah[4];
        LDSM_X4(ah[0], ah[1], ah[2], ah[3], usv + oaOff + kB);
        #pragma unroll
        for (int p = 0; p < 2; ++p) {
            uint32_t bh[2][2];
            uint32_t ba = usq + wbOff + kB + (uint32_t)(p * 16 * QR * 2);
            LDSM_X4(bh[0][0], bh[0][1], bh[1][0], bh[1][1], ba);
            MMAF16(pacc[2*p],     ah, bh[0]);
            MMAF16(pacc[2*p + 1], ah, bh[1]);
        }
    }

    // ---- epilogue: fp32 out ----
    #pragma unroll
    for (int nt = 0; nt < 4; ++nt) {
        int c = 32 * h + 8 * nt + 2 * t;
        float b0 = __ldg(&pbias[c]);
        float b1 = __ldg(&pbias[c + 1]);
        if (r0 < N_)
            *(float2*)&out[((size_t)b * N_ + r0) * DIM_ + c] =
                make_float2(pacc[nt][0] + b0, pacc[nt][1] + b1);
        if (r1 < N_)
            *(float2*)&out[((size_t)b * N_ + r1) * DIM_ + c] =
                make_float2(pacc[nt][2] + b0, pacc[nt][3] + b1);
    }
}

// ============================================================================
// launch
// ============================================================================
#define GEMM_SM_BYTES (4 * GSTG * (int)sizeof(__half))   // 40960

extern "C" void kernel_launch(void* const* d_in, const int* in_sizes, int n_in,
                              void* d_out, int out_size)
{
    const float* x      = (const float*)d_in[0];
    const float* mask   = (const float*)d_in[1];
    const float* qkv_w  = (const float*)d_in[2];
    const float* qkv_b  = (const float*)d_in[3];
    const float* proj_w = (const float*)d_in[4];
    const float* proj_b = (const float*)d_in[5];
    const float* rpb    = (const float*)d_in[6];
    const int*   rel    = (const int*)d_in[7];
    float* out = (float*)d_out;

    __half *xp, *qkvp, *wqp, *wpp;
    float* rmbp;
    cudaGetSymbolAddress((void**)&xp,   g_x);
    cudaGetSymbolAddress((void**)&qkvp, g_qkv);
    cudaGetSymbolAddress((void**)&wqp,  g_wq);
    cudaGetSymbolAddress((void**)&wpp,  g_wp);
    cudaGetSymbolAddress((void**)&rmbp, g_rmb);

    static bool attr_set = false;
    if (!attr_set) {
        cudaFuncSetAttribute(gemm_qkv,   cudaFuncAttributeMaxDynamicSharedMemorySize, GEMM_SM_BYTES);
        cudaFuncSetAttribute(attn_fused, cudaFuncAttributeMaxDynamicSharedMemorySize, ATTN_SM_BYTES);
        attr_set = true;
    }

    convert_x<<<(M_TOTAL * DIM_ / 4) / 256, 256>>>(x);
    convert_w<<<64, 256>>>(qkv_w, proj_w);
    build_rmb<<<N_ * N_, 256>>>(mask, rpb, rel);

    // QKV projection (fp16 single-pass) -> fp16
    gemm_qkv<<<dim3(QKV_N / 128, M_TOTAL / 128), 256, GEMM_SM_BYTES>>>(
        xp, wqp, qkv_b, qkvp);

    // fused window attention + output projection -> fp32 out
    attn_fused<<<B_, 512, ATTN_SM_BYTES>>>(qkvp, rmbp, wpp, proj_b, out);
}

// round 12
// speedup vs baseline: 2.1764x; 1.0202x over previous
#include <cuda_runtime.h>
#include <cuda_fp16.h>
#include <math.h>
#include <stdint.h>

// ---------------- problem constants ----------------
#define B_      8192
#define N_      49
#define DIM_    128
#define NH_     4
#define HD_     32
#define NW_     64
#define QKV_N   384
#define M_TOTAL (B_ * N_)          // 401408
#define SCALE_  0.17677669529663687f  // 32^-0.5

// ---------------- scratch (device globals; allocation-free) ----------------
__device__ __half g_x[(size_t)M_TOTAL * DIM_];      // x fp16
__device__ __half g_qkv[(size_t)M_TOTAL * QKV_N];   // qkv fp16
__device__ __half g_wq[QKV_N * DIM_];               // fp16 weights
__device__ __half g_wp[DIM_ * DIM_];
__device__ float g_rmb[NW_ * NH_ * N_ * N_];        // mask + rpb fused

// ---------------- helpers ----------------
#define MMAF16(d, a, b)                                                       \
  asm volatile(                                                               \
      "mma.sync.aligned.m16n8k16.row.col.f32.f16.f16.f32 "                    \
      "{%0,%1,%2,%3}, {%4,%5,%6,%7}, {%8,%9}, {%0,%1,%2,%3};"                 \
      : "+f"(d[0]), "+f"(d[1]), "+f"(d[2]), "+f"(d[3])                        \
      : "r"(a[0]), "r"(a[1]), "r"(a[2]), "r"(a[3]), "r"(b[0]), "r"(b[1]))

#define LDSM_X4(R0, R1, R2, R3, ADDR)                                         \
  asm volatile("ldmatrix.sync.aligned.m8n8.x4.shared.b16 {%0,%1,%2,%3}, [%4];"\
      : "=r"(R0), "=r"(R1), "=r"(R2), "=r"(R3) : "r"(ADDR))

#define LDSM_X4T(R0, R1, R2, R3, ADDR)                                        \
  asm volatile("ldmatrix.sync.aligned.m8n8.x4.trans.shared.b16 {%0,%1,%2,%3}, [%4];"\
      : "=r"(R0), "=r"(R1), "=r"(R2), "=r"(R3) : "r"(ADDR))

#define CP_ASYNC_COMMIT asm volatile("cp.async.commit_group;" ::: "memory")
#define CP_ASYNC_WAIT_0 asm volatile("cp.async.wait_group 0;" ::: "memory")

__device__ __forceinline__ void cp16(void* smem, const void* gmem)
{
    uint32_t s = (uint32_t)__cvta_generic_to_shared(smem);
    asm volatile("cp.async.cg.shared.global [%0], [%1], 16;" :: "r"(s), "l"(gmem));
}

__device__ __forceinline__ uint32_t smem_u32(const void* p) {
    uint32_t a;
    asm("{ .reg .u64 t; cvta.to.shared.u64 t, %1; cvt.u32.u64 %0, t; }" : "=r"(a) : "l"(p));
    return a;
}

__device__ __forceinline__ uint32_t pack2h(float a, float b)
{
    __half2 h = __floats2half2_rn(a, b);
    return *(uint32_t*)&h;
}

// ============================================================================
// setup kernels
// ============================================================================
__global__ void convert_x(const float* __restrict__ x)
{
    size_t i = (size_t)blockIdx.x * 256 + threadIdx.x;
    float4 v = ((const float4*)x)[i];
    ((uint2*)g_x)[i] = make_uint2(pack2h(v.x, v.y), pack2h(v.z, v.w));
}

__global__ void convert_w(const float* __restrict__ qkv_w, const float* __restrict__ proj_w)
{
    int i = blockIdx.x * 256 + threadIdx.x;
    float4 v = (i < 12288) ? ((const float4*)qkv_w)[i]
                           : ((const float4*)proj_w)[i - 12288];
    uint2 p = make_uint2(pack2h(v.x, v.y), pack2h(v.z, v.w));
    if (i < 12288) ((uint2*)g_wq)[i] = p;
    else           ((uint2*)g_wp)[i - 12288] = p;
}

__global__ void build_rmb(const float* __restrict__ mask, const float* __restrict__ rpb,
                          const int* __restrict__ rel)
{
    int t = blockIdx.x * 256 + threadIdx.x;
    int ij = t % (N_ * N_);
    int wh = t / (N_ * N_);
    int h = wh & 3, w = wh >> 2;
    g_rmb[t] = mask[w * N_ * N_ + ij] + rpb[rel[ij] * NH_ + h];
}

// ============================================================================
// Full-K fp16 HMMA GEMM: qkv = x @ Wq^T + bias (fp16 out).
// CTA 128x128, full K=128 resident in smem. ONE load group, ONE barrier,
// then 128 uninterrupted mma per warp (pass over ks with 16-deep ILP).
// 2 CTA/SM (68KB smem); cross-CTA overlap hides the load phase.
// ============================================================================
#define AROW 136                     // row stride (halfs); 272B, conflict-free LDSM
#define ASLAB (128 * AROW)           // one array (halfs) = 34816 B

__global__ void __launch_bounds__(256, 2) gemm_qkv(
    const __half* __restrict__ X, const __half* __restrict__ W,
    const float* __restrict__ bias, __half* __restrict__ out)
{
    extern __shared__ __align__(16) __half sm[];
    __half* sA = sm;                 // [128][AROW]
    __half* sB = sm + ASLAB;

    const int tid  = threadIdx.x;
    const int lane = tid & 31;
    const int warp = tid >> 5;
    const int wm   = warp & 3;
    const int wn   = warp >> 2;
    const int g    = lane >> 2;
    const int t    = lane & 3;
    const int m0   = blockIdx.y * 128;
    const int n0   = blockIdx.x * 128;

    // ---- one-shot load: A and B tiles, full K ----
    #pragma unroll
    for (int it = 0; it < 8; ++it) {
        int idx = tid + it * 256;            // 0..2047
        int row = idx >> 4;                  // 0..127
        int c8  = (idx & 15) * 8;            // 16B chunk
        cp16(sA + row * AROW + c8, X + (size_t)(m0 + row) * DIM_ + c8);
        cp16(sB + row * AROW + c8, W + (size_t)(n0 + row) * DIM_ + c8);
    }
    CP_ASYNC_COMMIT;

    const uint32_t uA = smem_u32(sA);
    const uint32_t uB = smem_u32(sB);
    const uint32_t aOff = ((wm * 32 + (lane & 7) + ((lane >> 3) & 1) * 8) * AROW
                           + ((lane >> 4) & 1) * 8) * 2;
    const uint32_t bOff = ((wn * 64 + (lane & 7) + ((lane >> 4) & 1) * 8) * AROW
                           + ((lane >> 3) & 1) * 8) * 2;

    float acc[2][8][4];
    #pragma unroll
    for (int mt = 0; mt < 2; ++mt)
        #pragma unroll
        for (int nt = 0; nt < 8; ++nt)
            #pragma unroll
            for (int r = 0; r < 4; ++r) acc[mt][nt][r] = 0.f;

    CP_ASYNC_WAIT_0;
    __syncthreads();

    // ---- 8 k-steps, no barriers ----
    #pragma unroll
    for (int ks = 0; ks < 8; ++ks) {
        const uint32_t kB = ks * 32;         // 16 halfs
        uint32_t af[2][4], bf[8][2];
        LDSM_X4(af[0][0], af[0][1], af[0][2], af[0][3], uA + aOff + kB);
        LDSM_X4(af[1][0], af[1][1], af[1][2], af[1][3], uA + aOff + kB + 4352);
        #pragma unroll
        for (int q = 0; q < 4; ++q) {
            uint32_t ba = uB + bOff + kB + (uint32_t)(q * 4352);
            LDSM_X4(bf[2*q][0], bf[2*q][1], bf[2*q+1][0], bf[2*q+1][1], ba);
        }
        #pragma unroll
        for (int nt = 0; nt < 8; ++nt)
            #pragma unroll
            for (int mt = 0; mt < 2; ++mt)
                MMAF16(acc[mt][nt], af[mt], bf[nt]);
    }

    // ---- epilogue: add bias, store fp16 ----
    #pragma unroll
    for (int mt = 0; mt < 2; ++mt) {
        int r0 = m0 + wm * 32 + mt * 16 + g;
        #pragma unroll
        for (int nt = 0; nt < 8; ++nt) {
            int cc = n0 + wn * 64 + nt * 8 + 2 * t;
            float b0 = __ldg(&bias[cc]);
            float b1 = __ldg(&bias[cc + 1]);
            *(uint32_t*)&out[(size_t)r0 * QKV_N + cc] =
                pack2h(acc[mt][nt][0] + b0, acc[mt][nt][1] + b1);
            *(uint32_t*)&out[(size_t)(r0 + 8) * QKV_N + cc] =
                pack2h(acc[mt][nt][2] + b0, acc[mt][nt][3] + b1);
        }
    }
}

// ============================================================================
// Fused fp16 attention + output projection (unchanged from round 11).
// ============================================================================
#define QR 136
#define SLB (64 * QR)
#define ATTN_ELEMS (3 * SLB)
#define ATTN_SM_BYTES (ATTN_ELEMS * 2)

__global__ void __launch_bounds__(512, 2) attn_fused(
    const __half* __restrict__ qkv, const float* __restrict__ rmb,
    const __half* __restrict__ wp,  const float* __restrict__ pbias,
    float* __restrict__ out)
{
    extern __shared__ __align__(16) __half sm[];
    __half* sq = sm;
    __half* sk = sm + SLB;
    __half* sv = sm + 2 * SLB;

    const int b    = blockIdx.x;
    const int tid  = threadIdx.x;
    const int lane = tid & 31;
    const int warp = tid >> 5;
    const int g    = lane >> 2;
    const int t    = lane & 3;
    const int h    = warp >> 2;
    const int wm   = warp & 3;

    {
        uint4 zz = make_uint4(0, 0, 0, 0);
        uint4* zp = (uint4*)sm;
        #pragma unroll 4
        for (int i = tid; i < ATTN_ELEMS / 8; i += 512) zp[i] = zz;
    }
    __syncthreads();

    for (int idx = tid; idx < 49 * 16; idx += 512) {
        int i = idx >> 4, seg = (idx & 15) * 8;
        size_t gb = (size_t)(b * N_ + i) * QKV_N + seg;
        cp16(sq + i * QR + seg, qkv + gb);
        cp16(sk + i * QR + seg, qkv + gb + 128);
        cp16(sv + i * QR + seg, qkv + gb + 256);
    }
    CP_ASYNC_COMMIT; CP_ASYNC_WAIT_0;
    __syncthreads();

    const int hoff = h * HD_;
    const int r0 = 16 * wm + g;
    const int r1 = r0 + 8;

    const uint32_t usq = smem_u32(sq);
    const uint32_t usv = smem_u32(sv);
    const uint32_t qaOff = ((16 * wm + (lane & 7) + ((lane >> 3) & 1) * 8) * QR
                            + hoff + ((lane >> 4) & 1) * 8) * 2;
    const uint32_t kbOff = (((lane & 7) + ((lane >> 4) & 1) * 8) * QR
                            + hoff + ((lane >> 3) & 1) * 8) * 2;
    const uint32_t vtOff = (((lane & 7) + ((lane >> 3) & 1) * 8) * QR
                            + ((lane >> 4) & 1) * 8) * 2;

    float sacc[8][4];
    #pragma unroll
    for (int nt = 0; nt < 8; ++nt)
        #pragma unroll
        for (int r = 0; r < 4; ++r) sacc[nt][r] = 0.f;

    #pragma unroll
    for (int ks = 0; ks < 2; ++ks) {
        const uint32_t kB = ks * 32;
        uint32_t ah[4];
        LDSM_X4(ah[0], ah[1], ah[2], ah[3], usq + qaOff + kB);
        #pragma unroll
        for (int p = 0; p < 4; ++p) {
            uint32_t bh[2][2];
            uint32_t ba = usq + (uint32_t)(SLB * 2) + kbOff + kB
                        + (uint32_t)(p * 16 * QR * 2);
            LDSM_X4(bh[0][0], bh[0][1], bh[1][0], bh[1][1], ba);
            MMAF16(sacc[2*p],     ah, bh[0]);
            MMAF16(sacc[2*p + 1], ah, bh[1]);
        }
    }
    __syncthreads();

    for (int idx = tid; idx < 128 * 16; idx += 512) {
        int r = idx >> 4, ch = (idx & 15) * 8;
        cp16(sq + r * QR + ch, wp + r * 128 + ch);
    }
    CP_ASYNC_COMMIT;

    const float* rmbw = rmb + (((b & (NW_ - 1)) * NH_ + h) * N_ * N_);
    float p0[16], p1[16];
    #pragma unroll
    for (int nt = 0; nt < 8; ++nt) {
        int c0 = 8 * nt + 2 * t;
        int c1 = c0 + 1;
        p0[2 * nt]     = (r0 < N_ && c0 < N_) ? fmaf(sacc[nt][0], SCALE_, __ldg(rmbw + r0 * N_ + c0)) : -1e30f;
        p0[2 * nt + 1] = (r0 < N_ && c1 < N_) ? fmaf(sacc[nt][1], SCALE_, __ldg(rmbw + r0 * N_ + c1)) : -1e30f;
        p1[2 * nt]     = (r1 < N_ && c0 < N_) ? fmaf(sacc[nt][2], SCALE_, __ldg(rmbw + r1 * N_ + c0)) : -1e30f;
        p1[2 * nt + 1] = (r1 < N_ && c1 < N_) ? fmaf(sacc[nt][3], SCALE_, __ldg(rmbw + r1 * N_ + c1)) : -1e30f;
    }
    float m0 = -1e30f, m1 = -1e30f;
    #pragma unroll
    for (int i = 0; i < 16; ++i) { m0 = fmaxf(m0, p0[i]); m1 = fmaxf(m1, p1[i]); }
    m0 = fmaxf(m0, __shfl_xor_sync(0xffffffffu, m0, 1));
    m0 = fmaxf(m0, __shfl_xor_sync(0xffffffffu, m0, 2));
    m1 = fmaxf(m1, __shfl_xor_sync(0xffffffffu, m1, 1));
    m1 = fmaxf(m1, __shfl_xor_sync(0xffffffffu, m1, 2));
    float s0 = 0.f, s1 = 0.f;
    #pragma unroll
    for (int i = 0; i < 16; ++i) {
        p0[i] = __expf(p0[i] - m0); s0 += p0[i];
        p1[i] = __expf(p1[i] - m1); s1 += p1[i];
    }
    s0 += __shfl_xor_sync(0xffffffffu, s0, 1);
    s0 += __shfl_xor_sync(0xffffffffu, s0, 2);
    s1 += __shfl_xor_sync(0xffffffffu, s1, 1);
    s1 += __shfl_xor_sync(0xffffffffu, s1, 2);
    float i0 = __frcp_rn(s0), i1 = __frcp_rn(s1);
    #pragma unroll
    for (int i = 0; i < 16; ++i) { p0[i] *= i0; p1[i] *= i1; }

    uint32_t pa[4][4];
    #pragma unroll
    for (int ks = 0; ks < 4; ++ks) {
        pa[ks][0] = pack2h(p0[4 * ks],     p0[4 * ks + 1]);
        pa[ks][1] = pack2h(p1[4 * ks],     p1[4 * ks + 1]);
        pa[ks][2] = pack2h(p0[4 * ks + 2], p0[4 * ks + 3]);
        pa[ks][3] = pack2h(p1[4 * ks + 2], p1[4 * ks + 3]);
    }

    float oacc[4][4];
    #pragma unroll
    for (int nt = 0; nt < 4; ++nt)
        #pragma unroll
        for (int r = 0; r < 4; ++r) oacc[nt][r] = 0.f;

    #pragma unroll
    for (int ks = 0; ks < 4; ++ks) {
        #pragma unroll
        for (int p = 0; p < 2; ++p) {
            uint32_t bh[2][2];
            uint32_t ba = usv + vtOff + (uint32_t)(ks * 16 * QR * 2)
                        + (hoff + p * 16) * 2;
            LDSM_X4T(bh[0][0], bh[0][1], bh[1][0], bh[1][1], ba);
            MMAF16(oacc[2*p],     pa[ks], bh[0]);
            MMAF16(oacc[2*p + 1], pa[ks], bh[1]);
        }
    }
    __syncthreads();

    #pragma unroll
    for (int nt = 0; nt < 4; ++nt) {
        int c = hoff + 8 * nt + 2 * t;
        *(uint32_t*)&sv[r0 * QR + c] = pack2h(oacc[nt][0], oacc[nt][1]);
        *(uint32_t*)&sv[r1 * QR + c] = pack2h(oacc[nt][2], oacc[nt][3]);
    }
    CP_ASYNC_WAIT_0;
    __syncthreads();

    const uint32_t oaOff = ((16 * wm + (lane & 7) + ((lane >> 3) & 1) * 8) * QR
                            + ((lane >> 4) & 1) * 8) * 2;
    const uint32_t wbOff = ((32 * h + (lane & 7) + ((lane >> 4) & 1) * 8) * QR
                            + ((lane >> 3) & 1) * 8) * 2;

    float pacc[4][4];
    #pragma unroll
    for (int nt = 0; nt < 4; ++nt)
        #pragma unroll
        for (int r = 0; r < 4; ++r) pacc[nt][r] = 0.f;

    #pragma unroll
    for (int ks = 0; ks < 8; ++ks) {
        const uint32_t kB = ks * 32;
        uint32_t ah[4];
        LDSM_X4(ah[0], ah[1], ah[2], ah[3], usv + oaOff + kB);
        #pragma unroll
        for (int p = 0; p < 2; ++p) {
            uint32_t bh[2][2];
            uint32_t ba = usq + wbOff + kB + (uint32_t)(p * 16 * QR * 2);
            LDSM_X4(bh[0][0], bh[0][1], bh[1][0], bh[1][1], ba);
            MMAF16(pacc[2*p],     ah, bh[0]);
            MMAF16(pacc[2*p + 1], ah, bh[1]);
        }
    }

    #pragma unroll
    for (int nt = 0; nt < 4; ++nt) {
        int c = 32 * h + 8 * nt + 2 * t;
        float b0 = __ldg(&pbias[c]);
        float b1 = __ldg(&pbias[c + 1]);
        if (r0 < N_)
            *(float2*)&out[((size_t)b * N_ + r0) * DIM_ + c] =
                make_float2(pacc[nt][0] + b0, pacc[nt][1] + b1);
        if (r1 < N_)
            *(float2*)&out[((size_t)b * N_ + r1) * DIM_ + c] =
                make_float2(pacc[nt][2] + b0, pacc[nt][3] + b1);
    }
}

// ============================================================================
// launch
// ============================================================================
#define GEMM_SM_BYTES (2 * ASLAB * (int)sizeof(__half))   // 69632

extern "C" void kernel_launch(void* const* d_in, const int* in_sizes, int n_in,
                              void* d_out, int out_size)
{
    const float* x      = (const float*)d_in[0];
    const float* mask   = (const float*)d_in[1];
    const float* qkv_w  = (const float*)d_in[2];
    const float* qkv_b  = (const float*)d_in[3];
    const float* proj_w = (const float*)d_in[4];
    const float* proj_b = (const float*)d_in[5];
    const float* rpb    = (const float*)d_in[6];
    const int*   rel    = (const int*)d_in[7];
    float* out = (float*)d_out;

    __half *xp, *qkvp, *wqp, *wpp;
    float* rmbp;
    cudaGetSymbolAddress((void**)&xp,   g_x);
    cudaGetSymbolAddress((void**)&qkvp, g_qkv);
    cudaGetSymbolAddress((void**)&wqp,  g_wq);
    cudaGetSymbolAddress((void**)&wpp,  g_wp);
    cudaGetSymbolAddress((void**)&rmbp, g_rmb);

    static bool attr_set = false;
    if (!attr_set) {
        cudaFuncSetAttribute(gemm_qkv,   cudaFuncAttributeMaxDynamicSharedMemorySize, GEMM_SM_BYTES);
        cudaFuncSetAttribute(attn_fused, cudaFuncAttributeMaxDynamicSharedMemorySize, ATTN_SM_BYTES);
        attr_set = true;
    }

    convert_x<<<(M_TOTAL * DIM_ / 4) / 256, 256>>>(x);
    convert_w<<<64, 256>>>(qkv_w, proj_w);
    build_rmb<<<N_ * N_, 256>>>(mask, rpb, rel);

    // QKV projection (fp16 full-K) -> fp16
    gemm_qkv<<<dim3(QKV_N / 128, M_TOTAL / 128), 256, GEMM_SM_BYTES>>>(
        xp, wqp, qkv_b, qkvp);

    // fused window attention + output projection -> fp32 out
    attn_fused<<<B_, 512, ATTN_SM_BYTES>>>(qkvp, rmbp, wpp, proj_b, out);
}

// round 13
// speedup vs baseline: 2.2231x; 1.0214x over previous
#include <cuda_runtime.h>
#include <cuda_fp16.h>
#include <math.h>
#include <stdint.h>

// ---------------- problem constants ----------------
#define B_      8192
#define N_      49
#define DIM_    128
#define NH_     4
#define HD_     32
#define NW_     64
#define QKV_N   384
#define M_TOTAL (B_ * N_)          // 401408
#define MBLK    (M_TOTAL / 128)    // 3136 m-blocks
#define GRIDY   96                 // persistent m-group count
#define SCALE_  0.17677669529663687f  // 32^-0.5

// ---------------- scratch (device globals; allocation-free) ----------------
__device__ __half g_x[(size_t)M_TOTAL * DIM_];      // x fp16
__device__ __half g_qkv[(size_t)M_TOTAL * QKV_N];   // qkv fp16
__device__ __half g_wq[QKV_N * DIM_];               // fp16 weights
__device__ __half g_wp[DIM_ * DIM_];
__device__ float g_rmb[NW_ * NH_ * N_ * N_];        // mask + rpb fused

// ---------------- helpers ----------------
#define MMAF16(d, a, b)                                                       \
  asm volatile(                                                               \
      "mma.sync.aligned.m16n8k16.row.col.f32.f16.f16.f32 "                    \
      "{%0,%1,%2,%3}, {%4,%5,%6,%7}, {%8,%9}, {%0,%1,%2,%3};"                 \
      : "+f"(d[0]), "+f"(d[1]), "+f"(d[2]), "+f"(d[3])                        \
      : "r"(a[0]), "r"(a[1]), "r"(a[2]), "r"(a[3]), "r"(b[0]), "r"(b[1]))

#define LDSM_X4(R0, R1, R2, R3, ADDR)                                         \
  asm volatile("ldmatrix.sync.aligned.m8n8.x4.shared.b16 {%0,%1,%2,%3}, [%4];"\
      : "=r"(R0), "=r"(R1), "=r"(R2), "=r"(R3) : "r"(ADDR))

#define LDSM_X4T(R0, R1, R2, R3, ADDR)                                        \
  asm volatile("ldmatrix.sync.aligned.m8n8.x4.trans.shared.b16 {%0,%1,%2,%3}, [%4];"\
      : "=r"(R0), "=r"(R1), "=r"(R2), "=r"(R3) : "r"(ADDR))

#define CP_ASYNC_COMMIT asm volatile("cp.async.commit_group;" ::: "memory")
#define CP_ASYNC_WAIT_0 asm volatile("cp.async.wait_group 0;" ::: "memory")

__device__ __forceinline__ void cp16(void* smem, const void* gmem)
{
    uint32_t s = (uint32_t)__cvta_generic_to_shared(smem);
    asm volatile("cp.async.cg.shared.global [%0], [%1], 16;" :: "r"(s), "l"(gmem));
}

__device__ __forceinline__ uint32_t smem_u32(const void* p) {
    uint32_t a;
    asm("{ .reg .u64 t; cvta.to.shared.u64 t, %1; cvt.u32.u64 %0, t; }" : "=r"(a) : "l"(p));
    return a;
}

__device__ __forceinline__ uint32_t pack2h(float a, float b)
{
    __half2 h = __floats2half2_rn(a, b);
    return *(uint32_t*)&h;
}

// ============================================================================
// setup kernels
// ============================================================================
__global__ void convert_x(const float* __restrict__ x)
{
    size_t i = (size_t)blockIdx.x * 256 + threadIdx.x;
    float4 v = ((const float4*)x)[i];
    ((uint2*)g_x)[i] = make_uint2(pack2h(v.x, v.y), pack2h(v.z, v.w));
}

__global__ void convert_w(const float* __restrict__ qkv_w, const float* __restrict__ proj_w)
{
    int i = blockIdx.x * 256 + threadIdx.x;
    float4 v = (i < 12288) ? ((const float4*)qkv_w)[i]
                           : ((const float4*)proj_w)[i - 12288];
    uint2 p = make_uint2(pack2h(v.x, v.y), pack2h(v.z, v.w));
    if (i < 12288) ((uint2*)g_wq)[i] = p;
    else           ((uint2*)g_wp)[i - 12288] = p;
}

__global__ void build_rmb(const float* __restrict__ mask, const float* __restrict__ rpb,
                          const int* __restrict__ rel)
{
    int t = blockIdx.x * 256 + threadIdx.x;
    int ij = t % (N_ * N_);
    int wh = t / (N_ * N_);
    int h = wh & 3, w = wh >> 2;
    g_rmb[t] = mask[w * N_ * N_ + ij] + rpb[rel[ij] * NH_ + h];
}

// ============================================================================
// Persistent fp16 HMMA GEMM: qkv = x @ Wq^T + bias (fp16 out).
// Grid (3 n-blocks, 96 m-groups). Each CTA pins its 128-col Wq block in smem
// once, then loops over ~33 m-blocks with A double-buffered: prefetch A(i+1)
// issued before compute(i) -> steady state = max(load, compute).
// Smem 102KB -> 2 CTA/SM.
// ============================================================================
#define AROW 136                     // row stride (halfs), conflict-free LDSM
#define ASLAB (128 * AROW)           // one slab (halfs) = 34816 B
#define GEMM_SM_BYTES (3 * ASLAB * (int)sizeof(__half))   // 104448

__global__ void __launch_bounds__(256, 2) gemm_qkv(
    const __half* __restrict__ X, const __half* __restrict__ W,
    const float* __restrict__ bias, __half* __restrict__ out)
{
    extern __shared__ __align__(16) __half sm[];
    __half* sA0 = sm;                 // A double buffer
    __half* sA1 = sm + ASLAB;
    __half* sB  = sm + 2 * ASLAB;     // Wq n-block, resident

    const int tid  = threadIdx.x;
    const int lane = tid & 31;
    const int warp = tid >> 5;
    const int wm   = warp & 3;
    const int wn   = warp >> 2;
    const int g    = lane >> 2;
    const int t    = lane & 3;
    const int n0   = blockIdx.x * 128;

    auto ld_A = [&](__half* dst, int m0) {
        #pragma unroll
        for (int it = 0; it < 8; ++it) {
            int idx = tid + it * 256;            // 0..2047
            int row = idx >> 4;
            int c8  = (idx & 15) * 8;
            cp16(dst + row * AROW + c8, X + (size_t)(m0 + row) * DIM_ + c8);
        }
    };

    // ---- prologue: B (once) + A(0) ----
    #pragma unroll
    for (int it = 0; it < 8; ++it) {
        int idx = tid + it * 256;
        int row = idx >> 4;
        int c8  = (idx & 15) * 8;
        cp16(sB + row * AROW + c8, W + (size_t)(n0 + row) * DIM_ + c8);
    }
    ld_A(sA0, blockIdx.y * 128);
    CP_ASYNC_COMMIT;

    const uint32_t uB = smem_u32(sB);
    const uint32_t aOff = ((wm * 32 + (lane & 7) + ((lane >> 3) & 1) * 8) * AROW
                           + ((lane >> 4) & 1) * 8) * 2;
    const uint32_t bOff = ((wn * 64 + (lane & 7) + ((lane >> 4) & 1) * 8) * AROW
                           + ((lane >> 3) & 1) * 8) * 2;

    int par = 0;
    for (int mb = blockIdx.y; mb < MBLK; mb += GRIDY, par ^= 1) {
        const int m0 = mb * 128;
        const uint32_t uA = smem_u32(par ? sA1 : sA0);
        __half* nxt = par ? sA0 : sA1;

        CP_ASYNC_WAIT_0;          // A(cur) (+B on first iter) resident
        __syncthreads();

        if (mb + GRIDY < MBLK) {  // prefetch next m-block into other buffer
            ld_A(nxt, (mb + GRIDY) * 128);
            CP_ASYNC_COMMIT;
        }

        float acc[2][8][4];
        #pragma unroll
        for (int mt = 0; mt < 2; ++mt)
            #pragma unroll
            for (int nt = 0; nt < 8; ++nt)
                #pragma unroll
                for (int r = 0; r < 4; ++r) acc[mt][nt][r] = 0.f;

        #pragma unroll
        for (int ks = 0; ks < 8; ++ks) {
            const uint32_t kB = ks * 32;
            uint32_t af[2][4], bf[8][2];
            LDSM_X4(af[0][0], af[0][1], af[0][2], af[0][3], uA + aOff + kB);
            LDSM_X4(af[1][0], af[1][1], af[1][2], af[1][3], uA + aOff + kB + 4352);
            #pragma unroll
            for (int q = 0; q < 4; ++q) {
                uint32_t ba = uB + bOff + kB + (uint32_t)(q * 4352);
                LDSM_X4(bf[2*q][0], bf[2*q][1], bf[2*q+1][0], bf[2*q+1][1], ba);
            }
            #pragma unroll
            for (int nt = 0; nt < 8; ++nt)
                #pragma unroll
                for (int mt = 0; mt < 2; ++mt)
                    MMAF16(acc[mt][nt], af[mt], bf[nt]);
        }

        // epilogue (overlaps the in-flight prefetch)
        #pragma unroll
        for (int mt = 0; mt < 2; ++mt) {
            int r0 = m0 + wm * 32 + mt * 16 + g;
            #pragma unroll
            for (int nt = 0; nt < 8; ++nt) {
                int cc = n0 + wn * 64 + nt * 8 + 2 * t;
                float b0 = __ldg(&bias[cc]);
                float b1 = __ldg(&bias[cc + 1]);
                *(uint32_t*)&out[(size_t)r0 * QKV_N + cc] =
                    pack2h(acc[mt][nt][0] + b0, acc[mt][nt][1] + b1);
                *(uint32_t*)&out[(size_t)(r0 + 8) * QKV_N + cc] =
                    pack2h(acc[mt][nt][2] + b0, acc[mt][nt][3] + b1);
            }
        }
        __syncthreads();   // everyone done reading cur buffer before it becomes nxt
    }
}

// ============================================================================
// Fused fp16 attention + output projection (unchanged from round 12).
// ============================================================================
#define QR 136
#define SLB (64 * QR)
#define ATTN_ELEMS (3 * SLB)
#define ATTN_SM_BYTES (ATTN_ELEMS * 2)

__global__ void __launch_bounds__(512, 2) attn_fused(
    const __half* __restrict__ qkv, const float* __restrict__ rmb,
    const __half* __restrict__ wp,  const float* __restrict__ pbias,
    float* __restrict__ out)
{
    extern __shared__ __align__(16) __half sm[];
    __half* sq = sm;
    __half* sk = sm + SLB;
    __half* sv = sm + 2 * SLB;

    const int b    = blockIdx.x;
    const int tid  = threadIdx.x;
    const int lane = tid & 31;
    const int warp = tid >> 5;
    const int g    = lane >> 2;
    const int t    = lane & 3;
    const int h    = warp >> 2;
    const int wm   = warp & 3;

    {
        uint4 zz = make_uint4(0, 0, 0, 0);
        uint4* zp = (uint4*)sm;
        #pragma unroll 4
        for (int i = tid; i < ATTN_ELEMS / 8; i += 512) zp[i] = zz;
    }
    __syncthreads();

    for (int idx = tid; idx < 49 * 16; idx += 512) {
        int i = idx >> 4, seg = (idx & 15) * 8;
        size_t gb = (size_t)(b * N_ + i) * QKV_N + seg;
        cp16(sq + i * QR + seg, qkv + gb);
        cp16(sk + i * QR + seg, qkv + gb + 128);
        cp16(sv + i * QR + seg, qkv + gb + 256);
    }
    CP_ASYNC_COMMIT; CP_ASYNC_WAIT_0;
    __syncthreads();

    const int hoff = h * HD_;
    const int r0 = 16 * wm + g;
    const int r1 = r0 + 8;

    const uint32_t usq = smem_u32(sq);
    const uint32_t usv = smem_u32(sv);
    const uint32_t qaOff = ((16 * wm + (lane & 7) + ((lane >> 3) & 1) * 8) * QR
                            + hoff + ((lane >> 4) & 1) * 8) * 2;
    const uint32_t kbOff = (((lane & 7) + ((lane >> 4) & 1) * 8) * QR
                            + hoff + ((lane >> 3) & 1) * 8) * 2;
    const uint32_t vtOff = (((lane & 7) + ((lane >> 3) & 1) * 8) * QR
                            + ((lane >> 4) & 1) * 8) * 2;

    float sacc[8][4];
    #pragma unroll
    for (int nt = 0; nt < 8; ++nt)
        #pragma unroll
        for (int r = 0; r < 4; ++r) sacc[nt][r] = 0.f;

    #pragma unroll
    for (int ks = 0; ks < 2; ++ks) {
        const uint32_t kB = ks * 32;
        uint32_t ah[4];
        LDSM_X4(ah[0], ah[1], ah[2], ah[3], usq + qaOff + kB);
        #pragma unroll
        for (int p = 0; p < 4; ++p) {
            uint32_t bh[2][2];
            uint32_t ba = usq + (uint32_t)(SLB * 2) + kbOff + kB
                        + (uint32_t)(p * 16 * QR * 2);
            LDSM_X4(bh[0][0], bh[0][1], bh[1][0], bh[1][1], ba);
            MMAF16(sacc[2*p],     ah, bh[0]);
            MMAF16(sacc[2*p + 1], ah, bh[1]);
        }
    }
    __syncthreads();

    for (int idx = tid; idx < 128 * 16; idx += 512) {
        int r = idx >> 4, ch = (idx & 15) * 8;
        cp16(sq + r * QR + ch, wp + r * 128 + ch);
    }
    CP_ASYNC_COMMIT;

    const float* rmbw = rmb + (((b & (NW_ - 1)) * NH_ + h) * N_ * N_);
    float p0[16], p1[16];
    #pragma unroll
    for (int nt = 0; nt < 8; ++nt) {
        int c0 = 8 * nt + 2 * t;
        int c1 = c0 + 1;
        p0[2 * nt]     = (r0 < N_ && c0 < N_) ? fmaf(sacc[nt][0], SCALE_, __ldg(rmbw + r0 * N_ + c0)) : -1e30f;
        p0[2 * nt + 1] = (r0 < N_ && c1 < N_) ? fmaf(sacc[nt][1], SCALE_, __ldg(rmbw + r0 * N_ + c1)) : -1e30f;
        p1[2 * nt]     = (r1 < N_ && c0 < N_) ? fmaf(sacc[nt][2], SCALE_, __ldg(rmbw + r1 * N_ + c0)) : -1e30f;
        p1[2 * nt + 1] = (r1 < N_ && c1 < N_) ? fmaf(sacc[nt][3], SCALE_, __ldg(rmbw + r1 * N_ + c1)) : -1e30f;
    }
    float m0 = -1e30f, m1 = -1e30f;
    #pragma unroll
    for (int i = 0; i < 16; ++i) { m0 = fmaxf(m0, p0[i]); m1 = fmaxf(m1, p1[i]); }
    m0 = fmaxf(m0, __shfl_xor_sync(0xffffffffu, m0, 1));
    m0 = fmaxf(m0, __shfl_xor_sync(0xffffffffu, m0, 2));
    m1 = fmaxf(m1, __shfl_xor_sync(0xffffffffu, m1, 1));
    m1 = fmaxf(m1, __shfl_xor_sync(0xffffffffu, m1, 2));
    float s0 = 0.f, s1 = 0.f;
    #pragma unroll
    for (int i = 0; i < 16; ++i) {
        p0[i] = __expf(p0[i] - m0); s0 += p0[i];
        p1[i] = __expf(p1[i] - m1); s1 += p1[i];
    }
    s0 += __shfl_xor_sync(0xffffffffu, s0, 1);
    s0 += __shfl_xor_sync(0xffffffffu, s0, 2);
    s1 += __shfl_xor_sync(0xffffffffu, s1, 1);
    s1 += __shfl_xor_sync(0xffffffffu, s1, 2);
    float i0 = __frcp_rn(s0), i1 = __frcp_rn(s1);
    #pragma unroll
    for (int i = 0; i < 16; ++i) { p0[i] *= i0; p1[i] *= i1; }

    uint32_t pa[4][4];
    #pragma unroll
    for (int ks = 0; ks < 4; ++ks) {
        pa[ks][0] = pack2h(p0[4 * ks],     p0[4 * ks + 1]);
        pa[ks][1] = pack2h(p1[4 * ks],     p1[4 * ks + 1]);
        pa[ks][2] = pack2h(p0[4 * ks + 2], p0[4 * ks + 3]);
        pa[ks][3] = pack2h(p1[4 * ks + 2], p1[4 * ks + 3]);
    }

    float oacc[4][4];
    #pragma unroll
    for (int nt = 0; nt < 4; ++nt)
        #pragma unroll
        for (int r = 0; r < 4; ++r) oacc[nt][r] = 0.f;

    #pragma unroll
    for (int ks = 0; ks < 4; ++ks) {
        #pragma unroll
        for (int p = 0; p < 2; ++p) {
            uint32_t bh[2][2];
            uint32_t ba = usv + vtOff + (uint32_t)(ks * 16 * QR * 2)
                        + (hoff + p * 16) * 2;
            LDSM_X4T(bh[0][0], bh[0][1], bh[1][0], bh[1][1], ba);
            MMAF16(oacc[2*p],     pa[ks], bh[0]);
            MMAF16(oacc[2*p + 1], pa[ks], bh[1]);
        }
    }
    __syncthreads();

    #pragma unroll
    for (int nt = 0; nt < 4; ++nt) {
        int c = hoff + 8 * nt + 2 * t;
        *(uint32_t*)&sv[r0 * QR + c] = pack2h(oacc[nt][0], oacc[nt][1]);
        *(uint32_t*)&sv[r1 * QR + c] = pack2h(oacc[nt][2], oacc[nt][3]);
    }
    CP_ASYNC_WAIT_0;
    __syncthreads();

    const uint32_t oaOff = ((16 * wm + (lane & 7) + ((lane >> 3) & 1) * 8) * QR
                            + ((lane >> 4) & 1) * 8) * 2;
    const uint32_t wbOff = ((32 * h + (lane & 7) + ((lane >> 4) & 1) * 8) * QR
                            + ((lane >> 3) & 1) * 8) * 2;

    float pacc[4][4];
    #pragma unroll
    for (int nt = 0; nt < 4; ++nt)
        #pragma unroll
        for (int r = 0; r < 4; ++r) pacc[nt][r] = 0.f;

    #pragma unroll
    for (int ks = 0; ks < 8; ++ks) {
        const uint32_t kB = ks * 32;
        uint32_t ah[4];
        LDSM_X4(ah[0], ah[1], ah[2], ah[3], usv + oaOff + kB);
        #pragma unroll
        for (int p = 0; p < 2; ++p) {
            uint32_t bh[2][2];
            uint32_t ba = usq + wbOff + kB + (uint32_t)(p * 16 * QR * 2);
            LDSM_X4(bh[0][0], bh[0][1], bh[1][0], bh[1][1], ba);
            MMAF16(pacc[2*p],     ah, bh[0]);
            MMAF16(pacc[2*p + 1], ah, bh[1]);
        }
    }

    #pragma unroll
    for (int nt = 0; nt < 4; ++nt) {
        int c = 32 * h + 8 * nt + 2 * t;
        float b0 = __ldg(&pbias[c]);
        float b1 = __ldg(&pbias[c + 1]);
        if (r0 < N_)
            *(float2*)&out[((size_t)b * N_ + r0) * DIM_ + c] =
                make_float2(pacc[nt][0] + b0, pacc[nt][1] + b1);
        if (r1 < N_)
            *(float2*)&out[((size_t)b * N_ + r1) * DIM_ + c] =
                make_float2(pacc[nt][2] + b0, pacc[nt][3] + b1);
    }
}

// ============================================================================
// launch
// ============================================================================
extern "C" void kernel_launch(void* const* d_in, const int* in_sizes, int n_in,
                              void* d_out, int out_size)
{
    const float* x      = (const float*)d_in[0];
    const float* mask   = (const float*)d_in[1];
    const float* qkv_w  = (const float*)d_in[2];
    const float* qkv_b  = (const float*)d_in[3];
    const float* proj_w = (const float*)d_in[4];
    const float* proj_b = (const float*)d_in[5];
    const float* rpb    = (const float*)d_in[6];
    const int*   rel    = (const int*)d_in[7];
    float* out = (float*)d_out;

    __half *xp, *qkvp, *wqp, *wpp;
    float* rmbp;
    cudaGetSymbolAddress((void**)&xp,   g_x);
    cudaGetSymbolAddress((void**)&qkvp, g_qkv);
    cudaGetSymbolAddress((void**)&wqp,  g_wq);
    cudaGetSymbolAddress((void**)&wpp,  g_wp);
    cudaGetSymbolAddress((void**)&rmbp, g_rmb);

    static bool attr_set = false;
    if (!attr_set) {
        cudaFuncSetAttribute(gemm_qkv,   cudaFuncAttributeMaxDynamicSharedMemorySize, GEMM_SM_BYTES);
        cudaFuncSetAttribute(attn_fused, cudaFuncAttributeMaxDynamicSharedMemorySize, ATTN_SM_BYTES);
        attr_set = true;
    }

    convert_x<<<(M_TOTAL * DIM_ / 4) / 256, 256>>>(x);
    convert_w<<<64, 256>>>(qkv_w, proj_w);
    build_rmb<<<N_ * N_, 256>>>(mask, rpb, rel);

    // QKV projection (persistent fp16) -> fp16
    gemm_qkv<<<dim3(QKV_N / 128, GRIDY), 256, GEMM_SM_BYTES>>>(
        xp, wqp, qkv_b, qkvp);

    // fused window attention + output projection -> fp32 out
    attn_fused<<<B_, 512, ATTN_SM_BYTES>>>(qkvp, rmbp, wpp, proj_b, out);
}

// round 14
// speedup vs baseline: 2.6318x; 1.1839x over previous
#include <cuda_runtime.h>
#include <cuda_fp16.h>
#include <math.h>
#include <stdint.h>

// ---------------- problem constants ----------------
#define B_      8192
#define N_      49
#define DIM_    128
#define NH_     4
#define HD_     32
#define NW_     64
#define QKV_N   384
#define M_TOTAL (B_ * N_)          // 401408
#define MBLK    (M_TOTAL / 128)    // 3136 m-blocks
#define GRIDY   96                 // persistent m-group count
#define SCALE_  0.17677669529663687f  // 32^-0.5

// ---------------- scratch (device globals; allocation-free) ----------------
__device__ __half g_x[(size_t)M_TOTAL * DIM_];      // x fp16
__device__ __half g_qkv[(size_t)M_TOTAL * QKV_N];   // qkv fp16
__device__ __half g_wq[QKV_N * DIM_];               // fp16 weights
__device__ __half g_wp[DIM_ * DIM_];
// mask+rpb in per-thread mma-fragment order, guards baked in:
// [w][h][wm][chunk(8)][lane(32)][4 floats] = 1024 tiles * 1024 floats = 4MB
__device__ float g_rmbf[NW_ * NH_ * 4 * 1024];

// ---------------- helpers ----------------
#define MMAF16(d, a, b)                                                       \
  asm volatile(                                                               \
      "mma.sync.aligned.m16n8k16.row.col.f32.f16.f16.f32 "                    \
      "{%0,%1,%2,%3}, {%4,%5,%6,%7}, {%8,%9}, {%0,%1,%2,%3};"                 \
      : "+f"(d[0]), "+f"(d[1]), "+f"(d[2]), "+f"(d[3])                        \
      : "r"(a[0]), "r"(a[1]), "r"(a[2]), "r"(a[3]), "r"(b[0]), "r"(b[1]))

#define LDSM_X4(R0, R1, R2, R3, ADDR)                                         \
  asm volatile("ldmatrix.sync.aligned.m8n8.x4.shared.b16 {%0,%1,%2,%3}, [%4];"\
      : "=r"(R0), "=r"(R1), "=r"(R2), "=r"(R3) : "r"(ADDR))

#define LDSM_X4T(R0, R1, R2, R3, ADDR)                                        \
  asm volatile("ldmatrix.sync.aligned.m8n8.x4.trans.shared.b16 {%0,%1,%2,%3}, [%4];"\
      : "=r"(R0), "=r"(R1), "=r"(R2), "=r"(R3) : "r"(ADDR))

#define CP_ASYNC_COMMIT asm volatile("cp.async.commit_group;" ::: "memory")
#define CP_ASYNC_WAIT_0 asm volatile("cp.async.wait_group 0;" ::: "memory")

__device__ __forceinline__ void cp16(void* smem, const void* gmem)
{
    uint32_t s = (uint32_t)__cvta_generic_to_shared(smem);
    asm volatile("cp.async.cg.shared.global [%0], [%1], 16;" :: "r"(s), "l"(gmem));
}

__device__ __forceinline__ uint32_t smem_u32(const void* p) {
    uint32_t a;
    asm("{ .reg .u64 t; cvta.to.shared.u64 t, %1; cvt.u32.u64 %0, t; }" : "=r"(a) : "l"(p));
    return a;
}

__device__ __forceinline__ uint32_t pack2h(float a, float b)
{
    __half2 h = __floats2half2_rn(a, b);
    return *(uint32_t*)&h;
}

// ============================================================================
// setup kernels
// ============================================================================
__global__ void convert_x(const float* __restrict__ x)
{
    size_t i = (size_t)blockIdx.x * 256 + threadIdx.x;
    float4 v = ((const float4*)x)[i];
    ((uint2*)g_x)[i] = make_uint2(pack2h(v.x, v.y), pack2h(v.z, v.w));
}

__global__ void convert_w(const float* __restrict__ qkv_w, const float* __restrict__ proj_w)
{
    int i = blockIdx.x * 256 + threadIdx.x;
    float4 v = (i < 12288) ? ((const float4*)qkv_w)[i]
                           : ((const float4*)proj_w)[i - 12288];
    uint2 p = make_uint2(pack2h(v.x, v.y), pack2h(v.z, v.w));
    if (i < 12288) ((uint2*)g_wq)[i] = p;
    else           ((uint2*)g_wp)[i - 12288] = p;
}

// mask+rpb in mma C-fragment order with out-of-range guards baked in.
// index: idx = (((w*4 + h)*4 + wm)*8 + c8)*32 + lane  (one float4 per idx)
__global__ void build_rmbf(const float* __restrict__ mask, const float* __restrict__ rpb,
                           const int* __restrict__ rel)
{
    int idx = blockIdx.x * 256 + threadIdx.x;   // 0..262143
    int lane = idx & 31;
    int c8   = (idx >> 5) & 7;
    int wm   = (idx >> 8) & 3;
    int h    = (idx >> 10) & 3;
    int w    = idx >> 12;
    float v[4];
    #pragma unroll
    for (int j = 0; j < 4; ++j) {
        int i   = c8 * 4 + j;            // 0..31
        int hb  = i >> 4;                // 0: rows r0, 1: rows r0+8
        int ii  = i & 15;
        int row = 16 * wm + (lane >> 2) + 8 * hb;
        int col = 8 * (ii >> 1) + 2 * (lane & 3) + (ii & 1);
        v[j] = (row < N_ && col < N_)
             ? mask[w * N_ * N_ + row * N_ + col] + rpb[rel[row * N_ + col] * NH_ + h]
             : -1e30f;
    }
    ((float4*)g_rmbf)[idx] = make_float4(v[0], v[1], v[2], v[3]);
}

// ============================================================================
// Persistent fp16 HMMA GEMM: qkv = x @ Wq^T + bias (fp16 out).
// Wq n-block resident; A double-buffered; STAGED epilogue: pack into the dead
// A buffer (conflict-free STS.32), then coalesced STG.128.
// ============================================================================
#define AROW 136                     // row stride (halfs)
#define ASLAB (128 * AROW)
#define GEMM_SM_BYTES (3 * ASLAB * (int)sizeof(__half))   // 104448

__global__ void __launch_bounds__(256, 2) gemm_qkv(
    const __half* __restrict__ X, const __half* __restrict__ W,
    const float* __restrict__ bias, __half* __restrict__ out)
{
    extern __shared__ __align__(16) __half sm[];
    __half* sA0 = sm;
    __half* sA1 = sm + ASLAB;
    __half* sB  = sm + 2 * ASLAB;

    const int tid  = threadIdx.x;
    const int lane = tid & 31;
    const int warp = tid >> 5;
    const int wm   = warp & 3;
    const int wn   = warp >> 2;
    const int g    = lane >> 2;
    const int t    = lane & 3;
    const int n0   = blockIdx.x * 128;

    auto ld_A = [&](__half* dst, int m0) {
        #pragma unroll
        for (int it = 0; it < 8; ++it) {
            int idx = tid + it * 256;
            int row = idx >> 4;
            int c8  = (idx & 15) * 8;
            cp16(dst + row * AROW + c8, X + (size_t)(m0 + row) * DIM_ + c8);
        }
    };

    // prologue: B (resident) + A(0)
    #pragma unroll
    for (int it = 0; it < 8; ++it) {
        int idx = tid + it * 256;
        int row = idx >> 4;
        int c8  = (idx & 15) * 8;
        cp16(sB + row * AROW + c8, W + (size_t)(n0 + row) * DIM_ + c8);
    }
    ld_A(sA0, blockIdx.y * 128);
    CP_ASYNC_COMMIT;

    const uint32_t uB = smem_u32(sB);
    const uint32_t aOff = ((wm * 32 + (lane & 7) + ((lane >> 3) & 1) * 8) * AROW
                           + ((lane >> 4) & 1) * 8) * 2;
    const uint32_t bOff = ((wn * 64 + (lane & 7) + ((lane >> 4) & 1) * 8) * AROW
                           + ((lane >> 3) & 1) * 8) * 2;

    // bias hoisted out of the persistent loop
    float bb[8][2];
    #pragma unroll
    for (int nt = 0; nt < 8; ++nt) {
        int cc = n0 + wn * 64 + nt * 8 + 2 * t;
        bb[nt][0] = __ldg(&bias[cc]);
        bb[nt][1] = __ldg(&bias[cc + 1]);
    }

    int par = 0;
    for (int mb = blockIdx.y; mb < MBLK; mb += GRIDY, par ^= 1) {
        const int m0 = mb * 128;
        __half* cur = par ? sA1 : sA0;
        __half* nxt = par ? sA0 : sA1;
        const uint32_t uA = smem_u32(cur);

        CP_ASYNC_WAIT_0;
        __syncthreads();

        if (mb + GRIDY < MBLK) {
            ld_A(nxt, (mb + GRIDY) * 128);
            CP_ASYNC_COMMIT;
        }

        float acc[2][8][4];
        #pragma unroll
        for (int mt = 0; mt < 2; ++mt)
            #pragma unroll
            for (int nt = 0; nt < 8; ++nt)
                #pragma unroll
                for (int r = 0; r < 4; ++r) acc[mt][nt][r] = 0.f;

        #pragma unroll
        for (int ks = 0; ks < 8; ++ks) {
            const uint32_t kB = ks * 32;
            uint32_t af[2][4], bf[8][2];
            LDSM_X4(af[0][0], af[0][1], af[0][2], af[0][3], uA + aOff + kB);
            LDSM_X4(af[1][0], af[1][1], af[1][2], af[1][3], uA + aOff + kB + 4352);
            #pragma unroll
            for (int q = 0; q < 4; ++q) {
                uint32_t ba = uB + bOff + kB + (uint32_t)(q * 4352);
                LDSM_X4(bf[2*q][0], bf[2*q][1], bf[2*q+1][0], bf[2*q+1][1], ba);
            }
            #pragma unroll
            for (int nt = 0; nt < 8; ++nt)
                #pragma unroll
                for (int mt = 0; mt < 2; ++mt)
                    MMAF16(acc[mt][nt], af[mt], bf[nt]);
        }

        __syncthreads();   // all warps done reading cur A -> reuse as staging

        // stage fp16 output tile into cur (STS.32, bank = 4g+t -> conflict-free)
        #pragma unroll
        for (int mt = 0; mt < 2; ++mt) {
            int rr = wm * 32 + mt * 16 + g;
            #pragma unroll
            for (int nt = 0; nt < 8; ++nt) {
                int cc = wn * 64 + nt * 8 + 2 * t;
                *(uint32_t*)&cur[rr * AROW + cc] =
                    pack2h(acc[mt][nt][0] + bb[nt][0], acc[mt][nt][1] + bb[nt][1]);
                *(uint32_t*)&cur[(rr + 8) * AROW + cc] =
                    pack2h(acc[mt][nt][2] + bb[nt][0], acc[mt][nt][3] + bb[nt][1]);
            }
        }
        __syncthreads();

        // coalesced copy-out: 128 rows x 128 halfs
        #pragma unroll
        for (int it = 0; it < 8; ++it) {
            int idx = tid + it * 256;
            int row = idx >> 4;
            int c8  = (idx & 15) * 8;
            *(uint4*)&out[(size_t)(m0 + row) * QKV_N + n0 + c8] =
                *(const uint4*)&cur[row * AROW + c8];
        }
        // next iteration's WAIT0+sync orders these reads before cur is re-filled
    }
}

// ============================================================================
// Fused fp16 attention + output projection. One CTA/window, 512 threads.
// rmb read via fragment-layout table (coalesced LDG.128, guards baked in).
// Minimal pad zeroing (rows 49..63 of q/k/v only).
// ============================================================================
#define QR 136
#define SLB (64 * QR)
#define ATTN_ELEMS (3 * SLB)
#define ATTN_SM_BYTES (ATTN_ELEMS * 2)

__global__ void __launch_bounds__(512, 2) attn_fused(
    const __half* __restrict__ qkv, const float* __restrict__ rmbf,
    const __half* __restrict__ wp,  const float* __restrict__ pbias,
    float* __restrict__ out)
{
    extern __shared__ __align__(16) __half sm[];
    __half* sq = sm;                // later Wp rows 0-63
    __half* sk = sm + SLB;          // later Wp rows 64-127
    __half* sv = sm + 2 * SLB;      // later O

    const int b    = blockIdx.x;
    const int tid  = threadIdx.x;
    const int lane = tid & 31;
    const int warp = tid >> 5;
    const int g    = lane >> 2;
    const int t    = lane & 3;
    const int h    = warp >> 2;
    const int wm   = warp & 3;

    // zero ONLY pad rows 49..63 of q,k,v (255 uint4 each, 16B-aligned base)
    {
        uint4 zz = make_uint4(0, 0, 0, 0);
        for (int idx = tid; idx < 768; idx += 512) {
            int slab = idx >> 8, off = idx & 255;
            if (off < 255)
                ((uint4*)(sm + slab * SLB + 49 * QR))[off] = zz;
        }
    }
    // load q, k, v rows (disjoint from pad rows -> no barrier needed between)
    for (int idx = tid; idx < 49 * 16; idx += 512) {
        int i = idx >> 4, seg = (idx & 15) * 8;
        size_t gb = (size_t)(b * N_ + i) * QKV_N + seg;
        cp16(sq + i * QR + seg, qkv + gb);
        cp16(sk + i * QR + seg, qkv + gb + 128);
        cp16(sv + i * QR + seg, qkv + gb + 256);
    }
    CP_ASYNC_COMMIT; CP_ASYNC_WAIT_0;
    __syncthreads();

    const int hoff = h * HD_;
    const int r0 = 16 * wm + g;
    const int r1 = r0 + 8;

    const uint32_t usq = smem_u32(sq);
    const uint32_t usv = smem_u32(sv);
    const uint32_t qaOff = ((16 * wm + (lane & 7) + ((lane >> 3) & 1) * 8) * QR
                            + hoff + ((lane >> 4) & 1) * 8) * 2;
    const uint32_t kbOff = (((lane & 7) + ((lane >> 4) & 1) * 8) * QR
                            + hoff + ((lane >> 3) & 1) * 8) * 2;
    const uint32_t vtOff = (((lane & 7) + ((lane >> 3) & 1) * 8) * QR
                            + ((lane >> 4) & 1) * 8) * 2;

    // ---- S = Q K^T ----
    float sacc[8][4];
    #pragma unroll
    for (int nt = 0; nt < 8; ++nt)
        #pragma unroll
        for (int r = 0; r < 4; ++r) sacc[nt][r] = 0.f;

    #pragma unroll
    for (int ks = 0; ks < 2; ++ks) {
        const uint32_t kB = ks * 32;
        uint32_t ah[4];
        LDSM_X4(ah[0], ah[1], ah[2], ah[3], usq + qaOff + kB);
        #pragma unroll
        for (int p = 0; p < 4; ++p) {
            uint32_t bh[2][2];
            uint32_t ba = usq + (uint32_t)(SLB * 2) + kbOff + kB
                        + (uint32_t)(p * 16 * QR * 2);
            LDSM_X4(bh[0][0], bh[0][1], bh[1][0], bh[1][1], ba);
            MMAF16(sacc[2*p],     ah, bh[0]);
            MMAF16(sacc[2*p + 1], ah, bh[1]);
        }
    }
    __syncthreads();   // q,k smem dead

    // overlap: load Wp into q/k smem space
    for (int idx = tid; idx < 128 * 16; idx += 512) {
        int r = idx >> 4, ch = (idx & 15) * 8;
        cp16(sq + r * QR + ch, wp + r * 128 + ch);
    }
    CP_ASYNC_COMMIT;

    // ---- rmb fragments (coalesced LDG.128, guards baked in) + softmax ----
    float rv[32];
    {
        const float4* rf = (const float4*)rmbf
                         + ((((b & (NW_ - 1)) * NH_ + h) * 4 + wm) * 256) + lane;
        #pragma unroll
        for (int c8 = 0; c8 < 8; ++c8) {
            float4 vv = __ldg(rf + c8 * 32);
            rv[c8 * 4]     = vv.x;
            rv[c8 * 4 + 1] = vv.y;
            rv[c8 * 4 + 2] = vv.z;
            rv[c8 * 4 + 3] = vv.w;
        }
    }
    float p0[16], p1[16];
    #pragma unroll
    for (int i = 0; i < 16; ++i) {
        p0[i] = fmaf(sacc[i >> 1][i & 1],       SCALE_, rv[i]);
        p1[i] = fmaf(sacc[i >> 1][2 + (i & 1)], SCALE_, rv[16 + i]);
    }
    float m0 = -1e30f, m1 = -1e30f;
    #pragma unroll
    for (int i = 0; i < 16; ++i) { m0 = fmaxf(m0, p0[i]); m1 = fmaxf(m1, p1[i]); }
    m0 = fmaxf(m0, __shfl_xor_sync(0xffffffffu, m0, 1));
    m0 = fmaxf(m0, __shfl_xor_sync(0xffffffffu, m0, 2));
    m1 = fmaxf(m1, __shfl_xor_sync(0xffffffffu, m1, 1));
    m1 = fmaxf(m1, __shfl_xor_sync(0xffffffffu, m1, 2));
    float s0 = 0.f, s1 = 0.f;
    #pragma unroll
    for (int i = 0; i < 16; ++i) {
        p0[i] = __expf(p0[i] - m0); s0 += p0[i];
        p1[i] = __expf(p1[i] - m1); s1 += p1[i];
    }
    s0 += __shfl_xor_sync(0xffffffffu, s0, 1);
    s0 += __shfl_xor_sync(0xffffffffu, s0, 2);
    s1 += __shfl_xor_sync(0xffffffffu, s1, 1);
    s1 += __shfl_xor_sync(0xffffffffu, s1, 2);
    float i0 = __frcp_rn(s0), i1 = __frcp_rn(s1);
    #pragma unroll
    for (int i = 0; i < 16; ++i) { p0[i] *= i0; p1[i] *= i1; }

    // ---- P -> PV A-fragments ----
    uint32_t pa[4][4];
    #pragma unroll
    for (int ks = 0; ks < 4; ++ks) {
        pa[ks][0] = pack2h(p0[4 * ks],     p0[4 * ks + 1]);
        pa[ks][1] = pack2h(p1[4 * ks],     p1[4 * ks + 1]);
        pa[ks][2] = pack2h(p0[4 * ks + 2], p0[4 * ks + 3]);
        pa[ks][3] = pack2h(p1[4 * ks + 2], p1[4 * ks + 3]);
    }

    // ---- O = P V ----
    float oacc[4][4];
    #pragma unroll
    for (int nt = 0; nt < 4; ++nt)
        #pragma unroll
        for (int r = 0; r < 4; ++r) oacc[nt][r] = 0.f;

    #pragma unroll
    for (int ks = 0; ks < 4; ++ks) {
        #pragma unroll
        for (int p = 0; p < 2; ++p) {
            uint32_t bh[2][2];
            uint32_t ba = usv + vtOff + (uint32_t)(ks * 16 * QR * 2)
                        + (hoff + p * 16) * 2;
            LDSM_X4T(bh[0][0], bh[0][1], bh[1][0], bh[1][1], ba);
            MMAF16(oacc[2*p],     pa[ks], bh[0]);
            MMAF16(oacc[2*p + 1], pa[ks], bh[1]);
        }
    }
    __syncthreads();   // all PV reads of sv done

    // ---- store O (fp16) into V smem space ----
    #pragma unroll
    for (int nt = 0; nt < 4; ++nt) {
        int c = hoff + 8 * nt + 2 * t;
        *(uint32_t*)&sv[r0 * QR + c] = pack2h(oacc[nt][0], oacc[nt][1]);
        *(uint32_t*)&sv[r1 * QR + c] = pack2h(oacc[nt][2], oacc[nt][3]);
    }
    CP_ASYNC_WAIT_0;   // Wp resident
    __syncthreads();   // O visible

    // ---- proj: out = O @ Wp^T + pbias ----
    const uint32_t oaOff = ((16 * wm + (lane & 7) + ((lane >> 3) & 1) * 8) * QR
                            + ((lane >> 4) & 1) * 8) * 2;
    const uint32_t wbOff = ((32 * h + (lane & 7) + ((lane >> 4) & 1) * 8) * QR
                            + ((lane >> 3) & 1) * 8) * 2;

    float pacc[4][4];
    #pragma unroll
    for (int nt = 0; nt < 4; ++nt)
        #pragma unroll
        for (int r = 0; r < 4; ++r) pacc[nt][r] = 0.f;

    #pragma unroll
    for (int ks = 0; ks < 8; ++ks) {
        const uint32_t kB = ks * 32;
        uint32_t ah[4];
        LDSM_X4(ah[0], ah[1], ah[2], ah[3], usv + oaOff + kB);
        #pragma unroll
        for (int p = 0; p < 2; ++p) {
            uint32_t bh[2][2];
            uint32_t ba = usq + wbOff + kB + (uint32_t)(p * 16 * QR * 2);
            LDSM_X4(bh[0][0], bh[0][1], bh[1][0], bh[1][1], ba);
            MMAF16(pacc[2*p],     ah, bh[0]);
            MMAF16(pacc[2*p + 1], ah, bh[1]);
        }
    }

    // ---- epilogue: fp32 out ----
    #pragma unroll
    for (int nt = 0; nt < 4; ++nt) {
        int c = 32 * h + 8 * nt + 2 * t;
        float b0 = __ldg(&pbias[c]);
        float b1 = __ldg(&pbias[c + 1]);
        if (r0 < N_)
            *(float2*)&out[((size_t)b * N_ + r0) * DIM_ + c] =
                make_float2(pacc[nt][0] + b0, pacc[nt][1] + b1);
        if (r1 < N_)
            *(float2*)&out[((size_t)b * N_ + r1) * DIM_ + c] =
                make_float2(pacc[nt][2] + b0, pacc[nt][3] + b1);
    }
}

// ============================================================================
// launch
// ============================================================================
extern "C" void kernel_launch(void* const* d_in, const int* in_sizes, int n_in,
                              void* d_out, int out_size)
{
    const float* x      = (const float*)d_in[0];
    const float* mask   = (const float*)d_in[1];
    const float* qkv_w  = (const float*)d_in[2];
    const float* qkv_b  = (const float*)d_in[3];
    const float* proj_w = (const float*)d_in[4];
    const float* proj_b = (const float*)d_in[5];
    const float* rpb    = (const float*)d_in[6];
    const int*   rel    = (const int*)d_in[7];
    float* out = (float*)d_out;

    __half *xp, *qkvp, *wqp, *wpp;
    float* rmbfp;
    cudaGetSymbolAddress((void**)&xp,    g_x);
    cudaGetSymbolAddress((void**)&qkvp,  g_qkv);
    cudaGetSymbolAddress((void**)&wqp,   g_wq);
    cudaGetSymbolAddress((void**)&wpp,   g_wp);
    cudaGetSymbolAddress((void**)&rmbfp, g_rmbf);

    static bool attr_set = false;
    if (!attr_set) {
        cudaFuncSetAttribute(gemm_qkv,   cudaFuncAttributeMaxDynamicSharedMemorySize, GEMM_SM_BYTES);
        cudaFuncSetAttribute(attn_fused, cudaFuncAttributeMaxDynamicSharedMemorySize, ATTN_SM_BYTES);
        attr_set = true;
    }

    convert_x<<<(M_TOTAL * DIM_ / 4) / 256, 256>>>(x);
    convert_w<<<64, 256>>>(qkv_w, proj_w);
    build_rmbf<<<1024, 256>>>(mask, rpb, rel);

    // QKV projection (persistent fp16, staged epilogue) -> fp16
    gemm_qkv<<<dim3(QKV_N / 128, GRIDY), 256, GEMM_SM_BYTES>>>(
        xp, wqp, qkv_b, qkvp);

    // fused window attention + output projection -> fp32 out
    attn_fused<<<B_, 512, ATTN_SM_BYTES>>>(qkvp, rmbfp, wpp, proj_b, out);
}

// round 15
// speedup vs baseline: 2.7622x; 1.0495x over previous
#include <cuda_runtime.h>
#include <cuda_fp16.h>
#include <math.h>
#include <stdint.h>

// ---------------- problem constants ----------------
#define B_      8192
#define N_      49
#define DIM_    128
#define NH_     4
#define HD_     32
#define NW_     64
#define QKV_N   384
#define M_TOTAL (B_ * N_)
#define GRID    148
#define SCALE_  0.17677669529663687f  // 32^-0.5

// ---------------- scratch (device globals; allocation-free) ----------------
__device__ __half g_x[(size_t)M_TOTAL * DIM_];      // x fp16
__device__ __half g_wq[QKV_N * DIM_];               // fp16 weights
__device__ __half g_wp[DIM_ * DIM_];
// mask+rpb in per-thread mma-fragment order, guards baked in (4MB, L2-hot)
__device__ float g_rmbf[NW_ * NH_ * 4 * 1024];

// ---------------- helpers ----------------
#define MMAF16(d, a, b)                                                       \
  asm volatile(                                                               \
      "mma.sync.aligned.m16n8k16.row.col.f32.f16.f16.f32 "                    \
      "{%0,%1,%2,%3}, {%4,%5,%6,%7}, {%8,%9}, {%0,%1,%2,%3};"                 \
      : "+f"(d[0]), "+f"(d[1]), "+f"(d[2]), "+f"(d[3])                        \
      : "r"(a[0]), "r"(a[1]), "r"(a[2]), "r"(a[3]), "r"(b[0]), "r"(b[1]))

#define LDSM_X4(R0, R1, R2, R3, ADDR)                                         \
  asm volatile("ldmatrix.sync.aligned.m8n8.x4.shared.b16 {%0,%1,%2,%3}, [%4];"\
      : "=r"(R0), "=r"(R1), "=r"(R2), "=r"(R3) : "r"(ADDR))

#define LDSM_X4T(R0, R1, R2, R3, ADDR)                                        \
  asm volatile("ldmatrix.sync.aligned.m8n8.x4.trans.shared.b16 {%0,%1,%2,%3}, [%4];"\
      : "=r"(R0), "=r"(R1), "=r"(R2), "=r"(R3) : "r"(ADDR))

#define CP_ASYNC_COMMIT asm volatile("cp.async.commit_group;" ::: "memory")
#define CP_ASYNC_WAIT_1 asm volatile("cp.async.wait_group 1;" ::: "memory")
#define CP_ASYNC_WAIT_0 asm volatile("cp.async.wait_group 0;" ::: "memory")

__device__ __forceinline__ void cp16(void* smem, const void* gmem)
{
    uint32_t s = (uint32_t)__cvta_generic_to_shared(smem);
    asm volatile("cp.async.cg.shared.global [%0], [%1], 16;" :: "r"(s), "l"(gmem));
}

__device__ __forceinline__ uint32_t smem_u32(const void* p) {
    uint32_t a;
    asm("{ .reg .u64 t; cvta.to.shared.u64 t, %1; cvt.u32.u64 %0, t; }" : "=r"(a) : "l"(p));
    return a;
}

__device__ __forceinline__ uint32_t pack2h(float a, float b)
{
    __half2 h = __floats2half2_rn(a, b);
    return *(uint32_t*)&h;
}

// ============================================================================
// setup kernels
// ============================================================================
__global__ void convert_x(const float* __restrict__ x)
{
    size_t i = (size_t)blockIdx.x * 256 + threadIdx.x;
    float4 v = ((const float4*)x)[i];
    ((uint2*)g_x)[i] = make_uint2(pack2h(v.x, v.y), pack2h(v.z, v.w));
}

__global__ void convert_w(const float* __restrict__ qkv_w, const float* __restrict__ proj_w)
{
    int i = blockIdx.x * 256 + threadIdx.x;
    float4 v = (i < 12288) ? ((const float4*)qkv_w)[i]
                           : ((const float4*)proj_w)[i - 12288];
    uint2 p = make_uint2(pack2h(v.x, v.y), pack2h(v.z, v.w));
    if (i < 12288) ((uint2*)g_wq)[i] = p;
    else           ((uint2*)g_wp)[i - 12288] = p;
}

__global__ void build_rmbf(const float* __restrict__ mask, const float* __restrict__ rpb,
                           const int* __restrict__ rel)
{
    int idx = blockIdx.x * 256 + threadIdx.x;   // 0..262143
    int lane = idx & 31;
    int c8   = (idx >> 5) & 7;
    int wm   = (idx >> 8) & 3;
    int h    = (idx >> 10) & 3;
    int w    = idx >> 12;
    float v[4];
    #pragma unroll
    for (int j = 0; j < 4; ++j) {
        int i   = c8 * 4 + j;
        int hb  = i >> 4;
        int ii  = i & 15;
        int row = 16 * wm + (lane >> 2) + 8 * hb;
        int col = 8 * (ii >> 1) + 2 * (lane & 3) + (ii & 1);
        v[j] = (row < N_ && col < N_)
             ? mask[w * N_ * N_ + row * N_ + col] + rpb[rel[row * N_ + col] * NH_ + h]
             : -1e30f;
    }
    ((float4*)g_rmbf)[idx] = make_float4(v[0], v[1], v[2], v[3]);
}

// ============================================================================
// Fully-fused persistent kernel: per window, QKV gemm -> attention -> proj.
// 148 CTAs x 512 threads. Weights resident in smem; x double-buffered via
// cp.async; qkv never touches DRAM.
// ============================================================================
#define QR   136
#define SLB  (64 * QR)            // 8704 halfs
#define WQH  (QKV_N * QR)         // 52224 halfs
#define WPH  (DIM_ * QR)          // 17408 halfs
#define SM_HALFS (WQH + WPH + 2 * SLB + 3 * SLB)   // 113152
#define FUSED_SM_BYTES (SM_HALFS * 2)              // 226304

__global__ void __launch_bounds__(512, 1) fused_all(
    const __half* __restrict__ xg, const float* __restrict__ rmbf,
    const __half* __restrict__ wqg, const __half* __restrict__ wpg,
    const float* __restrict__ qbias, const float* __restrict__ pbias,
    float* __restrict__ out)
{
    extern __shared__ __align__(16) __half sm[];
    __half* sWq = sm;                       // [384][QR]
    __half* sWp = sm + WQH;                 // [128][QR]
    __half* sX0 = sm + WQH + WPH;           // [64][QR] x / O-staging
    __half* sX1 = sX0 + SLB;
    __half* sQ  = sX1 + SLB;                // [64][QR]
    __half* sK  = sQ + SLB;
    __half* sV  = sK + SLB;

    const int tid  = threadIdx.x;
    const int lane = tid & 31;
    const int warp = tid >> 5;
    const int g    = lane >> 2;
    const int t    = lane & 3;
    const int h    = warp >> 2;     // attn head / qkv n-group
    const int wm   = warp & 3;      // m-tile

    auto ld_x = [&](__half* dst, int b) {
        for (int idx = tid; idx < N_ * 16; idx += 512) {
            int i = idx >> 4, seg = (idx & 15) * 8;
            cp16(dst + i * QR + seg, xg + (size_t)(b * N_ + i) * DIM_ + seg);
        }
    };
    auto zero_pads = [&](__half* dst) {   // rows 49..63
        uint4 zz = make_uint4(0, 0, 0, 0);
        uint4* zp = (uint4*)(dst + 49 * QR);
        for (int i = tid; i < 255; i += 512) zp[i] = zz;
    };

    // ---- prologue: weights + first x + pads ----
    for (int idx = tid; idx < QKV_N * 16; idx += 512) {
        int r = idx >> 4, c8 = (idx & 15) * 8;
        cp16(sWq + r * QR + c8, wqg + r * DIM_ + c8);
    }
    for (int idx = tid; idx < DIM_ * 16; idx += 512) {
        int r = idx >> 4, c8 = (idx & 15) * 8;
        cp16(sWp + r * QR + c8, wpg + r * DIM_ + c8);
    }
    zero_pads(sX0);
    zero_pads(sX1);
    if (blockIdx.x < B_) ld_x(sX0, blockIdx.x);
    CP_ASYNC_COMMIT;

    // per-warp constant bias fragments
    float qb[12][2];
    #pragma unroll
    for (int nt = 0; nt < 12; ++nt) {
        int cc = h * 96 + nt * 8 + 2 * t;
        qb[nt][0] = __ldg(&qbias[cc]);
        qb[nt][1] = __ldg(&qbias[cc + 1]);
    }
    float pb0 = 0.f, pb1 = 0.f, pb2 = 0.f, pb3 = 0.f,
          pb4 = 0.f, pb5 = 0.f, pb6 = 0.f, pb7 = 0.f;
    {
        int c = 32 * h + 2 * t;
        pb0 = __ldg(&pbias[c]);      pb1 = __ldg(&pbias[c + 1]);
        pb2 = __ldg(&pbias[c + 8]);  pb3 = __ldg(&pbias[c + 9]);
        pb4 = __ldg(&pbias[c + 16]); pb5 = __ldg(&pbias[c + 17]);
        pb6 = __ldg(&pbias[c + 24]); pb7 = __ldg(&pbias[c + 25]);
    }

    const uint32_t uWq = smem_u32(sWq);
    const uint32_t uWp = smem_u32(sWp);
    const uint32_t uQ  = smem_u32(sQ);
    const uint32_t uV  = smem_u32(sV);

    // fragment lane offsets (bytes)
    const uint32_t aOff  = ((16 * wm + (lane & 7) + ((lane >> 3) & 1) * 8) * QR
                            + ((lane >> 4) & 1) * 8) * 2;          // A rows 16wm, k cols
    const uint32_t wqOff = ((h * 96 + (lane & 7) + ((lane >> 4) & 1) * 8) * QR
                            + ((lane >> 3) & 1) * 8) * 2;          // Wq n rows
    const uint32_t qaOff = aOff + (h * HD_) * 2;                   // Q A-frag (head cols)
    const uint32_t kbOff = (((lane & 7) + ((lane >> 4) & 1) * 8) * QR
                            + h * HD_ + ((lane >> 3) & 1) * 8) * 2; // K B-frag
    const uint32_t vtOff = (((lane & 7) + ((lane >> 3) & 1) * 8) * QR
                            + ((lane >> 4) & 1) * 8) * 2;          // V trans
    const uint32_t wbOff = ((32 * h + (lane & 7) + ((lane >> 4) & 1) * 8) * QR
                            + ((lane >> 3) & 1) * 8) * 2;          // Wp B-frag

    const int r0 = 16 * wm + g;
    const int r1 = r0 + 8;
    const int hoff = h * HD_;

    int par = 0;
    for (int b = blockIdx.x; b < B_; b += GRID, par ^= 1) {
        __half* xc = par ? sX1 : sX0;
        __half* xn = par ? sX0 : sX1;
        const uint32_t uX = smem_u32(xc);

        // prefetch next window's x into the other buffer; re-zero its pads
        if (b + GRID < B_) {
            zero_pads(xn);
            ld_x(xn, b + GRID);
            CP_ASYNC_COMMIT;
            CP_ASYNC_WAIT_1;          // current x resident
        } else {
            CP_ASYNC_WAIT_0;
        }
        __syncthreads();              // x(b) ready; prev iteration fully done

        // ================= QKV gemm: qkv = x @ Wq^T + bias =================
        float qacc[12][4];
        #pragma unroll
        for (int nt = 0; nt < 12; ++nt)
            #pragma unroll
            for (int r = 0; r < 4; ++r) qacc[nt][r] = 0.f;

        #pragma unroll
        for (int ks = 0; ks < 8; ++ks) {
            const uint32_t kB = ks * 32;
            uint32_t af[4], bf[12][2];
            LDSM_X4(af[0], af[1], af[2], af[3], uX + aOff + kB);
            #pragma unroll
            for (int p = 0; p < 6; ++p) {
                uint32_t ba = uWq + wqOff + kB + (uint32_t)(p * 16 * QR * 2);
                LDSM_X4(bf[2*p][0], bf[2*p][1], bf[2*p+1][0], bf[2*p+1][1], ba);
            }
            #pragma unroll
            for (int nt = 0; nt < 12; ++nt)
                MMAF16(qacc[nt], af, bf[nt]);
        }

        __syncthreads();   // all qkv LDSM reads of xc done (xc becomes O staging later)

        // epilogue: bias + pack fp16 into q/k/v slabs (conflict-free STS.32)
        #pragma unroll
        for (int nt = 0; nt < 12; ++nt) {
            int cc = h * 96 + nt * 8 + 2 * t;
            __half* slab = sQ + (cc >> 7) * SLB;
            int off = cc & 127;
            *(uint32_t*)&slab[r0 * QR + off] =
                pack2h(qacc[nt][0] + qb[nt][0], qacc[nt][1] + qb[nt][1]);
            *(uint32_t*)&slab[r1 * QR + off] =
                pack2h(qacc[nt][2] + qb[nt][0], qacc[nt][3] + qb[nt][1]);
        }
        __syncthreads();   // qkv visible

        // ================= S = Q K^T =================
        float sacc[8][4];
        #pragma unroll
        for (int nt = 0; nt < 8; ++nt)
            #pragma unroll
            for (int r = 0; r < 4; ++r) sacc[nt][r] = 0.f;

        #pragma unroll
        for (int ks = 0; ks < 2; ++ks) {
            const uint32_t kB = ks * 32;
            uint32_t ah[4];
            LDSM_X4(ah[0], ah[1], ah[2], ah[3], uQ + qaOff + kB);
            #pragma unroll
            for (int p = 0; p < 4; ++p) {
                uint32_t bh[2][2];
                uint32_t ba = uQ + (uint32_t)(SLB * 2) + kbOff + kB
                            + (uint32_t)(p * 16 * QR * 2);
                LDSM_X4(bh[0][0], bh[0][1], bh[1][0], bh[1][1], ba);
                MMAF16(sacc[2*p],     ah, bh[0]);
                MMAF16(sacc[2*p + 1], ah, bh[1]);
            }
        }

        // ================= softmax (rmb fragments, guards baked in) =========
        float rv[32];
        {
            const float4* rf = (const float4*)rmbf
                             + ((((b & (NW_ - 1)) * NH_ + h) * 4 + wm) * 256) + lane;
            #pragma unroll
            for (int c8 = 0; c8 < 8; ++c8) {
                float4 vv = __ldg(rf + c8 * 32);
                rv[c8 * 4]     = vv.x;
                rv[c8 * 4 + 1] = vv.y;
                rv[c8 * 4 + 2] = vv.z;
                rv[c8 * 4 + 3] = vv.w;
            }
        }
        float p0[16], p1[16];
        #pragma unroll
        for (int i = 0; i < 16; ++i) {
            p0[i] = fmaf(sacc[i >> 1][i & 1],       SCALE_, rv[i]);
            p1[i] = fmaf(sacc[i >> 1][2 + (i & 1)], SCALE_, rv[16 + i]);
        }
        float m0 = -1e30f, m1 = -1e30f;
        #pragma unroll
        for (int i = 0; i < 16; ++i) { m0 = fmaxf(m0, p0[i]); m1 = fmaxf(m1, p1[i]); }
        m0 = fmaxf(m0, __shfl_xor_sync(0xffffffffu, m0, 1));
        m0 = fmaxf(m0, __shfl_xor_sync(0xffffffffu, m0, 2));
        m1 = fmaxf(m1, __shfl_xor_sync(0xffffffffu, m1, 1));
        m1 = fmaxf(m1, __shfl_xor_sync(0xffffffffu, m1, 2));
        float s0 = 0.f, s1 = 0.f;
        #pragma unroll
        for (int i = 0; i < 16; ++i) {
            p0[i] = __expf(p0[i] - m0); s0 += p0[i];
            p1[i] = __expf(p1[i] - m1); s1 += p1[i];
        }
        s0 += __shfl_xor_sync(0xffffffffu, s0, 1);
        s0 += __shfl_xor_sync(0xffffffffu, s0, 2);
        s1 += __shfl_xor_sync(0xffffffffu, s1, 1);
        s1 += __shfl_xor_sync(0xffffffffu, s1, 2);
        float i0 = __frcp_rn(s0), i1 = __frcp_rn(s1);
        #pragma unroll
        for (int i = 0; i < 16; ++i) { p0[i] *= i0; p1[i] *= i1; }

        // ================= O = P V =================
        uint32_t pa[4][4];
        #pragma unroll
        for (int ks = 0; ks < 4; ++ks) {
            pa[ks][0] = pack2h(p0[4 * ks],     p0[4 * ks + 1]);
            pa[ks][1] = pack2h(p1[4 * ks],     p1[4 * ks + 1]);
            pa[ks][2] = pack2h(p0[4 * ks + 2], p0[4 * ks + 3]);
            pa[ks][3] = pack2h(p1[4 * ks + 2], p1[4 * ks + 3]);
        }

        float oacc[4][4];
        #pragma unroll
        for (int nt = 0; nt < 4; ++nt)
            #pragma unroll
            for (int r = 0; r < 4; ++r) oacc[nt][r] = 0.f;

        #pragma unroll
        for (int ks = 0; ks < 4; ++ks) {
            #pragma unroll
            for (int p = 0; p < 2; ++p) {
                uint32_t bh[2][2];
                uint32_t ba = uV + vtOff + (uint32_t)(ks * 16 * QR * 2)
                            + (hoff + p * 16) * 2;
                LDSM_X4T(bh[0][0], bh[0][1], bh[1][0], bh[1][1], ba);
                MMAF16(oacc[2*p],     pa[ks], bh[0]);
                MMAF16(oacc[2*p + 1], pa[ks], bh[1]);
            }
        }

        // ---- stage O (fp16) into xc (x buffer is dead) ----
        #pragma unroll
        for (int nt = 0; nt < 4; ++nt) {
            int c = hoff + 8 * nt + 2 * t;
            *(uint32_t*)&xc[r0 * QR + c] = pack2h(oacc[nt][0], oacc[nt][1]);
            *(uint32_t*)&xc[r1 * QR + c] = pack2h(oacc[nt][2], oacc[nt][3]);
        }
        __syncthreads();   // O visible

        // ================= proj: out = O @ Wp^T + pbias =================
        float pacc[4][4];
        #pragma unroll
        for (int nt = 0; nt < 4; ++nt)
            #pragma unroll
            for (int r = 0; r < 4; ++r) pacc[nt][r] = 0.f;

        #pragma unroll
        for (int ks = 0; ks < 8; ++ks) {
            const uint32_t kB = ks * 32;
            uint32_t ah[4];
            LDSM_X4(ah[0], ah[1], ah[2], ah[3], uX + aOff + kB);
            #pragma unroll
            for (int p = 0; p < 2; ++p) {
                uint32_t bh[2][2];
                uint32_t ba = uWp + wbOff + kB + (uint32_t)(p * 16 * QR * 2);
                LDSM_X4(bh[0][0], bh[0][1], bh[1][0], bh[1][1], ba);
                MMAF16(pacc[2*p],     ah, bh[0]);
                MMAF16(pacc[2*p + 1], ah, bh[1]);
            }
        }
        __syncthreads();   // all proj reads of xc done before next ld_x/O-staging

        // ---- epilogue: fp32 out (rows < 49 only) ----
        if (r0 < N_) {
            size_t ob = ((size_t)b * N_ + r0) * DIM_ + 32 * h + 2 * t;
            *(float2*)&out[ob]      = make_float2(pacc[0][0] + pb0, pacc[0][1] + pb1);
            *(float2*)&out[ob + 8]  = make_float2(pacc[1][0] + pb2, pacc[1][1] + pb3);
            *(float2*)&out[ob + 16] = make_float2(pacc[2][0] + pb4, pacc[2][1] + pb5);
            *(float2*)&out[ob + 24] = make_float2(pacc[3][0] + pb6, pacc[3][1] + pb7);
        }
        if (r1 < N_) {
            size_t ob = ((size_t)b * N_ + r1) * DIM_ + 32 * h + 2 * t;
            *(float2*)&out[ob]      = make_float2(pacc[0][2] + pb0, pacc[0][3] + pb1);
            *(float2*)&out[ob + 8]  = make_float2(pacc[1][2] + pb2, pacc[1][3] + pb3);
            *(float2*)&out[ob + 16] = make_float2(pacc[2][2] + pb4, pacc[2][3] + pb5);
            *(float2*)&out[ob + 24] = make_float2(pacc[3][2] + pb6, pacc[3][3] + pb7);
        }
    }
}

// ============================================================================
// launch
// ============================================================================
extern "C" void kernel_launch(void* const* d_in, const int* in_sizes, int n_in,
                              void* d_out, int out_size)
{
    const float* x      = (const float*)d_in[0];
    const float* mask   = (const float*)d_in[1];
    const float* qkv_w  = (const float*)d_in[2];
    const float* qkv_b  = (const float*)d_in[3];
    const float* proj_w = (const float*)d_in[4];
    const float* proj_b = (const float*)d_in[5];
    const float* rpb    = (const float*)d_in[6];
    const int*   rel    = (const int*)d_in[7];
    float* out = (float*)d_out;

    __half *xp, *wqp, *wpp;
    float* rmbfp;
    cudaGetSymbolAddress((void**)&xp,    g_x);
    cudaGetSymbolAddress((void**)&wqp,   g_wq);
    cudaGetSymbolAddress((void**)&wpp,   g_wp);
    cudaGetSymbolAddress((void**)&rmbfp, g_rmbf);

    static bool attr_set = false;
    if (!attr_set) {
        cudaFuncSetAttribute(fused_all, cudaFuncAttributeMaxDynamicSharedMemorySize,
                             FUSED_SM_BYTES);
        attr_set = true;
    }

    convert_x<<<(M_TOTAL * DIM_ / 4) / 256, 256>>>(x);
    convert_w<<<64, 256>>>(qkv_w, proj_w);
    build_rmbf<<<1024, 256>>>(mask, rpb, rel);

    fused_all<<<GRID, 512, FUSED_SM_BYTES>>>(xp, rmbfp, wqp, wpp, qkv_b, proj_b, out);
}

// round 16
// speedup vs baseline: 3.0628x; 1.1088x over previous
#include <cuda_runtime.h>
#include <cuda_fp16.h>
#include <math.h>
#include <stdint.h>

// ---------------- problem constants ----------------
#define B_      8192
#define N_      49
#define DIM_    128
#define NH_     4
#define HD_     32
#define NW_     64
#define QKV_N   384
#define M_TOTAL (B_ * N_)
#define GRID    148
#define SCALE_  0.17677669529663687f  // 32^-0.5

// ---------------- scratch (device globals; allocation-free) ----------------
__device__ __half g_x[(size_t)M_TOTAL * DIM_];      // x fp16
__device__ __half g_wq[QKV_N * DIM_];               // fp16 weights
__device__ __half g_wp[DIM_ * DIM_];
// mask+rpb in per-thread mma-fragment order, guards baked in (4MB, L2-hot)
__device__ float g_rmbf[NW_ * NH_ * 4 * 1024];

// ---------------- helpers ----------------
#define MMAF16(d, a, b)                                                       \
  asm volatile(                                                               \
      "mma.sync.aligned.m16n8k16.row.col.f32.f16.f16.f32 "                    \
      "{%0,%1,%2,%3}, {%4,%5,%6,%7}, {%8,%9}, {%0,%1,%2,%3};"                 \
      : "+f"(d[0]), "+f"(d[1]), "+f"(d[2]), "+f"(d[3])                        \
      : "r"(a[0]), "r"(a[1]), "r"(a[2]), "r"(a[3]), "r"(b[0]), "r"(b[1]))

#define LDSM_X4(R0, R1, R2, R3, ADDR)                                         \
  asm volatile("ldmatrix.sync.aligned.m8n8.x4.shared.b16 {%0,%1,%2,%3}, [%4];"\
      : "=r"(R0), "=r"(R1), "=r"(R2), "=r"(R3) : "r"(ADDR))

#define LDSM_X4T(R0, R1, R2, R3, ADDR)                                        \
  asm volatile("ldmatrix.sync.aligned.m8n8.x4.trans.shared.b16 {%0,%1,%2,%3}, [%4];"\
      : "=r"(R0), "=r"(R1), "=r"(R2), "=r"(R3) : "r"(ADDR))

#define CP_ASYNC_COMMIT asm volatile("cp.async.commit_group;" ::: "memory")
#define CP_ASYNC_WAIT_1 asm volatile("cp.async.wait_group 1;" ::: "memory")
#define CP_ASYNC_WAIT_0 asm volatile("cp.async.wait_group 0;" ::: "memory")

__device__ __forceinline__ void cp16(void* smem, const void* gmem)
{
    uint32_t s = (uint32_t)__cvta_generic_to_shared(smem);
    asm volatile("cp.async.cg.shared.global [%0], [%1], 16;" :: "r"(s), "l"(gmem));
}

__device__ __forceinline__ uint32_t smem_u32(const void* p) {
    uint32_t a;
    asm("{ .reg .u64 t; cvta.to.shared.u64 t, %1; cvt.u32.u64 %0, t; }" : "=r"(a) : "l"(p));
    return a;
}

__device__ __forceinline__ uint32_t pack2h(float a, float b)
{
    __half2 h = __floats2half2_rn(a, b);
    return *(uint32_t*)&h;
}

// ============================================================================
// setup kernels
// ============================================================================
__global__ void convert_x(const float* __restrict__ x)
{
    size_t i = (size_t)blockIdx.x * 256 + threadIdx.x;
    float4 v = ((const float4*)x)[i];
    ((uint2*)g_x)[i] = make_uint2(pack2h(v.x, v.y), pack2h(v.z, v.w));
}

__global__ void convert_w(const float* __restrict__ qkv_w, const float* __restrict__ proj_w)
{
    int i = blockIdx.x * 256 + threadIdx.x;
    float4 v = (i < 12288) ? ((const float4*)qkv_w)[i]
                           : ((const float4*)proj_w)[i - 12288];
    uint2 p = make_uint2(pack2h(v.x, v.y), pack2h(v.z, v.w));
    if (i < 12288) ((uint2*)g_wq)[i] = p;
    else           ((uint2*)g_wp)[i - 12288] = p;
}

__global__ void build_rmbf(const float* __restrict__ mask, const float* __restrict__ rpb,
                           const int* __restrict__ rel)
{
    int idx = blockIdx.x * 256 + threadIdx.x;   // 0..262143
    int lane = idx & 31;
    int c8   = (idx >> 5) & 7;
    int wm   = (idx >> 8) & 3;
    int h    = (idx >> 10) & 3;
    int w    = idx >> 12;
    float v[4];
    #pragma unroll
    for (int j = 0; j < 4; ++j) {
        int i   = c8 * 4 + j;
        int hb  = i >> 4;
        int ii  = i & 15;
        int row = 16 * wm + (lane >> 2) + 8 * hb;
        int col = 8 * (ii >> 1) + 2 * (lane & 3) + (ii & 1);
        v[j] = (row < N_ && col < N_)
             ? mask[w * N_ * N_ + row * N_ + col] + rpb[rel[row * N_ + col] * NH_ + h]
             : -1e30f;
    }
    ((float4*)g_rmbf)[idx] = make_float4(v[0], v[1], v[2], v[3]);
}

// ============================================================================
// Fully-fused persistent kernel: per window, QKV gemm -> attention -> proj.
// QKV warp tile 32x48 (better ldsm:mma ratio). O staged in sV (dead after PV);
// x-buffer pads zeroed once. Softmax without max-pass (bounded logits).
// ============================================================================
#define QR   136
#define SLB  (64 * QR)            // 8704 halfs
#define WQH  (QKV_N * QR)         // 52224 halfs
#define WPH  (DIM_ * QR)          // 17408 halfs
#define SM_HALFS (WQH + WPH + 2 * SLB + 3 * SLB)   // 113152
#define FUSED_SM_BYTES (SM_HALFS * 2)              // 226304

__global__ void __launch_bounds__(512, 1) fused_all(
    const __half* __restrict__ xg, const float* __restrict__ rmbf,
    const __half* __restrict__ wqg, const __half* __restrict__ wpg,
    const float* __restrict__ qbias, const float* __restrict__ pbias,
    float* __restrict__ out)
{
    extern __shared__ __align__(16) __half sm[];
    __half* sWq = sm;                       // [384][QR]
    __half* sWp = sm + WQH;                 // [128][QR]
    __half* sX0 = sm + WQH + WPH;           // [64][QR]
    __half* sX1 = sX0 + SLB;
    __half* sQ  = sX1 + SLB;                // [64][QR]
    __half* sK  = sQ + SLB;
    __half* sV  = sK + SLB;                 // V; later O staging

    const int tid  = threadIdx.x;
    const int lane = tid & 31;
    const int warp = tid >> 5;
    const int g    = lane >> 2;
    const int t    = lane & 3;
    // attention-phase mapping
    const int h    = warp >> 2;
    const int wm   = warp & 3;
    // qkv-phase mapping (32x48 warp tile)
    const int wm2  = warp & 1;      // 2 m-tiles of 32 rows
    const int wn   = warp >> 1;     // 8 n-slices of 48 cols

    auto ld_x = [&](__half* dst, int b) {
        for (int idx = tid; idx < N_ * 16; idx += 512) {
            int i = idx >> 4, seg = (idx & 15) * 8;
            cp16(dst + i * QR + seg, xg + (size_t)(b * N_ + i) * DIM_ + seg);
        }
    };

    // ---- prologue: weights + x pads (once) + first x ----
    for (int idx = tid; idx < QKV_N * 16; idx += 512) {
        int r = idx >> 4, c8 = (idx & 15) * 8;
        cp16(sWq + r * QR + c8, wqg + r * DIM_ + c8);
    }
    for (int idx = tid; idx < DIM_ * 16; idx += 512) {
        int r = idx >> 4, c8 = (idx & 15) * 8;
        cp16(sWp + r * QR + c8, wpg + r * DIM_ + c8);
    }
    {
        uint4 zz = make_uint4(0, 0, 0, 0);
        uint4* z0 = (uint4*)(sX0 + 49 * QR);
        uint4* z1 = (uint4*)(sX1 + 49 * QR);
        for (int i = tid; i < 255; i += 512) { z0[i] = zz; z1[i] = zz; }
    }
    if (blockIdx.x < B_) ld_x(sX0, blockIdx.x);
    CP_ASYNC_COMMIT;

    // per-warp constant bias fragments (qkv phase: cols 48*wn + 8nt + 2t)
    float qb[6][2];
    #pragma unroll
    for (int nt = 0; nt < 6; ++nt) {
        int cc = wn * 48 + nt * 8 + 2 * t;
        qb[nt][0] = __ldg(&qbias[cc]);
        qb[nt][1] = __ldg(&qbias[cc + 1]);
    }
    float pb[4][2];
    #pragma unroll
    for (int nt = 0; nt < 4; ++nt) {
        int c = 32 * h + 8 * nt + 2 * t;
        pb[nt][0] = __ldg(&pbias[c]);
        pb[nt][1] = __ldg(&pbias[c + 1]);
    }

    const uint32_t uWq = smem_u32(sWq);
    const uint32_t uWp = smem_u32(sWp);
    const uint32_t uQ  = smem_u32(sQ);
    const uint32_t uV  = smem_u32(sV);

    // fragment lane offsets (bytes)
    const uint32_t aOffQ = ((32 * wm2 + (lane & 7) + ((lane >> 3) & 1) * 8) * QR
                            + ((lane >> 4) & 1) * 8) * 2;          // QKV A (rows 32*wm2)
    const uint32_t wqOff = ((wn * 48 + (lane & 7) + ((lane >> 4) & 1) * 8) * QR
                            + ((lane >> 3) & 1) * 8) * 2;          // QKV B (Wq rows 48*wn)
    const uint32_t qaOff = ((16 * wm + (lane & 7) + ((lane >> 3) & 1) * 8) * QR
                            + h * HD_ + ((lane >> 4) & 1) * 8) * 2; // S A (Q)
    const uint32_t kbOff = (((lane & 7) + ((lane >> 4) & 1) * 8) * QR
                            + h * HD_ + ((lane >> 3) & 1) * 8) * 2; // S B (K)
    const uint32_t vtOff = (((lane & 7) + ((lane >> 3) & 1) * 8) * QR
                            + ((lane >> 4) & 1) * 8) * 2;          // PV B (V trans)
    const uint32_t oaOff = ((16 * wm + (lane & 7) + ((lane >> 3) & 1) * 8) * QR
                            + ((lane >> 4) & 1) * 8) * 2;          // proj A (O rows)
    const uint32_t wbOff = ((32 * h + (lane & 7) + ((lane >> 4) & 1) * 8) * QR
                            + ((lane >> 3) & 1) * 8) * 2;          // proj B (Wp)

    const int r0 = 16 * wm + g;
    const int r1 = r0 + 8;
    const int hoff = h * HD_;

    int par = 0;
    for (int b = blockIdx.x; b < B_; b += GRID, par ^= 1) {
        __half* xc = par ? sX1 : sX0;
        __half* xn = par ? sX0 : sX1;
        const uint32_t uX = smem_u32(xc);

        if (b + GRID < B_) {
            ld_x(xn, b + GRID);
            CP_ASYNC_COMMIT;
            CP_ASYNC_WAIT_1;
        } else {
            CP_ASYNC_WAIT_0;
        }
        __syncthreads();              // x(b) ready; prev window fully done

        // ================= QKV gemm (warp tile 32x48) =================
        float qacc[2][6][4];
        #pragma unroll
        for (int mt = 0; mt < 2; ++mt)
            #pragma unroll
            for (int nt = 0; nt < 6; ++nt)
                #pragma unroll
                for (int r = 0; r < 4; ++r) qacc[mt][nt][r] = 0.f;

        #pragma unroll
        for (int ks = 0; ks < 8; ++ks) {
            const uint32_t kB = ks * 32;
            uint32_t af[2][4], bf[6][2];
            LDSM_X4(af[0][0], af[0][1], af[0][2], af[0][3], uX + aOffQ + kB);
            LDSM_X4(af[1][0], af[1][1], af[1][2], af[1][3], uX + aOffQ + kB + 16 * QR * 2);
            #pragma unroll
            for (int p = 0; p < 3; ++p) {
                uint32_t ba = uWq + wqOff + kB + (uint32_t)(p * 16 * QR * 2);
                LDSM_X4(bf[2*p][0], bf[2*p][1], bf[2*p+1][0], bf[2*p+1][1], ba);
            }
            #pragma unroll
            for (int nt = 0; nt < 6; ++nt)
                #pragma unroll
                for (int mt = 0; mt < 2; ++mt)
                    MMAF16(qacc[mt][nt], af[mt], bf[nt]);
        }

        __syncthreads();   // all qkv reads of xc done

        // epilogue: bias + pack fp16 into q/k/v slabs (conflict-free STS.32)
        #pragma unroll
        for (int mt = 0; mt < 2; ++mt) {
            int rq = 32 * wm2 + 16 * mt + g;
            #pragma unroll
            for (int nt = 0; nt < 6; ++nt) {
                int cc = wn * 48 + nt * 8 + 2 * t;
                __half* slab = sQ + (cc >> 7) * SLB;
                int off = cc & 127;
                *(uint32_t*)&slab[rq * QR + off] =
                    pack2h(qacc[mt][nt][0] + qb[nt][0], qacc[mt][nt][1] + qb[nt][1]);
                *(uint32_t*)&slab[(rq + 8) * QR + off] =
                    pack2h(qacc[mt][nt][2] + qb[nt][0], qacc[mt][nt][3] + qb[nt][1]);
            }
        }
        __syncthreads();   // qkv visible

        // ---- rmb fragments early (overlap L2 latency with S mma) ----
        float rv[32];
        {
            const float4* rf = (const float4*)rmbf
                             + ((((b & (NW_ - 1)) * NH_ + h) * 4 + wm) * 256) + lane;
            #pragma unroll
            for (int c8 = 0; c8 < 8; ++c8) {
                float4 vv = __ldg(rf + c8 * 32);
                rv[c8 * 4]     = vv.x;
                rv[c8 * 4 + 1] = vv.y;
                rv[c8 * 4 + 2] = vv.z;
                rv[c8 * 4 + 3] = vv.w;
            }
        }

        // ================= S = Q K^T =================
        float sacc[8][4];
        #pragma unroll
        for (int nt = 0; nt < 8; ++nt)
            #pragma unroll
            for (int r = 0; r < 4; ++r) sacc[nt][r] = 0.f;

        #pragma unroll
        for (int ks = 0; ks < 2; ++ks) {
            const uint32_t kB = ks * 32;
            uint32_t ah[4];
            LDSM_X4(ah[0], ah[1], ah[2], ah[3], uQ + qaOff + kB);
            #pragma unroll
            for (int p = 0; p < 4; ++p) {
                uint32_t bh[2][2];
                uint32_t ba = uQ + (uint32_t)(SLB * 2) + kbOff + kB
                            + (uint32_t)(p * 16 * QR * 2);
                LDSM_X4(bh[0][0], bh[0][1], bh[1][0], bh[1][1], ba);
                MMAF16(sacc[2*p],     ah, bh[0]);
                MMAF16(sacc[2*p + 1], ah, bh[1]);
            }
        }

        // ================= softmax (no max pass; logits bounded) ===========
        float p0[16], p1[16];
        float s0 = 0.f, s1 = 0.f;
        #pragma unroll
        for (int i = 0; i < 16; ++i) {
            p0[i] = __expf(fmaf(sacc[i >> 1][i & 1],       SCALE_, rv[i]));
            p1[i] = __expf(fmaf(sacc[i >> 1][2 + (i & 1)], SCALE_, rv[16 + i]));
            s0 += p0[i]; s1 += p1[i];
        }
        s0 += __shfl_xor_sync(0xffffffffu, s0, 1);
        s0 += __shfl_xor_sync(0xffffffffu, s0, 2);
        s1 += __shfl_xor_sync(0xffffffffu, s1, 1);
        s1 += __shfl_xor_sync(0xffffffffu, s1, 2);
        float i0 = __frcp_rn(fmaxf(s0, 1e-30f));
        float i1 = __frcp_rn(fmaxf(s1, 1e-30f));
        #pragma unroll
        for (int i = 0; i < 16; ++i) { p0[i] *= i0; p1[i] *= i1; }

        // ================= O = P V =================
        uint32_t pa[4][4];
        #pragma unroll
        for (int ks = 0; ks < 4; ++ks) {
            pa[ks][0] = pack2h(p0[4 * ks],     p0[4 * ks + 1]);
            pa[ks][1] = pack2h(p1[4 * ks],     p1[4 * ks + 1]);
            pa[ks][2] = pack2h(p0[4 * ks + 2], p0[4 * ks + 3]);
            pa[ks][3] = pack2h(p1[4 * ks + 2], p1[4 * ks + 3]);
        }

        float oacc[4][4];
        #pragma unroll
        for (int nt = 0; nt < 4; ++nt)
            #pragma unroll
            for (int r = 0; r < 4; ++r) oacc[nt][r] = 0.f;

        #pragma unroll
        for (int ks = 0; ks < 4; ++ks) {
            #pragma unroll
            for (int p = 0; p < 2; ++p) {
                uint32_t bh[2][2];
                uint32_t ba = uV + vtOff + (uint32_t)(ks * 16 * QR * 2)
                            + (hoff + p * 16) * 2;
                LDSM_X4T(bh[0][0], bh[0][1], bh[1][0], bh[1][1], ba);
                MMAF16(oacc[2*p],     pa[ks], bh[0]);
                MMAF16(oacc[2*p + 1], pa[ks], bh[1]);
            }
        }
        __syncthreads();   // all PV reads of sV done

        // ---- stage O (fp16) into sV (dead) ----
        #pragma unroll
        for (int nt = 0; nt < 4; ++nt) {
            int c = hoff + 8 * nt + 2 * t;
            *(uint32_t*)&sV[r0 * QR + c] = pack2h(oacc[nt][0], oacc[nt][1]);
            *(uint32_t*)&sV[r1 * QR + c] = pack2h(oacc[nt][2], oacc[nt][3]);
        }
        __syncthreads();   // O visible

        // ================= proj: out = O @ Wp^T + pbias =================
        float pacc[4][4];
        #pragma unroll
        for (int nt = 0; nt < 4; ++nt)
            #pragma unroll
            for (int r = 0; r < 4; ++r) pacc[nt][r] = 0.f;

        #pragma unroll
        for (int ks = 0; ks < 8; ++ks) {
            const uint32_t kB = ks * 32;
            uint32_t ah[4];
            LDSM_X4(ah[0], ah[1], ah[2], ah[3], uV + oaOff + kB);
            #pragma unroll
            for (int p = 0; p < 2; ++p) {
                uint32_t bh[2][2];
                uint32_t ba = uWp + wbOff + kB + (uint32_t)(p * 16 * QR * 2);
                LDSM_X4(bh[0][0], bh[0][1], bh[1][0], bh[1][1], ba);
                MMAF16(pacc[2*p],     ah, bh[0]);
                MMAF16(pacc[2*p + 1], ah, bh[1]);
            }
        }

        // ---- epilogue: fp32 out (rows < 49 only) ----
        if (r0 < N_) {
            size_t ob = ((size_t)b * N_ + r0) * DIM_ + 32 * h + 2 * t;
            #pragma unroll
            for (int nt = 0; nt < 4; ++nt)
                *(float2*)&out[ob + 8 * nt] =
                    make_float2(pacc[nt][0] + pb[nt][0], pacc[nt][1] + pb[nt][1]);
        }
        if (r1 < N_) {
            size_t ob = ((size_t)b * N_ + r1) * DIM_ + 32 * h + 2 * t;
            #pragma unroll
            for (int nt = 0; nt < 4; ++nt)
                *(float2*)&out[ob + 8 * nt] =
                    make_float2(pacc[nt][2] + pb[nt][0], pacc[nt][3] + pb[nt][1]);
        }
    }
}

// ============================================================================
// launch
// ============================================================================
extern "C" void kernel_launch(void* const* d_in, const int* in_sizes, int n_in,
                              void* d_out, int out_size)
{
    const float* x      = (const float*)d_in[0];
    const float* mask   = (const float*)d_in[1];
    const float* qkv_w  = (const float*)d_in[2];
    const float* qkv_b  = (const float*)d_in[3];
    const float* proj_w = (const float*)d_in[4];
    const float* proj_b = (const float*)d_in[5];
    const float* rpb    = (const float*)d_in[6];
    const int*   rel    = (const int*)d_in[7];
    float* out = (float*)d_out;

    __half *xp, *wqp, *wpp;
    float* rmbfp;
    cudaGetSymbolAddress((void**)&xp,    g_x);
    cudaGetSymbolAddress((void**)&wqp,   g_wq);
    cudaGetSymbolAddress((void**)&wpp,   g_wp);
    cudaGetSymbolAddress((void**)&rmbfp, g_rmbf);

    static bool attr_set = false;
    if (!attr_set) {
        cudaFuncSetAttribute(fused_all, cudaFuncAttributeMaxDynamicSharedMemorySize,
                             FUSED_SM_BYTES);
        attr_set = true;
    }

    convert_x<<<(M_TOTAL * DIM_ / 4) / 256, 256>>>(x);
    convert_w<<<64, 256>>>(qkv_w, proj_w);
    build_rmbf<<<1024, 256>>>(mask, rpb, rel);

    fused_all<<<GRID, 512, FUSED_SM_BYTES>>>(xp, rmbfp, wqp, wpp, qkv_b, proj_b, out);
}

// round 17
// speedup vs baseline: 3.3162x; 1.0827x over previous
#include <cuda_runtime.h>
#include <cuda_fp16.h>
#include <math.h>
#include <stdint.h>

// ---------------- problem constants ----------------
#define B_      8192
#define N_      49
#define DIM_    128
#define NH_     4
#define HD_     32
#define NW_     64
#define QKV_N   384
#define M_TOTAL (B_ * N_)
#define GRID    148
#define SCALE_  0.17677669529663687f  // 32^-0.5

// ---------------- scratch (device globals; allocation-free) ----------------
__device__ __half g_wq[QKV_N * DIM_];               // fp16 weights
__device__ __half g_wp[DIM_ * DIM_];
// mask+rpb in per-thread mma-fragment order, guards baked in (4MB, L2-hot)
__device__ float g_rmbf[NW_ * NH_ * 4 * 1024];

// ---------------- helpers ----------------
#define MMAF16(d, a, b)                                                       \
  asm volatile(                                                               \
      "mma.sync.aligned.m16n8k16.row.col.f32.f16.f16.f32 "                    \
      "{%0,%1,%2,%3}, {%4,%5,%6,%7}, {%8,%9}, {%0,%1,%2,%3};"                 \
      : "+f"(d[0]), "+f"(d[1]), "+f"(d[2]), "+f"(d[3])                        \
      : "r"(a[0]), "r"(a[1]), "r"(a[2]), "r"(a[3]), "r"(b[0]), "r"(b[1]))

#define LDSM_X4(R0, R1, R2, R3, ADDR)                                         \
  asm volatile("ldmatrix.sync.aligned.m8n8.x4.shared.b16 {%0,%1,%2,%3}, [%4];"\
      : "=r"(R0), "=r"(R1), "=r"(R2), "=r"(R3) : "r"(ADDR))

#define LDSM_X4T(R0, R1, R2, R3, ADDR)                                        \
  asm volatile("ldmatrix.sync.aligned.m8n8.x4.trans.shared.b16 {%0,%1,%2,%3}, [%4];"\
      : "=r"(R0), "=r"(R1), "=r"(R2), "=r"(R3) : "r"(ADDR))

#define CP_ASYNC_COMMIT asm volatile("cp.async.commit_group;" ::: "memory")
#define CP_ASYNC_WAIT_0 asm volatile("cp.async.wait_group 0;" ::: "memory")

__device__ __forceinline__ void cp16(void* smem, const void* gmem)
{
    uint32_t s = (uint32_t)__cvta_generic_to_shared(smem);
    asm volatile("cp.async.cg.shared.global [%0], [%1], 16;" :: "r"(s), "l"(gmem));
}

__device__ __forceinline__ uint32_t smem_u32(const void* p) {
    uint32_t a;
    asm("{ .reg .u64 t; cvta.to.shared.u64 t, %1; cvt.u32.u64 %0, t; }" : "=r"(a) : "l"(p));
    return a;
}

__device__ __forceinline__ uint32_t pack2h(float a, float b)
{
    __half2 h = __floats2half2_rn(a, b);
    return *(uint32_t*)&h;
}

// ============================================================================
// setup kernels
// ============================================================================
__global__ void convert_w(const float* __restrict__ qkv_w, const float* __restrict__ proj_w)
{
    int i = blockIdx.x * 256 + threadIdx.x;
    float4 v = (i < 12288) ? ((const float4*)qkv_w)[i]
                           : ((const float4*)proj_w)[i - 12288];
    uint2 p = make_uint2(pack2h(v.x, v.y), pack2h(v.z, v.w));
    if (i < 12288) ((uint2*)g_wq)[i] = p;
    else           ((uint2*)g_wp)[i - 12288] = p;
}

__global__ void build_rmbf(const float* __restrict__ mask, const float* __restrict__ rpb,
                           const int* __restrict__ rel)
{
    int idx = blockIdx.x * 256 + threadIdx.x;   // 0..262143
    int lane = idx & 31;
    int c8   = (idx >> 5) & 7;
    int wm   = (idx >> 8) & 3;
    int h    = (idx >> 10) & 3;
    int w    = idx >> 12;
    float v[4];
    #pragma unroll
    for (int j = 0; j < 4; ++j) {
        int i   = c8 * 4 + j;
        int hb  = i >> 4;
        int ii  = i & 15;
        int row = 16 * wm + (lane >> 2) + 8 * hb;
        int col = 8 * (ii >> 1) + 2 * (lane & 3) + (ii & 1);
        v[j] = (row < N_ && col < N_)
             ? mask[w * N_ * N_ + row * N_ + col] + rpb[rel[row * N_ + col] * NH_ + h]
             : -1e30f;
    }
    ((float4*)g_rmbf)[idx] = make_float4(v[0], v[1], v[2], v[3]);
}

// ============================================================================
// Fully-fused persistent kernel. x consumed as fp32 directly: LDG-prefetched
// two windows ahead into registers, converted + STS'd into a single fp16
// x slab after the current window's qkv reads finish.
// ============================================================================
#define QR   136
#define SLB  (64 * QR)            // 8704 halfs
#define WQH  (QKV_N * QR)         // 52224 halfs
#define WPH  (DIM_ * QR)          // 17408 halfs
#define SM_HALFS (WQH + WPH + SLB + 3 * SLB)       // 104448
#define FUSED_SM_BYTES (SM_HALFS * 2)              // 208896

#define XF4  (N_ * 32)            // 1568 float4 per window

__global__ void __launch_bounds__(512, 1) fused_all(
    const float* __restrict__ xg, const float* __restrict__ rmbf,
    const __half* __restrict__ wqg, const __half* __restrict__ wpg,
    const float* __restrict__ qbias, const float* __restrict__ pbias,
    float* __restrict__ out)
{
    extern __shared__ __align__(16) __half sm[];
    __half* sWq = sm;                       // [384][QR]
    __half* sWp = sm + WQH;                 // [128][QR]
    __half* sX  = sm + WQH + WPH;           // [64][QR] x (fp16)
    __half* sQ  = sX + SLB;                 // [64][QR]
    __half* sK  = sQ + SLB;
    __half* sV  = sK + SLB;                 // V; later O staging

    const int tid  = threadIdx.x;
    const int lane = tid & 31;
    const int warp = tid >> 5;
    const int g    = lane >> 2;
    const int t    = lane & 3;
    // attention-phase mapping
    const int h    = warp >> 2;
    const int wm   = warp & 3;
    // qkv-phase mapping (32x48 warp tile)
    const int wm2  = warp & 1;
    const int wn   = warp >> 1;

    // ---- prologue: weights (cp.async) ----
    for (int idx = tid; idx < QKV_N * 16; idx += 512) {
        int r = idx >> 4, c8 = (idx & 15) * 8;
        cp16(sWq + r * QR + c8, wqg + r * DIM_ + c8);
    }
    for (int idx = tid; idx < DIM_ * 16; idx += 512) {
        int r = idx >> 4, c8 = (idx & 15) * 8;
        cp16(sWp + r * QR + c8, wpg + r * DIM_ + c8);
    }
    CP_ASYNC_COMMIT;

    // zero x pad rows 49..63 (once; STS below never touches them)
    {
        uint4 zz = make_uint4(0, 0, 0, 0);
        uint4* z0 = (uint4*)(sX + 49 * QR);
        for (int i = tid; i < 255; i += 512) z0[i] = zz;
    }

    // per-thread x chunks: f4 index f = tid + j*512, j<4, valid if f < 1568
    // prologue: synchronous load+convert of x(b0)
    {
        int b0 = blockIdx.x;
        #pragma unroll
        for (int j = 0; j < 4; ++j) {
            int f = tid + j * 512;
            if (f < XF4) {
                float4 v = __ldg((const float4*)(xg + (size_t)b0 * N_ * DIM_) + f);
                int i = f >> 5, seg = (f & 31) * 4;
                *(uint2*)&sX[i * QR + seg] =
                    make_uint2(pack2h(v.x, v.y), pack2h(v.z, v.w));
            }
        }
    }
    // prefetch x(b0 + GRID) into registers
    float4 pf[4];
    {
        int bn = blockIdx.x + GRID;
        #pragma unroll
        for (int j = 0; j < 4; ++j) {
            int f = tid + j * 512;
            if (bn < B_ && f < XF4)
                pf[j] = __ldg((const float4*)(xg + (size_t)bn * N_ * DIM_) + f);
        }
    }

    // per-warp constant bias fragments
    float qb[6][2];
    #pragma unroll
    for (int nt = 0; nt < 6; ++nt) {
        int cc = wn * 48 + nt * 8 + 2 * t;
        qb[nt][0] = __ldg(&qbias[cc]);
        qb[nt][1] = __ldg(&qbias[cc + 1]);
    }
    float pb[4][2];
    #pragma unroll
    for (int nt = 0; nt < 4; ++nt) {
        int c = 32 * h + 8 * nt + 2 * t;
        pb[nt][0] = __ldg(&pbias[c]);
        pb[nt][1] = __ldg(&pbias[c + 1]);
    }

    const uint32_t uWq = smem_u32(sWq);
    const uint32_t uWp = smem_u32(sWp);
    const uint32_t uX  = smem_u32(sX);
    const uint32_t uQ  = smem_u32(sQ);
    const uint32_t uV  = smem_u32(sV);

    // fragment lane offsets (bytes)
    const uint32_t aOffQ = ((32 * wm2 + (lane & 7) + ((lane >> 3) & 1) * 8) * QR
                            + ((lane >> 4) & 1) * 8) * 2;
    const uint32_t wqOff = ((wn * 48 + (lane & 7) + ((lane >> 4) & 1) * 8) * QR
                            + ((lane >> 3) & 1) * 8) * 2;
    const uint32_t qaOff = ((16 * wm + (lane & 7) + ((lane >> 3) & 1) * 8) * QR
                            + h * HD_ + ((lane >> 4) & 1) * 8) * 2;
    const uint32_t kbOff = (((lane & 7) + ((lane >> 4) & 1) * 8) * QR
                            + h * HD_ + ((lane >> 3) & 1) * 8) * 2;
    const uint32_t vtOff = (((lane & 7) + ((lane >> 3) & 1) * 8) * QR
                            + ((lane >> 4) & 1) * 8) * 2;
    const uint32_t oaOff = ((16 * wm + (lane & 7) + ((lane >> 3) & 1) * 8) * QR
                            + ((lane >> 4) & 1) * 8) * 2;
    const uint32_t wbOff = ((32 * h + (lane & 7) + ((lane >> 4) & 1) * 8) * QR
                            + ((lane >> 3) & 1) * 8) * 2;

    const int r0 = 16 * wm + g;
    const int r1 = r0 + 8;
    const int hoff = h * HD_;

    CP_ASYNC_WAIT_0;   // weights resident

    for (int b = blockIdx.x; b < B_; b += GRID) {
        __syncthreads();   // x(b) visible; prev window's proj reads done

        // ================= QKV gemm (warp tile 32x48) =================
        float qacc[2][6][4];
        #pragma unroll
        for (int mt = 0; mt < 2; ++mt)
            #pragma unroll
            for (int nt = 0; nt < 6; ++nt)
                #pragma unroll
                for (int r = 0; r < 4; ++r) qacc[mt][nt][r] = 0.f;

        #pragma unroll
        for (int ks = 0; ks < 8; ++ks) {
            const uint32_t kB = ks * 32;
            uint32_t af[2][4], bf[6][2];
            LDSM_X4(af[0][0], af[0][1], af[0][2], af[0][3], uX + aOffQ + kB);
            LDSM_X4(af[1][0], af[1][1], af[1][2], af[1][3], uX + aOffQ + kB + 16 * QR * 2);
            #pragma unroll
            for (int p = 0; p < 3; ++p) {
                uint32_t ba = uWq + wqOff + kB + (uint32_t)(p * 16 * QR * 2);
                LDSM_X4(bf[2*p][0], bf[2*p][1], bf[2*p+1][0], bf[2*p+1][1], ba);
            }
            #pragma unroll
            for (int nt = 0; nt < 6; ++nt)
                #pragma unroll
                for (int mt = 0; mt < 2; ++mt)
                    MMAF16(qacc[mt][nt], af[mt], bf[nt]);
        }

        __syncthreads();   // all qkv reads of sX done

        // ---- store prefetched x(b+GRID) into sX; issue LDG for b+2*GRID ----
        if (b + GRID < B_) {
            #pragma unroll
            for (int j = 0; j < 4; ++j) {
                int f = tid + j * 512;
                if (f < XF4) {
                    int i = f >> 5, seg = (f & 31) * 4;
                    *(uint2*)&sX[i * QR + seg] =
                        make_uint2(pack2h(pf[j].x, pf[j].y), pack2h(pf[j].z, pf[j].w));
                }
            }
            int bn = b + 2 * GRID;
            if (bn < B_) {
                #pragma unroll
                for (int j = 0; j < 4; ++j) {
                    int f = tid + j * 512;
                    if (f < XF4)
                        pf[j] = __ldg((const float4*)(xg + (size_t)bn * N_ * DIM_) + f);
                }
            }
        }

        // qkv epilogue: bias + pack fp16 into q/k/v slabs
        #pragma unroll
        for (int mt = 0; mt < 2; ++mt) {
            int rq = 32 * wm2 + 16 * mt + g;
            #pragma unroll
            for (int nt = 0; nt < 6; ++nt) {
                int cc = wn * 48 + nt * 8 + 2 * t;
                __half* slab = sQ + (cc >> 7) * SLB;
                int off = cc & 127;
                *(uint32_t*)&slab[rq * QR + off] =
                    pack2h(qacc[mt][nt][0] + qb[nt][0], qacc[mt][nt][1] + qb[nt][1]);
                *(uint32_t*)&slab[(rq + 8) * QR + off] =
                    pack2h(qacc[mt][nt][2] + qb[nt][0], qacc[mt][nt][3] + qb[nt][1]);
            }
        }
        __syncthreads();   // qkv visible

        // ---- rmb fragments early (overlap L2 latency with S mma) ----
        float rv[32];
        {
            const float4* rf = (const float4*)rmbf
                             + ((((b & (NW_ - 1)) * NH_ + h) * 4 + wm) * 256) + lane;
            #pragma unroll
            for (int c8 = 0; c8 < 8; ++c8) {
                float4 vv = __ldg(rf + c8 * 32);
                rv[c8 * 4]     = vv.x;
                rv[c8 * 4 + 1] = vv.y;
                rv[c8 * 4 + 2] = vv.z;
                rv[c8 * 4 + 3] = vv.w;
            }
        }

        // ================= S = Q K^T =================
        float sacc[8][4];
        #pragma unroll
        for (int nt = 0; nt < 8; ++nt)
            #pragma unroll
            for (int r = 0; r < 4; ++r) sacc[nt][r] = 0.f;

        #pragma unroll
        for (int ks = 0; ks < 2; ++ks) {
            const uint32_t kB = ks * 32;
            uint32_t ah[4];
            LDSM_X4(ah[0], ah[1], ah[2], ah[3], uQ + qaOff + kB);
            #pragma unroll
            for (int p = 0; p < 4; ++p) {
                uint32_t bh[2][2];
                uint32_t ba = uQ + (uint32_t)(SLB * 2) + kbOff + kB
                            + (uint32_t)(p * 16 * QR * 2);
                LDSM_X4(bh[0][0], bh[0][1], bh[1][0], bh[1][1], ba);
                MMAF16(sacc[2*p],     ah, bh[0]);
                MMAF16(sacc[2*p + 1], ah, bh[1]);
            }
        }

        // ================= softmax (no max pass; logits bounded) ===========
        float p0[16], p1[16];
        float s0 = 0.f, s1 = 0.f;
        #pragma unroll
        for (int i = 0; i < 16; ++i) {
            p0[i] = __expf(fmaf(sacc[i >> 1][i & 1],       SCALE_, rv[i]));
            p1[i] = __expf(fmaf(sacc[i >> 1][2 + (i & 1)], SCALE_, rv[16 + i]));
            s0 += p0[i]; s1 += p1[i];
        }
        s0 += __shfl_xor_sync(0xffffffffu, s0, 1);
        s0 += __shfl_xor_sync(0xffffffffu, s0, 2);
        s1 += __shfl_xor_sync(0xffffffffu, s1, 1);
        s1 += __shfl_xor_sync(0xffffffffu, s1, 2);
        float i0 = __frcp_rn(fmaxf(s0, 1e-30f));
        float i1 = __frcp_rn(fmaxf(s1, 1e-30f));
        #pragma unroll
        for (int i = 0; i < 16; ++i) { p0[i] *= i0; p1[i] *= i1; }

        // ================= O = P V =================
        uint32_t pa[4][4];
        #pragma unroll
        for (int ks = 0; ks < 4; ++ks) {
            pa[ks][0] = pack2h(p0[4 * ks],     p0[4 * ks + 1]);
            pa[ks][1] = pack2h(p1[4 * ks],     p1[4 * ks + 1]);
            pa[ks][2] = pack2h(p0[4 * ks + 2], p0[4 * ks + 3]);
            pa[ks][3] = pack2h(p1[4 * ks + 2], p1[4 * ks + 3]);
        }

        float oacc[4][4];
        #pragma unroll
        for (int nt = 0; nt < 4; ++nt)
            #pragma unroll
            for (int r = 0; r < 4; ++r) oacc[nt][r] = 0.f;

        #pragma unroll
        for (int ks = 0; ks < 4; ++ks) {
            #pragma unroll
            for (int p = 0; p < 2; ++p) {
                uint32_t bh[2][2];
                uint32_t ba = uV + vtOff + (uint32_t)(ks * 16 * QR * 2)
                            + (hoff + p * 16) * 2;
                LDSM_X4T(bh[0][0], bh[0][1], bh[1][0], bh[1][1], ba);
                MMAF16(oacc[2*p],     pa[ks], bh[0]);
                MMAF16(oacc[2*p + 1], pa[ks], bh[1]);
            }
        }
        __syncthreads();   // all PV reads of sV done

        // ---- stage O (fp16) into sV (dead) ----
        #pragma unroll
        for (int nt = 0; nt < 4; ++nt) {
            int c = hoff + 8 * nt + 2 * t;
            *(uint32_t*)&sV[r0 * QR + c] = pack2h(oacc[nt][0], oacc[nt][1]);
            *(uint32_t*)&sV[r1 * QR + c] = pack2h(oacc[nt][2], oacc[nt][3]);
        }
        __syncthreads();   // O visible

        // ================= proj: out = O @ Wp^T + pbias =================
        float pacc[4][4];
        #pragma unroll
        for (int nt = 0; nt < 4; ++nt)
            #pragma unroll
            for (int r = 0; r < 4; ++r) pacc[nt][r] = 0.f;

        #pragma unroll
        for (int ks = 0; ks < 8; ++ks) {
            const uint32_t kB = ks * 32;
            uint32_t ah[4];
            LDSM_X4(ah[0], ah[1], ah[2], ah[3], uV + oaOff + kB);
            #pragma unroll
            for (int p = 0; p < 2; ++p) {
                uint32_t bh[2][2];
                uint32_t ba = uWp + wbOff + kB + (uint32_t)(p * 16 * QR * 2);
                LDSM_X4(bh[0][0], bh[0][1], bh[1][0], bh[1][1], ba);
                MMAF16(pacc[2*p],     ah, bh[0]);
                MMAF16(pacc[2*p + 1], ah, bh[1]);
            }
        }

        // ---- epilogue: fp32 out (rows < 49 only) ----
        if (r0 < N_) {
            size_t ob = ((size_t)b * N_ + r0) * DIM_ + 32 * h + 2 * t;
            #pragma unroll
            for (int nt = 0; nt < 4; ++nt)
                *(float2*)&out[ob + 8 * nt] =
                    make_float2(pacc[nt][0] + pb[nt][0], pacc[nt][1] + pb[nt][1]);
        }
        if (r1 < N_) {
            size_t ob = ((size_t)b * N_ + r1) * DIM_ + 32 * h + 2 * t;
            #pragma unroll
            for (int nt = 0; nt < 4; ++nt)
                *(float2*)&out[ob + 8 * nt] =
                    make_float2(pacc[nt][2] + pb[nt][0], pacc[nt][3] + pb[nt][1]);
        }
    }
}

// ============================================================================
// launch
// ============================================================================
extern "C" void kernel_launch(void* const* d_in, const int* in_sizes, int n_in,
                              void* d_out, int out_size)
{
    const float* x      = (const float*)d_in[0];
    const float* mask   = (const float*)d_in[1];
    const float* qkv_w  = (const float*)d_in[2];
    const float* qkv_b  = (const float*)d_in[3];
    const float* proj_w = (const float*)d_in[4];
    const float* proj_b = (const float*)d_in[5];
    const float* rpb    = (const float*)d_in[6];
    const int*   rel    = (const int*)d_in[7];
    float* out = (float*)d_out;

    __half *wqp, *wpp;
    float* rmbfp;
    cudaGetSymbolAddress((void**)&wqp,   g_wq);
    cudaGetSymbolAddress((void**)&wpp,   g_wp);
    cudaGetSymbolAddress((void**)&rmbfp, g_rmbf);

    static bool attr_set = false;
    if (!attr_set) {
        cudaFuncSetAttribute(fused_all, cudaFuncAttributeMaxDynamicSharedMemorySize,
                             FUSED_SM_BYTES);
        attr_set = true;
    }

    convert_w<<<64, 256>>>(qkv_w, proj_w);
    build_rmbf<<<1024, 256>>>(mask, rpb, rel);

    fused_all<<<GRID, 512, FUSED_SM_BYTES>>>(x, rmbfp, wqp, wpp, qkv_b, proj_b, out);
}